// round 10
// baseline (speedup 1.0000x reference)
#include <cuda_runtime.h>
#include <cuda_bf16.h>
#include <cstdint>

// ---------------------------------------------------------------------------
// PointNet++ part-seg forward. TF32 tensor-core MLPs + forked-stream DAG:
//   origin: prep -> fps1 -> fps2 -> fps3 -> fps4
//   s1:     [E1] knn20L1 -> SA1 -> [EL2] SA2 -> [EL3] SA3 -> [EL4] SA4
//           -> [EK] FP3 -> FP2 -> FP1 -> FP0 -> seg -> transpose
//   s2:     [E2] knn20L2 -> [E3] knn20L3 -> [E4] knn20L4 -> knn3
// ---------------------------------------------------------------------------

#define B_ 8
#define N_ 4096

// ---- scratch layout (floats) ----
#define SZ_XYZ4  (B_*N_*4)
#define SZ_NRM   (B_*N_*3)
#define SZ_SKIP0 (B_*N_*22)
#define SZ_X1    (B_*512*4)
#define SZ_X2    (B_*256*4)
#define SZ_X3    (B_*128*4)
#define SZ_X4    (B_*64*4)
#define SZ_F1    (B_*512*64)
#define SZ_F2    (B_*256*128)
#define SZ_F3    (B_*128*256)
#define SZ_F4    (B_*64*512)
#define SZ_G3    (B_*128*512)
#define SZ_G2    (B_*256*256)
#define SZ_G1    (B_*512*128)
#define SZ_G0    (B_*N_*128)
#define SZ_NI1   (B_*512*20)
#define SZ_NI2   (B_*256*20)
#define SZ_NI3   (B_*128*20)
#define SZ_NI4   (B_*64*20)
#define SZ_I33   (B_*128*3)
#define SZ_I32   (B_*256*3)
#define SZ_I31   (B_*512*3)
#define SZ_I30   (B_*N_*3)
#define SZ_W33   (B_*128*3)
#define SZ_W32   (B_*256*3)
#define SZ_W31   (B_*512*3)
#define SZ_W30   (B_*N_*3)
#define SZ_ABUF  (B_*N_*152)
#define SZ_CBUF  (B_*512*20*64)

#define OFF_XYZ4  0
#define OFF_NRM   (OFF_XYZ4 + SZ_XYZ4)
#define OFF_SKIP0 (OFF_NRM + SZ_NRM)
#define OFF_X1    (OFF_SKIP0 + SZ_SKIP0)
#define OFF_X2    (OFF_X1 + SZ_X1)
#define OFF_X3    (OFF_X2 + SZ_X2)
#define OFF_X4    (OFF_X3 + SZ_X3)
#define OFF_F1    (OFF_X4 + SZ_X4)
#define OFF_F2    (OFF_F1 + SZ_F1)
#define OFF_F3    (OFF_F2 + SZ_F2)
#define OFF_F4    (OFF_F3 + SZ_F3)
#define OFF_G3    (OFF_F4 + SZ_F4)
#define OFF_G2    (OFF_G3 + SZ_G3)
#define OFF_G1    (OFF_G2 + SZ_G2)
#define OFF_G0    (OFF_G1 + SZ_G1)
#define OFF_NI1   (OFF_G0 + SZ_G0)
#define OFF_NI2   (OFF_NI1 + SZ_NI1)
#define OFF_NI3   (OFF_NI2 + SZ_NI2)
#define OFF_NI4   (OFF_NI3 + SZ_NI3)
#define OFF_I33   (OFF_NI4 + SZ_NI4)
#define OFF_I32   (OFF_I33 + SZ_I33)
#define OFF_I31   (OFF_I32 + SZ_I32)
#define OFF_I30   (OFF_I31 + SZ_I31)
#define OFF_W33   (OFF_I30 + SZ_I30)
#define OFF_W32   (OFF_W33 + SZ_W33)
#define OFF_W31   (OFF_W32 + SZ_W32)
#define OFF_W30   (OFF_W31 + SZ_W31)
#define OFF_ABUF  (OFF_W30 + SZ_W30)
#define OFF_CBUF  (OFF_ABUF + SZ_ABUF)
#define SCRATCH_TOTAL (OFF_CBUF + SZ_CBUF)

__device__ __align__(16) float g_scratch[SCRATCH_TOTAL];

// ---------------------------------------------------------------------------
// prep
// ---------------------------------------------------------------------------
__global__ void prep_kernel(const float* __restrict__ x, const float* __restrict__ cls,
                            float4* __restrict__ xyz4, float* __restrict__ nrm,
                            float* __restrict__ skip0) {
    int n = blockIdx.x * blockDim.x + threadIdx.x;
    int b = blockIdx.y;
    if (n >= N_) return;
    const float* xb = x + (size_t)b * 6 * N_;
    float px = xb[0*N_+n], py = xb[1*N_+n], pz = xb[2*N_+n];
    float nx = xb[3*N_+n], ny = xb[4*N_+n], nz = xb[5*N_+n];
    float pp = px*px + py*py + pz*pz;
    xyz4[(size_t)b*N_+n] = make_float4(px, py, pz, pp);
    float* np_ = nrm + ((size_t)b*N_+n)*3;
    np_[0]=nx; np_[1]=ny; np_[2]=nz;
    float* sk = skip0 + ((size_t)b*N_+n)*22;
    #pragma unroll
    for (int c = 0; c < 16; c++) sk[c] = cls[b*16+c];
    sk[16]=px; sk[17]=py; sk[18]=pz;
    sk[19]=nx; sk[20]=ny; sk[21]=nz;
}

// ---------------------------------------------------------------------------
// FPS (proven form), one kernel per level
// ---------------------------------------------------------------------------
#define FPS_NT 512

struct FpsRed {
    unsigned key[16];
    int      idx[16];
    float4   bc;
};

template<int P>
__device__ void fps_level(const float4* __restrict__ pts, int M, int S,
                          float4* __restrict__ o, float4* spts, FpsRed* r) {
    const int tid = threadIdx.x;
    float px[P], py[P], pz[P], dist[P];
    #pragma unroll
    for (int j = 0; j < P; j++) {
        int i = tid + j*FPS_NT;
        if (i < M) {
            float4 p = pts[i];
            spts[i] = p;
            px[j]=p.x; py[j]=p.y; pz[j]=p.z; dist[j]=1e10f;
        } else {
            px[j]=0.f; py[j]=0.f; pz[j]=0.f; dist[j]=-1.0f;
        }
    }
    if (tid == 0) {
        float4 p0 = pts[0];
        r->bc = make_float4(p0.x, p0.y, p0.z, p0.x*p0.x + p0.y*p0.y + p0.z*p0.z);
    }
    __syncthreads();

    for (int it = 0; it < S; ++it) {
        float4 f = r->bc;
        if (tid == 0) o[it] = f;

        float bv = -1.0f; int bj = 0;
        #pragma unroll
        for (int j = 0; j < P; j++) {
            float dx = px[j]-f.x, dy = py[j]-f.y, dz = pz[j]-f.z;
            float d = dx*dx + dy*dy + dz*dz;
            float nd = fminf(dist[j], d);
            dist[j] = nd;
            if (nd > bv) { bv = nd; bj = j; }
        }
        int myi = tid + bj*FPS_NT;
        unsigned key = (bv > 0.0f) ? __float_as_uint(bv) : 0u;
        unsigned wmax = __reduce_max_sync(0xffffffffu, key);
        int cand = (key == wmax) ? myi : 0x7fffffff;
        int wmin = __reduce_min_sync(0xffffffffu, cand);
        if ((tid & 31) == 0) { r->key[tid>>5] = wmax; r->idx[tid>>5] = wmin; }
        __syncthreads();
        if (tid < 32) {
            unsigned k2 = (tid < (FPS_NT/32)) ? r->key[tid] : 0u;
            int      i2 = (tid < (FPS_NT/32)) ? r->idx[tid] : 0x7fffffff;
            unsigned g  = __reduce_max_sync(0xffffffffu, k2);
            int c2 = (k2 == g) ? i2 : 0x7fffffff;
            int win = __reduce_min_sync(0xffffffffu, c2);
            if (tid == 0) {
                float4 p = spts[win];
                r->bc = make_float4(p.x, p.y, p.z, p.x*p.x + p.y*p.y + p.z*p.z);
            }
        }
        __syncthreads();
    }
}

template<int P>
__global__ void __launch_bounds__(FPS_NT)
fps_level_kernel(const float4* __restrict__ pts_all, int M, int S,
                 float4* __restrict__ out_all) {
    extern __shared__ __align__(16) float4 spts[];
    __shared__ FpsRed r;
    int b = blockIdx.x;
    fps_level<P>(pts_all + (size_t)b*M, M, S, out_all + (size_t)b*S, spts, &r);
}

// ---------------------------------------------------------------------------
// kNN (x4-unrolled; ascending-m inserts preserve top_k tie-break)
// ---------------------------------------------------------------------------
template<int K>
__device__ __forceinline__ void knn_insert(float d, int m, float* bd, int* bi) {
    if (d < bd[K-1]) {
        #pragma unroll
        for (int t = K-1; t >= 0; --t) {
            bool pred_gt = (t > 0) ? (bd[t-1] > d) : false;
            if (bd[t] > d) {
                if (pred_gt) { bd[t] = bd[t-1]; bi[t] = bi[t-1]; }
                else         { bd[t] = d;       bi[t] = m; }
            }
        }
    }
}

template<int K>
__device__ __forceinline__ void knn_scan(float4 qp, const float4* __restrict__ ref,
                                         int M, float* bd, int* bi) {
    float qq = qp.w;
    #pragma unroll
    for (int j = 0; j < K; j++) { bd[j] = 3.0e38f; bi[j] = 0; }
    for (int m = 0; m < M; m += 4) {
        float4 r0 = ref[m+0];
        float4 r1 = ref[m+1];
        float4 r2 = ref[m+2];
        float4 r3 = ref[m+3];
        float d0 = qq - 2.0f*(qp.x*r0.x + qp.y*r0.y + qp.z*r0.z) + r0.w;
        float d1 = qq - 2.0f*(qp.x*r1.x + qp.y*r1.y + qp.z*r1.z) + r1.w;
        float d2 = qq - 2.0f*(qp.x*r2.x + qp.y*r2.y + qp.z*r2.z) + r2.w;
        float d3 = qq - 2.0f*(qp.x*r3.x + qp.y*r3.y + qp.z*r3.z) + r3.w;
        knn_insert<K>(d0, m+0, bd, bi);
        knn_insert<K>(d1, m+1, bd, bi);
        knn_insert<K>(d2, m+2, bd, bi);
        knn_insert<K>(d3, m+3, bd, bi);
    }
}

__global__ void knn20_level_kernel(const float4* __restrict__ q, const float4* __restrict__ ref,
                                   int Sq, int M, int* __restrict__ out) {
    int s = blockIdx.x * blockDim.x + threadIdx.x;
    int b = blockIdx.y;
    if (s >= Sq) return;
    float bd[20]; int bi[20];
    knn_scan<20>(q[(size_t)b*Sq + s], ref + (size_t)b*M, M, bd, bi);
    int* o = out + ((size_t)b*Sq + s)*20;
    #pragma unroll
    for (int j = 0; j < 20; j++) o[j] = bi[j];
}

__device__ __forceinline__ void knn3w_body(const float4* __restrict__ q,
                                           const float4* __restrict__ ref,
                                           int s, int M,
                                           int* __restrict__ oi, float* __restrict__ ow) {
    float4 qp = q[s];
    float bd[3]; int bi[3];
    knn_scan<3>(qp, ref, M, bd, bi);
    float wv[3]; float wsum = 0.0f;
    #pragma unroll
    for (int j = 0; j < 3; j++) {
        float4 r = ref[bi[j]];
        float dx = r.x-qp.x, dy = r.y-qp.y, dz = r.z-qp.z;
        float dd = dx*dx + dy*dy + dz*dz;
        float w = 1.0f / (dd + 1e-8f);
        wv[j] = w; wsum += w;
    }
    float inv = 1.0f / wsum;
    #pragma unroll
    for (int j = 0; j < 3; j++) {
        oi[(size_t)s*3 + j] = bi[j];
        ow[(size_t)s*3 + j] = wv[j]*inv;
    }
}

__global__ void knn3_all_kernel(const float4* __restrict__ xyz4,
                                const float4* __restrict__ x1, const float4* __restrict__ x2,
                                const float4* __restrict__ x3, const float4* __restrict__ x4,
                                int* __restrict__ i30, int* __restrict__ i31,
                                int* __restrict__ i32, int* __restrict__ i33,
                                float* __restrict__ w30, float* __restrict__ w31,
                                float* __restrict__ w32, float* __restrict__ w33) {
    int blk = blockIdx.x, b = blockIdx.y, tid = threadIdx.x;
    if (blk < 32) {
        int s = blk*128 + tid;
        knn3w_body(xyz4 + (size_t)b*N_, x1 + (size_t)b*512, s, 512,
                   i30 + (size_t)b*N_*3, w30 + (size_t)b*N_*3);
    } else if (blk < 36) {
        int s = (blk-32)*128 + tid;
        knn3w_body(x1 + (size_t)b*512, x2 + (size_t)b*256, s, 256,
                   i31 + (size_t)b*512*3, w31 + (size_t)b*512*3);
    } else if (blk < 38) {
        int s = (blk-36)*128 + tid;
        knn3w_body(x2 + (size_t)b*256, x3 + (size_t)b*128, s, 128,
                   i32 + (size_t)b*256*3, w32 + (size_t)b*256*3);
    } else {
        knn3w_body(x3 + (size_t)b*128, x4 + (size_t)b*64, tid, 64,
                   i33 + (size_t)b*128*3, w33 + (size_t)b*128*3);
    }
}

// ---------------------------------------------------------------------------
// SA gather / maxpool, FP gather (unchanged)
// ---------------------------------------------------------------------------
template<int CIN, int LDA>
__global__ void sa_gather_kernel(const float4* __restrict__ qxyz, const float4* __restrict__ rxyz,
                                 const float* __restrict__ rfeat, const int* __restrict__ nidx,
                                 int S, int M, float* __restrict__ A) {
    constexpr int CFEAT = CIN - 3;
    int e = blockIdx.x * blockDim.x + threadIdx.x;
    int total = B_ * S * 20 * LDA;
    if (e >= total) return;
    int c = e % LDA;
    int row = e / LDA;
    int bs = row / 20;
    int b = bs / S;
    float v = 0.0f;
    if (c < CIN) {
        int n = nidx[row];
        if (c < 3) {
            v = ((const float*)(rxyz + (size_t)b*M + n))[c]
              - ((const float*)(qxyz + bs))[c];
        } else {
            v = rfeat[((size_t)b*M + n)*CFEAT + (c-3)];
        }
    }
    A[e] = v;
}

template<int COUT>
__global__ void sa_maxpool_kernel(const float* __restrict__ C, const float* __restrict__ bias,
                                  int S, float* __restrict__ out) {
    int e = blockIdx.x * blockDim.x + threadIdx.x;
    int total = B_ * S * COUT;
    if (e >= total) return;
    int d = e % COUT;
    int bs = e / COUT;
    const float* cp = C + (size_t)bs*20*COUT + d;
    float m = cp[0];
    #pragma unroll 4
    for (int k = 1; k < 20; k++) m = fmaxf(m, cp[(size_t)k*COUT]);
    out[e] = fmaxf(m + bias[d], 0.0f);
}

template<int CI, int CS, int LDA>
__global__ void fp_gather_kernel(const float* __restrict__ fr, const float* __restrict__ skip,
                                 const int* __restrict__ idx3, const float* __restrict__ w3,
                                 int Sq, int M, float* __restrict__ A) {
    int e = blockIdx.x * blockDim.x + threadIdx.x;
    int total = B_ * Sq * LDA;
    if (e >= total) return;
    int c = e % LDA;
    int row = e / LDA;
    float v = 0.0f;
    if (c < CI) {
        int b = row / Sq;
        const int*   ip = idx3 + (size_t)row*3;
        const float* wp = w3   + (size_t)row*3;
        size_t base = (size_t)b*M;
        v = wp[0]*fr[(base + ip[0])*CI + c]
          + wp[1]*fr[(base + ip[1])*CI + c]
          + wp[2]*fr[(base + ip[2])*CI + c];
    } else if (c < CI + CS) {
        v = skip[(size_t)row*CS + (c - CI)];
    }
    A[e] = v;
}

// ---------------------------------------------------------------------------
// TF32 tensor-core GEMM (proven R8 form)
// ---------------------------------------------------------------------------
__device__ __forceinline__ unsigned f2tf32(float f) {
    unsigned r; asm("cvt.rna.tf32.f32 %0, %1;" : "=r"(r) : "f"(f)); return r;
}

template<bool BIAS_RELU>
__global__ void __launch_bounds__(256)
gemm_tc_kernel(const float* __restrict__ A, int lda,
               const float* __restrict__ Wm, const float* __restrict__ bias,
               float* __restrict__ C, int N, int Kdim) {
    __shared__ unsigned As[16][132];
    __shared__ unsigned Bs[16][68];
    int bm = blockIdx.x * 128;
    int bn = blockIdx.y * 64;
    int tid = threadIdx.x;
    int warp = tid >> 5, lane = tid & 31;
    int wm = (warp & 3) * 32;
    int wn = (warp >> 2) * 32;
    int g = lane >> 2, tq = lane & 3;

    float acc[2][4][4];
    #pragma unroll
    for (int mt = 0; mt < 2; mt++)
        #pragma unroll
        for (int nt = 0; nt < 4; nt++)
            #pragma unroll
            for (int j = 0; j < 4; j++) acc[mt][nt][j] = 0.0f;

    int ktiles = (Kdim + 15) >> 4;
    for (int t = 0; t < ktiles; t++) {
        int k0 = t * 16;
        {
            int r = tid >> 2;
            int kk = (tid & 3) * 4;
            #pragma unroll
            for (int h = 0; h < 2; h++) {
                int row = r + h*64;
                float4 v = make_float4(0.f,0.f,0.f,0.f);
                if (k0 + kk < lda)
                    v = *(const float4*)&A[(size_t)(bm+row)*lda + k0 + kk];
                As[kk+0][row] = f2tf32(v.x);
                As[kk+1][row] = f2tf32(v.y);
                As[kk+2][row] = f2tf32(v.z);
                As[kk+3][row] = f2tf32(v.w);
            }
        }
        {
            int kk = tid >> 4;
            int nn = (tid & 15) * 4;
            float4 v = make_float4(0.f,0.f,0.f,0.f);
            if (k0 + kk < Kdim)
                v = *(const float4*)&Wm[(size_t)(k0+kk)*N + bn + nn];
            Bs[kk][nn+0] = f2tf32(v.x);
            Bs[kk][nn+1] = f2tf32(v.y);
            Bs[kk][nn+2] = f2tf32(v.z);
            Bs[kk][nn+3] = f2tf32(v.w);
        }
        __syncthreads();
        #pragma unroll
        for (int kh = 0; kh < 2; kh++) {
            int kb = kh*8;
            unsigned a[2][4], bfr[4][2];
            #pragma unroll
            for (int mt = 0; mt < 2; mt++) {
                int m0 = wm + mt*16;
                a[mt][0] = As[kb+tq][m0+g];
                a[mt][1] = As[kb+tq][m0+g+8];
                a[mt][2] = As[kb+tq+4][m0+g];
                a[mt][3] = As[kb+tq+4][m0+g+8];
            }
            #pragma unroll
            for (int nt = 0; nt < 4; nt++) {
                int n0 = wn + nt*8;
                bfr[nt][0] = Bs[kb+tq][n0+g];
                bfr[nt][1] = Bs[kb+tq+4][n0+g];
            }
            #pragma unroll
            for (int mt = 0; mt < 2; mt++)
                #pragma unroll
                for (int nt = 0; nt < 4; nt++) {
                    asm volatile(
                        "mma.sync.aligned.m16n8k8.row.col.f32.tf32.tf32.f32 "
                        "{%0,%1,%2,%3}, {%4,%5,%6,%7}, {%8,%9}, {%0,%1,%2,%3};"
                        : "+f"(acc[mt][nt][0]), "+f"(acc[mt][nt][1]),
                          "+f"(acc[mt][nt][2]), "+f"(acc[mt][nt][3])
                        : "r"(a[mt][0]), "r"(a[mt][1]), "r"(a[mt][2]), "r"(a[mt][3]),
                          "r"(bfr[nt][0]), "r"(bfr[nt][1]));
                }
        }
        __syncthreads();
    }

    #pragma unroll
    for (int mt = 0; mt < 2; mt++) {
        int row0 = bm + wm + mt*16 + g;
        #pragma unroll
        for (int nt = 0; nt < 4; nt++) {
            int col = bn + wn + nt*8 + 2*tq;
            float2 v0 = make_float2(acc[mt][nt][0], acc[mt][nt][1]);
            float2 v1 = make_float2(acc[mt][nt][2], acc[mt][nt][3]);
            if (BIAS_RELU) {
                float b0v = bias[col], b1v = bias[col+1];
                v0.x = fmaxf(v0.x + b0v, 0.f); v0.y = fmaxf(v0.y + b1v, 0.f);
                v1.x = fmaxf(v1.x + b0v, 0.f); v1.y = fmaxf(v1.y + b1v, 0.f);
            }
            *(float2*)&C[(size_t)row0*N + col]     = v0;
            *(float2*)&C[(size_t)(row0+8)*N + col] = v1;
        }
    }
}

// ---------------------------------------------------------------------------
// Seg head + transpose (proven forms)
// ---------------------------------------------------------------------------
__global__ void seg_kernel(const float* __restrict__ g0, const float* __restrict__ Wseg,
                           const float* __restrict__ bseg, float* __restrict__ out) {
    constexpr int TS = 16;
    __shared__ __align__(16) float sg[TS * 128];
    int b = blockIdx.y;
    int s0 = blockIdx.x * TS;
    int tid = threadIdx.x;
    for (int e = tid; e < TS*128; e += 64)
        sg[e] = g0[((size_t)b*N_ + s0)*128 + e];
    __syncthreads();
    int j = tid;
    if (j < 50) {
        float acc[TS];
        #pragma unroll
        for (int t = 0; t < TS; t++) acc[t] = 0.0f;
        for (int c = 0; c < 128; c += 4) {
            float w0 = Wseg[(c+0)*50 + j];
            float w1 = Wseg[(c+1)*50 + j];
            float w2 = Wseg[(c+2)*50 + j];
            float w3 = Wseg[(c+3)*50 + j];
            #pragma unroll
            for (int t = 0; t < TS; t++) {
                float4 v = *(const float4*)&sg[t*128 + c];
                acc[t] += v.x*w0 + v.y*w1 + v.z*w2 + v.w*w3;
            }
        }
        float bb = bseg[j];
        #pragma unroll
        for (int t = 0; t < TS; t++)
            out[((size_t)b*N_ + s0 + t)*50 + j] = acc[t] + bb;
    }
}

__global__ void transpose_kernel(const float* __restrict__ g0, float* __restrict__ out) {
    __shared__ float tile[32][33];
    int b = blockIdx.z;
    int n0 = blockIdx.x * 32, c0 = blockIdx.y * 32;
    int tx = threadIdx.x, ty = threadIdx.y;
    tile[ty][tx] = g0[((size_t)b*N_ + n0 + ty)*128 + c0 + tx];
    __syncthreads();
    out[((size_t)b*128 + c0 + ty)*N_ + n0 + tx] = tile[tx][ty];
}

// ---------------------------------------------------------------------------
extern "C" void kernel_launch(void* const* d_in, const int* in_sizes, int n_in,
                              void* d_out, int out_size) {
    const float* x      = (const float*)d_in[0];
    const float* cls    = (const float*)d_in[1];
    const float* W0 = (const float*)d_in[2];  const float* b0 = (const float*)d_in[3];
    const float* W1 = (const float*)d_in[4];  const float* b1 = (const float*)d_in[5];
    const float* W2 = (const float*)d_in[6];  const float* b2 = (const float*)d_in[7];
    const float* W3 = (const float*)d_in[8];  const float* b3 = (const float*)d_in[9];
    const float* F3 = (const float*)d_in[10]; const float* fb3 = (const float*)d_in[11];
    const float* F2 = (const float*)d_in[12]; const float* fb2 = (const float*)d_in[13];
    const float* F1 = (const float*)d_in[14]; const float* fb1 = (const float*)d_in[15];
    const float* F0 = (const float*)d_in[16]; const float* fb0 = (const float*)d_in[17];
    const float* Wseg = (const float*)d_in[18]; const float* bseg = (const float*)d_in[19];

    float* scratch = nullptr;
    cudaGetSymbolAddress((void**)&scratch, g_scratch);

    float4* xyz4 = (float4*)(scratch + OFF_XYZ4);
    float* nrm   = scratch + OFF_NRM;
    float* skip0 = scratch + OFF_SKIP0;
    float4* x1 = (float4*)(scratch + OFF_X1);
    float4* x2 = (float4*)(scratch + OFF_X2);
    float4* x3 = (float4*)(scratch + OFF_X3);
    float4* x4 = (float4*)(scratch + OFF_X4);
    float* f1 = scratch + OFF_F1;  float* f2 = scratch + OFF_F2;
    float* f3 = scratch + OFF_F3;  float* f4 = scratch + OFF_F4;
    float* g3 = scratch + OFF_G3;  float* g2 = scratch + OFF_G2;
    float* g1 = scratch + OFF_G1;  float* g0 = scratch + OFF_G0;
    int* ni1 = (int*)(scratch + OFF_NI1);
    int* ni2 = (int*)(scratch + OFF_NI2);
    int* ni3 = (int*)(scratch + OFF_NI3);
    int* ni4 = (int*)(scratch + OFF_NI4);
    int* i33 = (int*)(scratch + OFF_I33);
    int* i32 = (int*)(scratch + OFF_I32);
    int* i31 = (int*)(scratch + OFF_I31);
    int* i30 = (int*)(scratch + OFF_I30);
    float* w33 = scratch + OFF_W33;
    float* w32 = scratch + OFF_W32;
    float* w31 = scratch + OFF_W31;
    float* w30 = scratch + OFF_W30;
    float* Abuf = scratch + OFF_ABUF;
    float* Cbuf = scratch + OFF_CBUF;

    float* out1 = (float*)d_out;                    // result [B,N,50]
    float* out2 = out1 + (size_t)B_ * N_ * 50;      // g0^T   [B,128,N]

    // one-time host resources (streams/events carry no device-mem footprint)
    static cudaStream_t s1 = nullptr, s2 = nullptr;
    static cudaEvent_t E1, E2, E3, E4, EL2, EL3, EL4, EK, ED;
    static bool init_done = false;
    if (!init_done) {
        cudaStreamCreateWithFlags(&s1, cudaStreamNonBlocking);
        cudaStreamCreateWithFlags(&s2, cudaStreamNonBlocking);
        cudaEventCreateWithFlags(&E1,  cudaEventDisableTiming);
        cudaEventCreateWithFlags(&E2,  cudaEventDisableTiming);
        cudaEventCreateWithFlags(&E3,  cudaEventDisableTiming);
        cudaEventCreateWithFlags(&E4,  cudaEventDisableTiming);
        cudaEventCreateWithFlags(&EL2, cudaEventDisableTiming);
        cudaEventCreateWithFlags(&EL3, cudaEventDisableTiming);
        cudaEventCreateWithFlags(&EL4, cudaEventDisableTiming);
        cudaEventCreateWithFlags(&EK,  cudaEventDisableTiming);
        cudaEventCreateWithFlags(&ED,  cudaEventDisableTiming);
        cudaFuncSetAttribute(fps_level_kernel<8>, cudaFuncAttributeMaxDynamicSharedMemorySize,
                             N_ * (int)sizeof(float4));
        init_done = true;
    }

    // ---- origin stream: prep + FPS chain ----
    prep_kernel<<<dim3(N_/256, B_), 256>>>(x, cls, xyz4, nrm, skip0);
    fps_level_kernel<8><<<B_, FPS_NT, N_*sizeof(float4)>>>(xyz4, N_, 512, x1);
    cudaEventRecord(E1, 0);
    fps_level_kernel<1><<<B_, FPS_NT, 512*sizeof(float4)>>>(x1, 512, 256, x2);
    cudaEventRecord(E2, 0);
    fps_level_kernel<1><<<B_, FPS_NT, 256*sizeof(float4)>>>(x2, 256, 128, x3);
    cudaEventRecord(E3, 0);
    fps_level_kernel<1><<<B_, FPS_NT, 128*sizeof(float4)>>>(x3, 128, 64, x4);
    cudaEventRecord(E4, 0);

    // ---- s2: knn20 levels 2-4 + knn3 ----
    cudaStreamWaitEvent(s2, E2, 0);
    knn20_level_kernel<<<dim3(2, B_), 128, 0, s2>>>(x2, x1, 256, 512, ni2);
    cudaEventRecord(EL2, s2);
    cudaStreamWaitEvent(s2, E3, 0);
    knn20_level_kernel<<<dim3(1, B_), 128, 0, s2>>>(x3, x2, 128, 256, ni3);
    cudaEventRecord(EL3, s2);
    cudaStreamWaitEvent(s2, E4, 0);
    knn20_level_kernel<<<dim3(1, B_), 64, 0, s2>>>(x4, x3, 64, 128, ni4);
    cudaEventRecord(EL4, s2);
    knn3_all_kernel<<<dim3(39, B_), 128, 0, s2>>>(xyz4, x1, x2, x3, x4,
                                                  i30, i31, i32, i33, w30, w31, w32, w33);
    cudaEventRecord(EK, s2);

    // ---- s1: SA chain -> FP chain -> outputs ----
    cudaStreamWaitEvent(s1, E1, 0);
    knn20_level_kernel<<<dim3(4, B_), 128, 0, s1>>>(x1, xyz4, 512, N_, ni1);
    {   // SA1: rows=81920, K=6 (lda 8), N=64
        int total = B_*512*20*8;
        sa_gather_kernel<6,8><<<(total+255)/256, 256, 0, s1>>>(x1, xyz4, nrm, ni1, 512, N_, Abuf);
        gemm_tc_kernel<false><<<dim3(81920/128, 1), 256, 0, s1>>>(Abuf, 8, W0, nullptr, Cbuf, 64, 6);
        int pt = B_*512*64;
        sa_maxpool_kernel<64><<<(pt+255)/256, 256, 0, s1>>>(Cbuf, b0, 512, f1);
    }
    cudaStreamWaitEvent(s1, EL2, 0);
    {   // SA2: rows=40960, K=67 (lda 68), N=128
        int total = B_*256*20*68;
        sa_gather_kernel<67,68><<<(total+255)/256, 256, 0, s1>>>(x2, x1, f1, ni2, 256, 512, Abuf);
        gemm_tc_kernel<false><<<dim3(40960/128, 2), 256, 0, s1>>>(Abuf, 68, W1, nullptr, Cbuf, 128, 67);
        int pt = B_*256*128;
        sa_maxpool_kernel<128><<<(pt+255)/256, 256, 0, s1>>>(Cbuf, b1, 256, f2);
    }
    cudaStreamWaitEvent(s1, EL3, 0);
    {   // SA3: rows=20480, K=131 (lda 132), N=256
        int total = B_*128*20*132;
        sa_gather_kernel<131,132><<<(total+255)/256, 256, 0, s1>>>(x3, x2, f2, ni3, 128, 256, Abuf);
        gemm_tc_kernel<false><<<dim3(20480/128, 4), 256, 0, s1>>>(Abuf, 132, W2, nullptr, Cbuf, 256, 131);
        int pt = B_*128*256;
        sa_maxpool_kernel<256><<<(pt+255)/256, 256, 0, s1>>>(Cbuf, b2, 128, f3);
    }
    cudaStreamWaitEvent(s1, EL4, 0);
    {   // SA4: rows=10240, K=259 (lda 260), N=512
        int total = B_*64*20*260;
        sa_gather_kernel<259,260><<<(total+255)/256, 256, 0, s1>>>(x4, x3, f3, ni4, 64, 128, Abuf);
        gemm_tc_kernel<false><<<dim3(10240/128, 8), 256, 0, s1>>>(Abuf, 260, W3, nullptr, Cbuf, 512, 259);
        int pt = B_*64*512;
        sa_maxpool_kernel<512><<<(pt+255)/256, 256, 0, s1>>>(Cbuf, b3, 64, f4);
    }
    cudaStreamWaitEvent(s1, EK, 0);
    {   // FP3: rows=1024, K=768, N=512
        int total = B_*128*768;
        fp_gather_kernel<512,256,768><<<(total+255)/256, 256, 0, s1>>>(f4, f3, i33, w33, 128, 64, Abuf);
        gemm_tc_kernel<true><<<dim3(1024/128, 8), 256, 0, s1>>>(Abuf, 768, F3, fb3, g3, 512, 768);
    }
    {   // FP2: rows=2048, K=640, N=256
        int total = B_*256*640;
        fp_gather_kernel<512,128,640><<<(total+255)/256, 256, 0, s1>>>(g3, f2, i32, w32, 256, 128, Abuf);
        gemm_tc_kernel<true><<<dim3(2048/128, 4), 256, 0, s1>>>(Abuf, 640, F2, fb2, g2, 256, 640);
    }
    {   // FP1: rows=4096, K=320, N=128
        int total = B_*512*320;
        fp_gather_kernel<256,64,320><<<(total+255)/256, 256, 0, s1>>>(g2, f1, i31, w31, 512, 256, Abuf);
        gemm_tc_kernel<true><<<dim3(4096/128, 2), 256, 0, s1>>>(Abuf, 320, F1, fb1, g1, 128, 320);
    }
    {   // FP0: rows=32768, K=150 (lda 152), N=128
        int total = B_*N_*152;
        fp_gather_kernel<128,22,152><<<(total+255)/256, 256, 0, s1>>>(g1, skip0, i30, w30, N_, 512, Abuf);
        gemm_tc_kernel<true><<<dim3(32768/128, 2), 256, 0, s1>>>(Abuf, 152, F0, fb0, g0, 128, 150);
    }
    seg_kernel<<<dim3(N_/16, B_), 64, 0, s1>>>(g0, Wseg, bseg, out1);
    transpose_kernel<<<dim3(N_/32, 128/32, B_), dim3(32,32), 0, s1>>>(g0, out2);
    cudaEventRecord(ED, s1);

    // join forks back into origin stream
    cudaStreamWaitEvent(0, ED, 0);
}

// round 11
// speedup vs baseline: 1.2088x; 1.2088x over previous
#include <cuda_runtime.h>
#include <cuda_bf16.h>
#include <cstdint>

// ---------------------------------------------------------------------------
// PointNet++ part-seg forward. Single stream, TF32 tensor-core MLPs with
// gather fused into the GEMM A-tile loader:
// prep -> FPS(4 levels fused) -> knn20_all -> knn3_all(+weights)
//   -> [gemm_sa -> maxpool] x4 -> [gemm_fp(bias+relu)] x4 -> seg + transpose
// ---------------------------------------------------------------------------

#define B_ 8
#define N_ 4096

// ---- scratch layout (floats) ----
#define SZ_XYZ4  (B_*N_*4)
#define SZ_NRM   (B_*N_*3)
#define SZ_SKIP0 (B_*N_*22)
#define SZ_X1    (B_*512*4)
#define SZ_X2    (B_*256*4)
#define SZ_X3    (B_*128*4)
#define SZ_X4    (B_*64*4)
#define SZ_F1    (B_*512*64)
#define SZ_F2    (B_*256*128)
#define SZ_F3    (B_*128*256)
#define SZ_F4    (B_*64*512)
#define SZ_G3    (B_*128*512)
#define SZ_G2    (B_*256*256)
#define SZ_G1    (B_*512*128)
#define SZ_G0    (B_*N_*128)
#define SZ_NI1   (B_*512*20)
#define SZ_NI2   (B_*256*20)
#define SZ_NI3   (B_*128*20)
#define SZ_NI4   (B_*64*20)
#define SZ_I33   (B_*128*3)
#define SZ_I32   (B_*256*3)
#define SZ_I31   (B_*512*3)
#define SZ_I30   (B_*N_*3)
#define SZ_W33   (B_*128*3)
#define SZ_W32   (B_*256*3)
#define SZ_W31   (B_*512*3)
#define SZ_W30   (B_*N_*3)
#define SZ_CBUF  (B_*512*20*64)       // 5.24M floats (sa1/sa3/sa4 peak)

#define OFF_XYZ4  0
#define OFF_NRM   (OFF_XYZ4 + SZ_XYZ4)
#define OFF_SKIP0 (OFF_NRM + SZ_NRM)
#define OFF_X1    (OFF_SKIP0 + SZ_SKIP0)
#define OFF_X2    (OFF_X1 + SZ_X1)
#define OFF_X3    (OFF_X2 + SZ_X2)
#define OFF_X4    (OFF_X3 + SZ_X3)
#define OFF_F1    (OFF_X4 + SZ_X4)
#define OFF_F2    (OFF_F1 + SZ_F1)
#define OFF_F3    (OFF_F2 + SZ_F2)
#define OFF_F4    (OFF_F3 + SZ_F3)
#define OFF_G3    (OFF_F4 + SZ_F4)
#define OFF_G2    (OFF_G3 + SZ_G3)
#define OFF_G1    (OFF_G2 + SZ_G2)
#define OFF_G0    (OFF_G1 + SZ_G1)
#define OFF_NI1   (OFF_G0 + SZ_G0)
#define OFF_NI2   (OFF_NI1 + SZ_NI1)
#define OFF_NI3   (OFF_NI2 + SZ_NI2)
#define OFF_NI4   (OFF_NI3 + SZ_NI3)
#define OFF_I33   (OFF_NI4 + SZ_NI4)
#define OFF_I32   (OFF_I33 + SZ_I33)
#define OFF_I31   (OFF_I32 + SZ_I32)
#define OFF_I30   (OFF_I31 + SZ_I31)
#define OFF_W33   (OFF_I30 + SZ_I30)
#define OFF_W32   (OFF_W33 + SZ_W33)
#define OFF_W31   (OFF_W32 + SZ_W32)
#define OFF_W30   (OFF_W31 + SZ_W31)
#define OFF_CBUF  (OFF_W30 + SZ_W30)
#define SCRATCH_TOTAL (OFF_CBUF + SZ_CBUF)

__device__ __align__(16) float g_scratch[SCRATCH_TOTAL];

// ---------------------------------------------------------------------------
// prep
// ---------------------------------------------------------------------------
__global__ void prep_kernel(const float* __restrict__ x, const float* __restrict__ cls,
                            float4* __restrict__ xyz4, float* __restrict__ nrm,
                            float* __restrict__ skip0) {
    int n = blockIdx.x * blockDim.x + threadIdx.x;
    int b = blockIdx.y;
    if (n >= N_) return;
    const float* xb = x + (size_t)b * 6 * N_;
    float px = xb[0*N_+n], py = xb[1*N_+n], pz = xb[2*N_+n];
    float nx = xb[3*N_+n], ny = xb[4*N_+n], nz = xb[5*N_+n];
    float pp = px*px + py*py + pz*pz;
    xyz4[(size_t)b*N_+n] = make_float4(px, py, pz, pp);
    float* np_ = nrm + ((size_t)b*N_+n)*3;
    np_[0]=nx; np_[1]=ny; np_[2]=nz;
    float* sk = skip0 + ((size_t)b*N_+n)*22;
    #pragma unroll
    for (int c = 0; c < 16; c++) sk[c] = cls[b*16+c];
    sk[16]=px; sk[17]=py; sk[18]=pz;
    sk[19]=nx; sk[20]=ny; sk[21]=nz;
}

// ---------------------------------------------------------------------------
// FPS (proven fused form)
// ---------------------------------------------------------------------------
#define FPS_NT 512

struct FpsRed {
    unsigned key[16];
    int      idx[16];
    float4   bc;
};

template<int P>
__device__ void fps_level(const float4* __restrict__ pts, int M, int S,
                          float4* __restrict__ o, float4* spts, FpsRed* r) {
    const int tid = threadIdx.x;
    float px[P], py[P], pz[P], dist[P];
    #pragma unroll
    for (int j = 0; j < P; j++) {
        int i = tid + j*FPS_NT;
        if (i < M) {
            float4 p = pts[i];
            spts[i] = p;
            px[j]=p.x; py[j]=p.y; pz[j]=p.z; dist[j]=1e10f;
        } else {
            px[j]=0.f; py[j]=0.f; pz[j]=0.f; dist[j]=-1.0f;
        }
    }
    if (tid == 0) {
        float4 p0 = pts[0];
        r->bc = make_float4(p0.x, p0.y, p0.z, p0.x*p0.x + p0.y*p0.y + p0.z*p0.z);
    }
    __syncthreads();

    for (int it = 0; it < S; ++it) {
        float4 f = r->bc;
        if (tid == 0) o[it] = f;

        float bv = -1.0f; int bj = 0;
        #pragma unroll
        for (int j = 0; j < P; j++) {
            float dx = px[j]-f.x, dy = py[j]-f.y, dz = pz[j]-f.z;
            float d = dx*dx + dy*dy + dz*dz;
            float nd = fminf(dist[j], d);
            dist[j] = nd;
            if (nd > bv) { bv = nd; bj = j; }
        }
        int myi = tid + bj*FPS_NT;
        unsigned key = (bv > 0.0f) ? __float_as_uint(bv) : 0u;
        unsigned wmax = __reduce_max_sync(0xffffffffu, key);
        int cand = (key == wmax) ? myi : 0x7fffffff;
        int wmin = __reduce_min_sync(0xffffffffu, cand);
        if ((tid & 31) == 0) { r->key[tid>>5] = wmax; r->idx[tid>>5] = wmin; }
        __syncthreads();
        if (tid < 32) {
            unsigned k2 = (tid < (FPS_NT/32)) ? r->key[tid] : 0u;
            int      i2 = (tid < (FPS_NT/32)) ? r->idx[tid] : 0x7fffffff;
            unsigned g  = __reduce_max_sync(0xffffffffu, k2);
            int c2 = (k2 == g) ? i2 : 0x7fffffff;
            int win = __reduce_min_sync(0xffffffffu, c2);
            if (tid == 0) {
                float4 p = spts[win];
                r->bc = make_float4(p.x, p.y, p.z, p.x*p.x + p.y*p.y + p.z*p.z);
            }
        }
        __syncthreads();
    }
    __syncthreads();
}

__global__ void __launch_bounds__(FPS_NT)
fps_all_kernel(const float4* __restrict__ xyz4,
               float4* __restrict__ x1, float4* __restrict__ x2,
               float4* __restrict__ x3, float4* __restrict__ x4) {
    extern __shared__ __align__(16) float4 spts[];
    __shared__ FpsRed r;
    int b = blockIdx.x;
    fps_level<8>(xyz4 + (size_t)b*N_, N_, 512, x1 + (size_t)b*512, spts, &r);
    fps_level<1>(x1 + (size_t)b*512, 512, 256, x2 + (size_t)b*256, spts, &r);
    fps_level<1>(x2 + (size_t)b*256, 256, 128, x3 + (size_t)b*128, spts, &r);
    fps_level<1>(x3 + (size_t)b*128, 128, 64,  x4 + (size_t)b*64,  spts, &r);
}

// ---------------------------------------------------------------------------
// kNN (x4-unrolled; ascending-m inserts preserve top_k tie-break)
// ---------------------------------------------------------------------------
template<int K>
__device__ __forceinline__ void knn_insert(float d, int m, float* bd, int* bi) {
    if (d < bd[K-1]) {
        #pragma unroll
        for (int t = K-1; t >= 0; --t) {
            bool pred_gt = (t > 0) ? (bd[t-1] > d) : false;
            if (bd[t] > d) {
                if (pred_gt) { bd[t] = bd[t-1]; bi[t] = bi[t-1]; }
                else         { bd[t] = d;       bi[t] = m; }
            }
        }
    }
}

template<int K>
__device__ __forceinline__ void knn_scan(float4 qp, const float4* __restrict__ ref,
                                         int M, float* bd, int* bi) {
    float qq = qp.w;
    #pragma unroll
    for (int j = 0; j < K; j++) { bd[j] = 3.0e38f; bi[j] = 0; }
    for (int m = 0; m < M; m += 4) {
        float4 r0 = ref[m+0];
        float4 r1 = ref[m+1];
        float4 r2 = ref[m+2];
        float4 r3 = ref[m+3];
        float d0 = qq - 2.0f*(qp.x*r0.x + qp.y*r0.y + qp.z*r0.z) + r0.w;
        float d1 = qq - 2.0f*(qp.x*r1.x + qp.y*r1.y + qp.z*r1.z) + r1.w;
        float d2 = qq - 2.0f*(qp.x*r2.x + qp.y*r2.y + qp.z*r2.z) + r2.w;
        float d3 = qq - 2.0f*(qp.x*r3.x + qp.y*r3.y + qp.z*r3.z) + r3.w;
        knn_insert<K>(d0, m+0, bd, bi);
        knn_insert<K>(d1, m+1, bd, bi);
        knn_insert<K>(d2, m+2, bd, bi);
        knn_insert<K>(d3, m+3, bd, bi);
    }
}

__device__ __forceinline__ void knn20_body(const float4* __restrict__ q,
                                           const float4* __restrict__ ref,
                                           int s, int M, int* __restrict__ out) {
    float bd[20]; int bi[20];
    knn_scan<20>(q[s], ref, M, bd, bi);
    int* o = out + (size_t)s*20;
    #pragma unroll
    for (int j = 0; j < 20; j++) o[j] = bi[j];
}

__device__ __forceinline__ void knn3w_body(const float4* __restrict__ q,
                                           const float4* __restrict__ ref,
                                           int s, int M,
                                           int* __restrict__ oi, float* __restrict__ ow) {
    float4 qp = q[s];
    float bd[3]; int bi[3];
    knn_scan<3>(qp, ref, M, bd, bi);
    float wv[3]; float wsum = 0.0f;
    #pragma unroll
    for (int j = 0; j < 3; j++) {
        float4 r = ref[bi[j]];
        float dx = r.x-qp.x, dy = r.y-qp.y, dz = r.z-qp.z;
        float dd = dx*dx + dy*dy + dz*dz;
        float w = 1.0f / (dd + 1e-8f);
        wv[j] = w; wsum += w;
    }
    float inv = 1.0f / wsum;
    #pragma unroll
    for (int j = 0; j < 3; j++) {
        oi[(size_t)s*3 + j] = bi[j];
        ow[(size_t)s*3 + j] = wv[j]*inv;
    }
}

__global__ void knn20_all_kernel(const float4* __restrict__ xyz4,
                                 const float4* __restrict__ x1, const float4* __restrict__ x2,
                                 const float4* __restrict__ x3, const float4* __restrict__ x4,
                                 int* __restrict__ ni1, int* __restrict__ ni2,
                                 int* __restrict__ ni3, int* __restrict__ ni4) {
    int blk = blockIdx.x, b = blockIdx.y, tid = threadIdx.x;
    if (blk < 4) {
        int s = blk*128 + tid;
        knn20_body(x1 + (size_t)b*512, xyz4 + (size_t)b*N_, s, N_, ni1 + (size_t)b*512*20);
    } else if (blk < 6) {
        int s = (blk-4)*128 + tid;
        knn20_body(x2 + (size_t)b*256, x1 + (size_t)b*512, s, 512, ni2 + (size_t)b*256*20);
    } else if (blk < 7) {
        knn20_body(x3 + (size_t)b*128, x2 + (size_t)b*256, tid, 256, ni3 + (size_t)b*128*20);
    } else {
        if (tid < 64)
            knn20_body(x4 + (size_t)b*64, x3 + (size_t)b*128, tid, 128, ni4 + (size_t)b*64*20);
    }
}

__global__ void knn3_all_kernel(const float4* __restrict__ xyz4,
                                const float4* __restrict__ x1, const float4* __restrict__ x2,
                                const float4* __restrict__ x3, const float4* __restrict__ x4,
                                int* __restrict__ i30, int* __restrict__ i31,
                                int* __restrict__ i32, int* __restrict__ i33,
                                float* __restrict__ w30, float* __restrict__ w31,
                                float* __restrict__ w32, float* __restrict__ w33) {
    int blk = blockIdx.x, b = blockIdx.y, tid = threadIdx.x;
    if (blk < 32) {
        int s = blk*128 + tid;
        knn3w_body(xyz4 + (size_t)b*N_, x1 + (size_t)b*512, s, 512,
                   i30 + (size_t)b*N_*3, w30 + (size_t)b*N_*3);
    } else if (blk < 36) {
        int s = (blk-32)*128 + tid;
        knn3w_body(x1 + (size_t)b*512, x2 + (size_t)b*256, s, 256,
                   i31 + (size_t)b*512*3, w31 + (size_t)b*512*3);
    } else if (blk < 38) {
        int s = (blk-36)*128 + tid;
        knn3w_body(x2 + (size_t)b*256, x3 + (size_t)b*128, s, 128,
                   i32 + (size_t)b*256*3, w32 + (size_t)b*256*3);
    } else {
        knn3w_body(x3 + (size_t)b*128, x4 + (size_t)b*64, tid, 64,
                   i33 + (size_t)b*128*3, w33 + (size_t)b*128*3);
    }
}

// ---------------------------------------------------------------------------
// SA maxpool: out[bs,d] = relu(max_k C[bs*20+k, d] + bias[d])
// ---------------------------------------------------------------------------
template<int COUT>
__global__ void sa_maxpool_kernel(const float* __restrict__ C, const float* __restrict__ bias,
                                  int S, float* __restrict__ out) {
    int e = blockIdx.x * blockDim.x + threadIdx.x;
    int total = B_ * S * COUT;
    if (e >= total) return;
    int d = e % COUT;
    int bs = e / COUT;
    const float* cp = C + (size_t)bs*20*COUT + d;
    float m = cp[0];
    #pragma unroll 4
    for (int k = 1; k < 20; k++) m = fmaxf(m, cp[(size_t)k*COUT]);
    out[e] = fmaxf(m + bias[d], 0.0f);
}

// ---------------------------------------------------------------------------
// TF32 GEMM core pieces
// ---------------------------------------------------------------------------
__device__ __forceinline__ unsigned f2tf32(float f) {
    unsigned r; asm("cvt.rna.tf32.f32 %0, %1;" : "=r"(r) : "f"(f)); return r;
}

// ---------------------------------------------------------------------------
// SA GEMM with fused gather: rows = (b*S+s)*20+k, A[row,c] = rel-xyz|feat|0.
// C[rows, COUT] (no bias). BM=128, BN=64, BK=16, 256 threads.
// ---------------------------------------------------------------------------
template<int CIN>
__global__ void __launch_bounds__(256)
gemm_sa_kernel(const float4* __restrict__ qxyz, const float4* __restrict__ rxyz,
               const float* __restrict__ rfeat, const int* __restrict__ nidx,
               int S, int M,
               const float* __restrict__ Wm, float* __restrict__ C, int N) {
    constexpr int CFEAT = CIN - 3;
    __shared__ unsigned As[16][132];
    __shared__ unsigned Bs[16][68];
    int bm = blockIdx.x * 128;
    int bn = blockIdx.y * 64;
    int tid = threadIdx.x;
    int warp = tid >> 5, lane = tid & 31;
    int wm = (warp & 3) * 32;
    int wn = (warp >> 2) * 32;
    int g = lane >> 2, tq = lane & 3;

    // hoisted per-row gather state (2 rows per thread, fixed across k-tiles)
    int ar = tid >> 2;
    int ak = (tid & 3) * 4;
    int nrow[2]; int bsrow[2]; int brow[2];
    #pragma unroll
    for (int h = 0; h < 2; h++) {
        int grow = bm + ar + h*64;
        int bs = grow / 20;
        nrow[h] = nidx[grow];
        bsrow[h] = bs;
        brow[h] = bs / S;
    }

    float acc[2][4][4];
    #pragma unroll
    for (int mt = 0; mt < 2; mt++)
        #pragma unroll
        for (int nt = 0; nt < 4; nt++)
            #pragma unroll
            for (int j = 0; j < 4; j++) acc[mt][nt][j] = 0.0f;

    int ktiles = (CIN + 15) >> 4;
    for (int t = 0; t < ktiles; t++) {
        int k0 = t * 16;
        #pragma unroll
        for (int h = 0; h < 2; h++) {
            int row = ar + h*64;
            const float* rf = rfeat + ((size_t)brow[h]*M + nrow[h])*CFEAT;
            const float* rx = (const float*)(rxyz + (size_t)brow[h]*M + nrow[h]);
            const float* qx = (const float*)(qxyz + bsrow[h]);
            #pragma unroll
            for (int j = 0; j < 4; j++) {
                int c = k0 + ak + j;
                float v = 0.0f;
                if (c < CIN) {
                    if (c < 3) v = rx[c] - qx[c];
                    else       v = rf[c-3];
                }
                As[ak+j][row] = f2tf32(v);
            }
        }
        {
            int kk = tid >> 4;
            int nn = (tid & 15) * 4;
            float4 v = make_float4(0.f,0.f,0.f,0.f);
            if (k0 + kk < CIN)
                v = *(const float4*)&Wm[(size_t)(k0+kk)*N + bn + nn];
            Bs[kk][nn+0] = f2tf32(v.x);
            Bs[kk][nn+1] = f2tf32(v.y);
            Bs[kk][nn+2] = f2tf32(v.z);
            Bs[kk][nn+3] = f2tf32(v.w);
        }
        __syncthreads();
        #pragma unroll
        for (int kh = 0; kh < 2; kh++) {
            int kb = kh*8;
            unsigned a[2][4], bfr[4][2];
            #pragma unroll
            for (int mt = 0; mt < 2; mt++) {
                int m0 = wm + mt*16;
                a[mt][0] = As[kb+tq][m0+g];
                a[mt][1] = As[kb+tq][m0+g+8];
                a[mt][2] = As[kb+tq+4][m0+g];
                a[mt][3] = As[kb+tq+4][m0+g+8];
            }
            #pragma unroll
            for (int nt = 0; nt < 4; nt++) {
                int n0 = wn + nt*8;
                bfr[nt][0] = Bs[kb+tq][n0+g];
                bfr[nt][1] = Bs[kb+tq+4][n0+g];
            }
            #pragma unroll
            for (int mt = 0; mt < 2; mt++)
                #pragma unroll
                for (int nt = 0; nt < 4; nt++) {
                    asm volatile(
                        "mma.sync.aligned.m16n8k8.row.col.f32.tf32.tf32.f32 "
                        "{%0,%1,%2,%3}, {%4,%5,%6,%7}, {%8,%9}, {%0,%1,%2,%3};"
                        : "+f"(acc[mt][nt][0]), "+f"(acc[mt][nt][1]),
                          "+f"(acc[mt][nt][2]), "+f"(acc[mt][nt][3])
                        : "r"(a[mt][0]), "r"(a[mt][1]), "r"(a[mt][2]), "r"(a[mt][3]),
                          "r"(bfr[nt][0]), "r"(bfr[nt][1]));
                }
        }
        __syncthreads();
    }

    #pragma unroll
    for (int mt = 0; mt < 2; mt++) {
        int row0 = bm + wm + mt*16 + g;
        #pragma unroll
        for (int nt = 0; nt < 4; nt++) {
            int col = bn + wn + nt*8 + 2*tq;
            *(float2*)&C[(size_t)row0*N + col]     = make_float2(acc[mt][nt][0], acc[mt][nt][1]);
            *(float2*)&C[(size_t)(row0+8)*N + col] = make_float2(acc[mt][nt][2], acc[mt][nt][3]);
        }
    }
}

// ---------------------------------------------------------------------------
// FP GEMM with fused interp-gather: rows = b*Sq+s,
// A[row,c] = interp(fr) (c<CI) | skip (CI<=c<CI+CS) | 0. bias+relu epilogue.
// ---------------------------------------------------------------------------
template<int CI, int CS>
__global__ void __launch_bounds__(256)
gemm_fp_kernel(const float* __restrict__ fr, const float* __restrict__ skip,
               const int* __restrict__ idx3, const float* __restrict__ w3,
               int Sq, int M,
               const float* __restrict__ Wm, const float* __restrict__ bias,
               float* __restrict__ C, int N) {
    constexpr int CTOT = CI + CS;
    __shared__ unsigned As[16][132];
    __shared__ unsigned Bs[16][68];
    int bm = blockIdx.x * 128;
    int bn = blockIdx.y * 64;
    int tid = threadIdx.x;
    int warp = tid >> 5, lane = tid & 31;
    int wm = (warp & 3) * 32;
    int wn = (warp >> 2) * 32;
    int g = lane >> 2, tq = lane & 3;

    // hoisted per-row interp state (2 rows per thread)
    int ar = tid >> 2;
    int ak = (tid & 3) * 4;
    const float* fp0[2]; const float* fp1[2]; const float* fp2[2];
    float wr0[2], wr1[2], wr2[2];
    const float* skp[2];
    #pragma unroll
    for (int h = 0; h < 2; h++) {
        int grow = bm + ar + h*64;
        int b = grow / Sq;
        const int*   ip = idx3 + (size_t)grow*3;
        const float* wp = w3   + (size_t)grow*3;
        size_t base = (size_t)b*M;
        fp0[h] = fr + (base + ip[0])*CI;
        fp1[h] = fr + (base + ip[1])*CI;
        fp2[h] = fr + (base + ip[2])*CI;
        wr0[h] = wp[0]; wr1[h] = wp[1]; wr2[h] = wp[2];
        skp[h] = skip + (size_t)grow*CS;
    }

    float acc[2][4][4];
    #pragma unroll
    for (int mt = 0; mt < 2; mt++)
        #pragma unroll
        for (int nt = 0; nt < 4; nt++)
            #pragma unroll
            for (int j = 0; j < 4; j++) acc[mt][nt][j] = 0.0f;

    int ktiles = (CTOT + 15) >> 4;
    for (int t = 0; t < ktiles; t++) {
        int k0 = t * 16;
        #pragma unroll
        for (int h = 0; h < 2; h++) {
            int row = ar + h*64;
            #pragma unroll
            for (int j = 0; j < 4; j++) {
                int c = k0 + ak + j;
                float v = 0.0f;
                if (c < CI) {
                    v = wr0[h]*fp0[h][c] + wr1[h]*fp1[h][c] + wr2[h]*fp2[h][c];
                } else if (c < CTOT) {
                    v = skp[h][c - CI];
                }
                As[ak+j][row] = f2tf32(v);
            }
        }
        {
            int kk = tid >> 4;
            int nn = (tid & 15) * 4;
            float4 v = make_float4(0.f,0.f,0.f,0.f);
            if (k0 + kk < CTOT)
                v = *(const float4*)&Wm[(size_t)(k0+kk)*N + bn + nn];
            Bs[kk][nn+0] = f2tf32(v.x);
            Bs[kk][nn+1] = f2tf32(v.y);
            Bs[kk][nn+2] = f2tf32(v.z);
            Bs[kk][nn+3] = f2tf32(v.w);
        }
        __syncthreads();
        #pragma unroll
        for (int kh = 0; kh < 2; kh++) {
            int kb = kh*8;
            unsigned a[2][4], bfr[4][2];
            #pragma unroll
            for (int mt = 0; mt < 2; mt++) {
                int m0 = wm + mt*16;
                a[mt][0] = As[kb+tq][m0+g];
                a[mt][1] = As[kb+tq][m0+g+8];
                a[mt][2] = As[kb+tq+4][m0+g];
                a[mt][3] = As[kb+tq+4][m0+g+8];
            }
            #pragma unroll
            for (int nt = 0; nt < 4; nt++) {
                int n0 = wn + nt*8;
                bfr[nt][0] = Bs[kb+tq][n0+g];
                bfr[nt][1] = Bs[kb+tq+4][n0+g];
            }
            #pragma unroll
            for (int mt = 0; mt < 2; mt++)
                #pragma unroll
                for (int nt = 0; nt < 4; nt++) {
                    asm volatile(
                        "mma.sync.aligned.m16n8k8.row.col.f32.tf32.tf32.f32 "
                        "{%0,%1,%2,%3}, {%4,%5,%6,%7}, {%8,%9}, {%0,%1,%2,%3};"
                        : "+f"(acc[mt][nt][0]), "+f"(acc[mt][nt][1]),
                          "+f"(acc[mt][nt][2]), "+f"(acc[mt][nt][3])
                        : "r"(a[mt][0]), "r"(a[mt][1]), "r"(a[mt][2]), "r"(a[mt][3]),
                          "r"(bfr[nt][0]), "r"(bfr[nt][1]));
                }
        }
        __syncthreads();
    }

    #pragma unroll
    for (int mt = 0; mt < 2; mt++) {
        int row0 = bm + wm + mt*16 + g;
        #pragma unroll
        for (int nt = 0; nt < 4; nt++) {
            int col = bn + wn + nt*8 + 2*tq;
            float b0v = bias[col], b1v = bias[col+1];
            float2 v0 = make_float2(fmaxf(acc[mt][nt][0] + b0v, 0.f),
                                    fmaxf(acc[mt][nt][1] + b1v, 0.f));
            float2 v1 = make_float2(fmaxf(acc[mt][nt][2] + b0v, 0.f),
                                    fmaxf(acc[mt][nt][3] + b1v, 0.f));
            *(float2*)&C[(size_t)row0*N + col]     = v0;
            *(float2*)&C[(size_t)(row0+8)*N + col] = v1;
        }
    }
}

// ---------------------------------------------------------------------------
// Seg head + transpose (proven forms)
// ---------------------------------------------------------------------------
__global__ void seg_kernel(const float* __restrict__ g0, const float* __restrict__ Wseg,
                           const float* __restrict__ bseg, float* __restrict__ out) {
    constexpr int TS = 16;
    __shared__ __align__(16) float sg[TS * 128];
    int b = blockIdx.y;
    int s0 = blockIdx.x * TS;
    int tid = threadIdx.x;
    for (int e = tid; e < TS*128; e += 64)
        sg[e] = g0[((size_t)b*N_ + s0)*128 + e];
    __syncthreads();
    int j = tid;
    if (j < 50) {
        float acc[TS];
        #pragma unroll
        for (int t = 0; t < TS; t++) acc[t] = 0.0f;
        for (int c = 0; c < 128; c += 4) {
            float w0 = Wseg[(c+0)*50 + j];
            float w1 = Wseg[(c+1)*50 + j];
            float w2 = Wseg[(c+2)*50 + j];
            float w3 = Wseg[(c+3)*50 + j];
            #pragma unroll
            for (int t = 0; t < TS; t++) {
                float4 v = *(const float4*)&sg[t*128 + c];
                acc[t] += v.x*w0 + v.y*w1 + v.z*w2 + v.w*w3;
            }
        }
        float bb = bseg[j];
        #pragma unroll
        for (int t = 0; t < TS; t++)
            out[((size_t)b*N_ + s0 + t)*50 + j] = acc[t] + bb;
    }
}

__global__ void transpose_kernel(const float* __restrict__ g0, float* __restrict__ out) {
    __shared__ float tile[32][33];
    int b = blockIdx.z;
    int n0 = blockIdx.x * 32, c0 = blockIdx.y * 32;
    int tx = threadIdx.x, ty = threadIdx.y;
    tile[ty][tx] = g0[((size_t)b*N_ + n0 + ty)*128 + c0 + tx];
    __syncthreads();
    out[((size_t)b*128 + c0 + ty)*N_ + n0 + tx] = tile[tx][ty];
}

// ---------------------------------------------------------------------------
extern "C" void kernel_launch(void* const* d_in, const int* in_sizes, int n_in,
                              void* d_out, int out_size) {
    const float* x      = (const float*)d_in[0];
    const float* cls    = (const float*)d_in[1];
    const float* W0 = (const float*)d_in[2];  const float* b0 = (const float*)d_in[3];
    const float* W1 = (const float*)d_in[4];  const float* b1 = (const float*)d_in[5];
    const float* W2 = (const float*)d_in[6];  const float* b2 = (const float*)d_in[7];
    const float* W3 = (const float*)d_in[8];  const float* b3 = (const float*)d_in[9];
    const float* F3 = (const float*)d_in[10]; const float* fb3 = (const float*)d_in[11];
    const float* F2 = (const float*)d_in[12]; const float* fb2 = (const float*)d_in[13];
    const float* F1 = (const float*)d_in[14]; const float* fb1 = (const float*)d_in[15];
    const float* F0 = (const float*)d_in[16]; const float* fb0 = (const float*)d_in[17];
    const float* Wseg = (const float*)d_in[18]; const float* bseg = (const float*)d_in[19];

    float* scratch = nullptr;
    cudaGetSymbolAddress((void**)&scratch, g_scratch);

    float4* xyz4 = (float4*)(scratch + OFF_XYZ4);
    float* nrm   = scratch + OFF_NRM;
    float* skip0 = scratch + OFF_SKIP0;
    float4* x1 = (float4*)(scratch + OFF_X1);
    float4* x2 = (float4*)(scratch + OFF_X2);
    float4* x3 = (float4*)(scratch + OFF_X3);
    float4* x4 = (float4*)(scratch + OFF_X4);
    float* f1 = scratch + OFF_F1;  float* f2 = scratch + OFF_F2;
    float* f3 = scratch + OFF_F3;  float* f4 = scratch + OFF_F4;
    float* g3 = scratch + OFF_G3;  float* g2 = scratch + OFF_G2;
    float* g1 = scratch + OFF_G1;  float* g0 = scratch + OFF_G0;
    int* ni1 = (int*)(scratch + OFF_NI1);
    int* ni2 = (int*)(scratch + OFF_NI2);
    int* ni3 = (int*)(scratch + OFF_NI3);
    int* ni4 = (int*)(scratch + OFF_NI4);
    int* i33 = (int*)(scratch + OFF_I33);
    int* i32 = (int*)(scratch + OFF_I32);
    int* i31 = (int*)(scratch + OFF_I31);
    int* i30 = (int*)(scratch + OFF_I30);
    float* w33 = scratch + OFF_W33;
    float* w32 = scratch + OFF_W32;
    float* w31 = scratch + OFF_W31;
    float* w30 = scratch + OFF_W30;
    float* Cbuf = scratch + OFF_CBUF;

    float* out1 = (float*)d_out;                    // result [B,N,50]
    float* out2 = out1 + (size_t)B_ * N_ * 50;      // g0^T   [B,128,N]

    const int fps_smem = N_ * (int)sizeof(float4);
    cudaFuncSetAttribute(fps_all_kernel, cudaFuncAttributeMaxDynamicSharedMemorySize, fps_smem);

    prep_kernel<<<dim3(N_/256, B_), 256>>>(x, cls, xyz4, nrm, skip0);
    fps_all_kernel<<<B_, FPS_NT, fps_smem>>>(xyz4, x1, x2, x3, x4);

    knn20_all_kernel<<<dim3(8, B_), 128>>>(xyz4, x1, x2, x3, x4, ni1, ni2, ni3, ni4);
    knn3_all_kernel<<<dim3(39, B_), 128>>>(xyz4, x1, x2, x3, x4,
                                           i30, i31, i32, i33, w30, w31, w32, w33);

    // ---- SA chain (fused-gather gemm -> maxpool) ----
    gemm_sa_kernel<6><<<dim3(81920/128, 1), 256>>>(x1, xyz4, nrm, ni1, 512, N_, W0, Cbuf, 64);
    sa_maxpool_kernel<64><<<(B_*512*64+255)/256, 256>>>(Cbuf, b0, 512, f1);

    gemm_sa_kernel<67><<<dim3(40960/128, 2), 256>>>(x2, x1, f1, ni2, 256, 512, W1, Cbuf, 128);
    sa_maxpool_kernel<128><<<(B_*256*128+255)/256, 256>>>(Cbuf, b1, 256, f2);

    gemm_sa_kernel<131><<<dim3(20480/128, 4), 256>>>(x3, x2, f2, ni3, 128, 256, W2, Cbuf, 256);
    sa_maxpool_kernel<256><<<(B_*128*256+255)/256, 256>>>(Cbuf, b2, 128, f3);

    gemm_sa_kernel<259><<<dim3(10240/128, 8), 256>>>(x4, x3, f3, ni4, 64, 128, W3, Cbuf, 512);
    sa_maxpool_kernel<512><<<(B_*64*512+255)/256, 256>>>(Cbuf, b3, 64, f4);

    // ---- FP chain (fused-interp gemm, bias+relu) ----
    gemm_fp_kernel<512,256><<<dim3(1024/128, 8), 256>>>(f4, f3, i33, w33, 128, 64, F3, fb3, g3, 512);
    gemm_fp_kernel<512,128><<<dim3(2048/128, 4), 256>>>(g3, f2, i32, w32, 256, 128, F2, fb2, g2, 256);
    gemm_fp_kernel<256,64><<<dim3(4096/128, 2), 256>>>(g2, f1, i31, w31, 512, 256, F1, fb1, g1, 128);
    gemm_fp_kernel<128,22><<<dim3(32768/128, 2), 256>>>(g1, skip0, i30, w30, N_, 512, F0, fb0, g0, 128);

    // Seg head + transposed feature output
    seg_kernel<<<dim3(N_/16, B_), 64>>>(g0, Wseg, bseg, out1);
    transpose_kernel<<<dim3(N_/32, 128/32, B_), dim3(32,32)>>>(g0, out2);
}

// round 12
// speedup vs baseline: 1.3646x; 1.1289x over previous
#include <cuda_runtime.h>
#include <cuda_bf16.h>
#include <cstdint>

// ---------------------------------------------------------------------------
// PointNet++ part-seg forward. TF32 tensor-core MLPs (R8 skeleton) + FPS with
// single-barrier double-buffered all-warp reduction:
// prep -> FPS -> knn20 -> knn3(+weights)
//   -> [sa_gather -> gemm_tc -> maxpool] x4
//   -> [fp_gather -> gemm_tc(bias+relu)] x4 -> seg + transpose
// ---------------------------------------------------------------------------

#define B_ 8
#define N_ 4096

// ---- scratch layout (floats) ----
#define SZ_XYZ4  (B_*N_*4)
#define SZ_NRM   (B_*N_*3)
#define SZ_SKIP0 (B_*N_*22)
#define SZ_X1    (B_*512*4)
#define SZ_X2    (B_*256*4)
#define SZ_X3    (B_*128*4)
#define SZ_X4    (B_*64*4)
#define SZ_F1    (B_*512*64)
#define SZ_F2    (B_*256*128)
#define SZ_F3    (B_*128*256)
#define SZ_F4    (B_*64*512)
#define SZ_G3    (B_*128*512)
#define SZ_G2    (B_*256*256)
#define SZ_G1    (B_*512*128)
#define SZ_G0    (B_*N_*128)
#define SZ_NI1   (B_*512*20)
#define SZ_NI2   (B_*256*20)
#define SZ_NI3   (B_*128*20)
#define SZ_NI4   (B_*64*20)
#define SZ_I33   (B_*128*3)
#define SZ_I32   (B_*256*3)
#define SZ_I31   (B_*512*3)
#define SZ_I30   (B_*N_*3)
#define SZ_W33   (B_*128*3)
#define SZ_W32   (B_*256*3)
#define SZ_W31   (B_*512*3)
#define SZ_W30   (B_*N_*3)
#define SZ_ABUF  (B_*N_*152)
#define SZ_CBUF  (B_*512*20*64)

#define OFF_XYZ4  0
#define OFF_NRM   (OFF_XYZ4 + SZ_XYZ4)
#define OFF_SKIP0 (OFF_NRM + SZ_NRM)
#define OFF_X1    (OFF_SKIP0 + SZ_SKIP0)
#define OFF_X2    (OFF_X1 + SZ_X1)
#define OFF_X3    (OFF_X2 + SZ_X2)
#define OFF_X4    (OFF_X3 + SZ_X3)
#define OFF_F1    (OFF_X4 + SZ_X4)
#define OFF_F2    (OFF_F1 + SZ_F1)
#define OFF_F3    (OFF_F2 + SZ_F2)
#define OFF_F4    (OFF_F3 + SZ_F3)
#define OFF_G3    (OFF_F4 + SZ_F4)
#define OFF_G2    (OFF_G3 + SZ_G3)
#define OFF_G1    (OFF_G2 + SZ_G2)
#define OFF_G0    (OFF_G1 + SZ_G1)
#define OFF_NI1   (OFF_G0 + SZ_G0)
#define OFF_NI2   (OFF_NI1 + SZ_NI1)
#define OFF_NI3   (OFF_NI2 + SZ_NI2)
#define OFF_NI4   (OFF_NI3 + SZ_NI3)
#define OFF_I33   (OFF_NI4 + SZ_NI4)
#define OFF_I32   (OFF_I33 + SZ_I33)
#define OFF_I31   (OFF_I32 + SZ_I32)
#define OFF_I30   (OFF_I31 + SZ_I31)
#define OFF_W33   (OFF_I30 + SZ_I30)
#define OFF_W32   (OFF_W33 + SZ_W33)
#define OFF_W31   (OFF_W32 + SZ_W32)
#define OFF_W30   (OFF_W31 + SZ_W31)
#define OFF_ABUF  (OFF_W30 + SZ_W30)
#define OFF_CBUF  (OFF_ABUF + SZ_ABUF)
#define SCRATCH_TOTAL (OFF_CBUF + SZ_CBUF)

__device__ __align__(16) float g_scratch[SCRATCH_TOTAL];

// ---------------------------------------------------------------------------
// prep
// ---------------------------------------------------------------------------
__global__ void prep_kernel(const float* __restrict__ x, const float* __restrict__ cls,
                            float4* __restrict__ xyz4, float* __restrict__ nrm,
                            float* __restrict__ skip0) {
    int n = blockIdx.x * blockDim.x + threadIdx.x;
    int b = blockIdx.y;
    if (n >= N_) return;
    const float* xb = x + (size_t)b * 6 * N_;
    float px = xb[0*N_+n], py = xb[1*N_+n], pz = xb[2*N_+n];
    float nx = xb[3*N_+n], ny = xb[4*N_+n], nz = xb[5*N_+n];
    float pp = px*px + py*py + pz*pz;
    xyz4[(size_t)b*N_+n] = make_float4(px, py, pz, pp);
    float* np_ = nrm + ((size_t)b*N_+n)*3;
    np_[0]=nx; np_[1]=ny; np_[2]=nz;
    float* sk = skip0 + ((size_t)b*N_+n)*22;
    #pragma unroll
    for (int c = 0; c < 16; c++) sk[c] = cls[b*16+c];
    sk[16]=px; sk[17]=py; sk[18]=pz;
    sk[19]=nx; sk[20]=ny; sk[21]=nz;
}

// ---------------------------------------------------------------------------
// FPS: single-barrier iteration. Double-buffered per-warp partials, all-warp
// redundant final REDUX, every thread loads spts[win] (LDS broadcast).
// Tie-break: max dist-key, then min index (matches jnp.argmax).
// ---------------------------------------------------------------------------
#define FPS_NT 512
#define FPS_NW (FPS_NT/32)

struct FpsRed {
    unsigned key[2][FPS_NW];
    int      idx[2][FPS_NW];
};

template<int P>
__device__ void fps_level(const float4* __restrict__ pts, int M, int S,
                          float4* __restrict__ o, float4* spts, FpsRed* r) {
    const int tid = threadIdx.x;
    const int lane = tid & 31;
    const int w = tid >> 5;
    float px[P], py[P], pz[P], dist[P];
    #pragma unroll
    for (int j = 0; j < P; j++) {
        int i = tid + j*FPS_NT;
        if (i < M) {
            float4 p = pts[i];
            spts[i] = p;
            px[j]=p.x; py[j]=p.y; pz[j]=p.z; dist[j]=1e10f;
        } else {
            px[j]=0.f; py[j]=0.f; pz[j]=0.f; dist[j]=-1.0f;
        }
    }
    __syncthreads();

    int win = 0;   // jax scan: first far = 0
    for (int it = 0; it < S; ++it) {
        float4 f = spts[win];
        if (tid == 0) o[it] = f;

        float bv = -1.0f; int bj = 0;
        #pragma unroll
        for (int j = 0; j < P; j++) {
            float dx = px[j]-f.x, dy = py[j]-f.y, dz = pz[j]-f.z;
            float d = dx*dx + dy*dy + dz*dz;
            float nd = fminf(dist[j], d);
            dist[j] = nd;
            if (nd > bv) { bv = nd; bj = j; }
        }
        int myi = tid + bj*FPS_NT;
        unsigned key = (bv > 0.0f) ? __float_as_uint(bv) : 0u;
        unsigned wmax = __reduce_max_sync(0xffffffffu, key);
        int cand = (key == wmax) ? myi : 0x7fffffff;
        int wmin = __reduce_min_sync(0xffffffffu, cand);
        int buf = it & 1;
        if (lane == 0) { r->key[buf][w] = wmax; r->idx[buf][w] = wmin; }
        __syncthreads();
        // all warps do the final reduce redundantly (no second barrier)
        unsigned k2 = (lane < FPS_NW) ? r->key[buf][lane] : 0u;
        int      i2 = (lane < FPS_NW) ? r->idx[buf][lane] : 0x7fffffff;
        unsigned g  = __reduce_max_sync(0xffffffffu, k2);
        int c2 = (k2 == g) ? i2 : 0x7fffffff;
        win = __reduce_min_sync(0xffffffffu, c2);
    }
    __syncthreads();
}

__global__ void __launch_bounds__(FPS_NT)
fps_all_kernel(const float4* __restrict__ xyz4,
               float4* __restrict__ x1, float4* __restrict__ x2,
               float4* __restrict__ x3, float4* __restrict__ x4) {
    extern __shared__ __align__(16) float4 spts[];
    __shared__ FpsRed r;
    int b = blockIdx.x;
    fps_level<8>(xyz4 + (size_t)b*N_, N_, 512, x1 + (size_t)b*512, spts, &r);
    fps_level<1>(x1 + (size_t)b*512, 512, 256, x2 + (size_t)b*256, spts, &r);
    fps_level<1>(x2 + (size_t)b*256, 256, 128, x3 + (size_t)b*128, spts, &r);
    fps_level<1>(x3 + (size_t)b*128, 128, 64,  x4 + (size_t)b*64,  spts, &r);
}

// ---------------------------------------------------------------------------
// kNN (x4-unrolled; ascending-m inserts preserve top_k tie-break)
// ---------------------------------------------------------------------------
template<int K>
__device__ __forceinline__ void knn_insert(float d, int m, float* bd, int* bi) {
    if (d < bd[K-1]) {
        #pragma unroll
        for (int t = K-1; t >= 0; --t) {
            bool pred_gt = (t > 0) ? (bd[t-1] > d) : false;
            if (bd[t] > d) {
                if (pred_gt) { bd[t] = bd[t-1]; bi[t] = bi[t-1]; }
                else         { bd[t] = d;       bi[t] = m; }
            }
        }
    }
}

template<int K>
__device__ __forceinline__ void knn_scan(float4 qp, const float4* __restrict__ ref,
                                         int M, float* bd, int* bi) {
    float qq = qp.w;
    #pragma unroll
    for (int j = 0; j < K; j++) { bd[j] = 3.0e38f; bi[j] = 0; }
    for (int m = 0; m < M; m += 4) {
        float4 r0 = ref[m+0];
        float4 r1 = ref[m+1];
        float4 r2 = ref[m+2];
        float4 r3 = ref[m+3];
        float d0 = qq - 2.0f*(qp.x*r0.x + qp.y*r0.y + qp.z*r0.z) + r0.w;
        float d1 = qq - 2.0f*(qp.x*r1.x + qp.y*r1.y + qp.z*r1.z) + r1.w;
        float d2 = qq - 2.0f*(qp.x*r2.x + qp.y*r2.y + qp.z*r2.z) + r2.w;
        float d3 = qq - 2.0f*(qp.x*r3.x + qp.y*r3.y + qp.z*r3.z) + r3.w;
        knn_insert<K>(d0, m+0, bd, bi);
        knn_insert<K>(d1, m+1, bd, bi);
        knn_insert<K>(d2, m+2, bd, bi);
        knn_insert<K>(d3, m+3, bd, bi);
    }
}

__device__ __forceinline__ void knn20_body(const float4* __restrict__ q,
                                           const float4* __restrict__ ref,
                                           int s, int M, int* __restrict__ out) {
    float bd[20]; int bi[20];
    knn_scan<20>(q[s], ref, M, bd, bi);
    int* o = out + (size_t)s*20;
    #pragma unroll
    for (int j = 0; j < 20; j++) o[j] = bi[j];
}

__device__ __forceinline__ void knn3w_body(const float4* __restrict__ q,
                                           const float4* __restrict__ ref,
                                           int s, int M,
                                           int* __restrict__ oi, float* __restrict__ ow) {
    float4 qp = q[s];
    float bd[3]; int bi[3];
    knn_scan<3>(qp, ref, M, bd, bi);
    float wv[3]; float wsum = 0.0f;
    #pragma unroll
    for (int j = 0; j < 3; j++) {
        float4 r = ref[bi[j]];
        float dx = r.x-qp.x, dy = r.y-qp.y, dz = r.z-qp.z;
        float dd = dx*dx + dy*dy + dz*dz;
        float w = 1.0f / (dd + 1e-8f);
        wv[j] = w; wsum += w;
    }
    float inv = 1.0f / wsum;
    #pragma unroll
    for (int j = 0; j < 3; j++) {
        oi[(size_t)s*3 + j] = bi[j];
        ow[(size_t)s*3 + j] = wv[j]*inv;
    }
}

__global__ void knn20_all_kernel(const float4* __restrict__ xyz4,
                                 const float4* __restrict__ x1, const float4* __restrict__ x2,
                                 const float4* __restrict__ x3, const float4* __restrict__ x4,
                                 int* __restrict__ ni1, int* __restrict__ ni2,
                                 int* __restrict__ ni3, int* __restrict__ ni4) {
    int blk = blockIdx.x, b = blockIdx.y, tid = threadIdx.x;
    if (blk < 4) {
        int s = blk*128 + tid;
        knn20_body(x1 + (size_t)b*512, xyz4 + (size_t)b*N_, s, N_, ni1 + (size_t)b*512*20);
    } else if (blk < 6) {
        int s = (blk-4)*128 + tid;
        knn20_body(x2 + (size_t)b*256, x1 + (size_t)b*512, s, 512, ni2 + (size_t)b*256*20);
    } else if (blk < 7) {
        knn20_body(x3 + (size_t)b*128, x2 + (size_t)b*256, tid, 256, ni3 + (size_t)b*128*20);
    } else {
        if (tid < 64)
            knn20_body(x4 + (size_t)b*64, x3 + (size_t)b*128, tid, 128, ni4 + (size_t)b*64*20);
    }
}

__global__ void knn3_all_kernel(const float4* __restrict__ xyz4,
                                const float4* __restrict__ x1, const float4* __restrict__ x2,
                                const float4* __restrict__ x3, const float4* __restrict__ x4,
                                int* __restrict__ i30, int* __restrict__ i31,
                                int* __restrict__ i32, int* __restrict__ i33,
                                float* __restrict__ w30, float* __restrict__ w31,
                                float* __restrict__ w32, float* __restrict__ w33) {
    int blk = blockIdx.x, b = blockIdx.y, tid = threadIdx.x;
    if (blk < 32) {
        int s = blk*128 + tid;
        knn3w_body(xyz4 + (size_t)b*N_, x1 + (size_t)b*512, s, 512,
                   i30 + (size_t)b*N_*3, w30 + (size_t)b*N_*3);
    } else if (blk < 36) {
        int s = (blk-32)*128 + tid;
        knn3w_body(x1 + (size_t)b*512, x2 + (size_t)b*256, s, 256,
                   i31 + (size_t)b*512*3, w31 + (size_t)b*512*3);
    } else if (blk < 38) {
        int s = (blk-36)*128 + tid;
        knn3w_body(x2 + (size_t)b*256, x3 + (size_t)b*128, s, 128,
                   i32 + (size_t)b*256*3, w32 + (size_t)b*256*3);
    } else {
        knn3w_body(x3 + (size_t)b*128, x4 + (size_t)b*64, tid, 64,
                   i33 + (size_t)b*128*3, w33 + (size_t)b*128*3);
    }
}

// ---------------------------------------------------------------------------
// SA gather: A[(b*S+s)*20+k, c] = rel-xyz | feat | 0 pad
// ---------------------------------------------------------------------------
template<int CIN, int LDA>
__global__ void sa_gather_kernel(const float4* __restrict__ qxyz, const float4* __restrict__ rxyz,
                                 const float* __restrict__ rfeat, const int* __restrict__ nidx,
                                 int S, int M, float* __restrict__ A) {
    constexpr int CFEAT = CIN - 3;
    int e = blockIdx.x * blockDim.x + threadIdx.x;
    int total = B_ * S * 20 * LDA;
    if (e >= total) return;
    int c = e % LDA;
    int row = e / LDA;
    int bs = row / 20;
    int b = bs / S;
    float v = 0.0f;
    if (c < CIN) {
        int n = nidx[row];
        if (c < 3) {
            v = ((const float*)(rxyz + (size_t)b*M + n))[c]
              - ((const float*)(qxyz + bs))[c];
        } else {
            v = rfeat[((size_t)b*M + n)*CFEAT + (c-3)];
        }
    }
    A[e] = v;
}

// ---------------------------------------------------------------------------
// SA maxpool
// ---------------------------------------------------------------------------
template<int COUT>
__global__ void sa_maxpool_kernel(const float* __restrict__ C, const float* __restrict__ bias,
                                  int S, float* __restrict__ out) {
    int e = blockIdx.x * blockDim.x + threadIdx.x;
    int total = B_ * S * COUT;
    if (e >= total) return;
    int d = e % COUT;
    int bs = e / COUT;
    const float* cp = C + (size_t)bs*20*COUT + d;
    float m = cp[0];
    #pragma unroll 4
    for (int k = 1; k < 20; k++) m = fmaxf(m, cp[(size_t)k*COUT]);
    out[e] = fmaxf(m + bias[d], 0.0f);
}

// ---------------------------------------------------------------------------
// FP gather: A[b*Sq+s, c] = 3-NN interp (c<CI) | skip | 0 pad
// ---------------------------------------------------------------------------
template<int CI, int CS, int LDA>
__global__ void fp_gather_kernel(const float* __restrict__ fr, const float* __restrict__ skip,
                                 const int* __restrict__ idx3, const float* __restrict__ w3,
                                 int Sq, int M, float* __restrict__ A) {
    int e = blockIdx.x * blockDim.x + threadIdx.x;
    int total = B_ * Sq * LDA;
    if (e >= total) return;
    int c = e % LDA;
    int row = e / LDA;
    float v = 0.0f;
    if (c < CI) {
        int b = row / Sq;
        const int*   ip = idx3 + (size_t)row*3;
        const float* wp = w3   + (size_t)row*3;
        size_t base = (size_t)b*M;
        v = wp[0]*fr[(base + ip[0])*CI + c]
          + wp[1]*fr[(base + ip[1])*CI + c]
          + wp[2]*fr[(base + ip[2])*CI + c];
    } else if (c < CI + CS) {
        v = skip[(size_t)row*CS + (c - CI)];
    }
    A[e] = v;
}

// ---------------------------------------------------------------------------
// TF32 tensor-core GEMM (proven R8 form)
// ---------------------------------------------------------------------------
__device__ __forceinline__ unsigned f2tf32(float f) {
    unsigned r; asm("cvt.rna.tf32.f32 %0, %1;" : "=r"(r) : "f"(f)); return r;
}

template<bool BIAS_RELU>
__global__ void __launch_bounds__(256)
gemm_tc_kernel(const float* __restrict__ A, int lda,
               const float* __restrict__ Wm, const float* __restrict__ bias,
               float* __restrict__ C, int N, int Kdim) {
    __shared__ unsigned As[16][132];
    __shared__ unsigned Bs[16][68];
    int bm = blockIdx.x * 128;
    int bn = blockIdx.y * 64;
    int tid = threadIdx.x;
    int warp = tid >> 5, lane = tid & 31;
    int wm = (warp & 3) * 32;
    int wn = (warp >> 2) * 32;
    int g = lane >> 2, tq = lane & 3;

    float acc[2][4][4];
    #pragma unroll
    for (int mt = 0; mt < 2; mt++)
        #pragma unroll
        for (int nt = 0; nt < 4; nt++)
            #pragma unroll
            for (int j = 0; j < 4; j++) acc[mt][nt][j] = 0.0f;

    int ktiles = (Kdim + 15) >> 4;
    for (int t = 0; t < ktiles; t++) {
        int k0 = t * 16;
        {
            int r = tid >> 2;
            int kk = (tid & 3) * 4;
            #pragma unroll
            for (int h = 0; h < 2; h++) {
                int row = r + h*64;
                float4 v = make_float4(0.f,0.f,0.f,0.f);
                if (k0 + kk < lda)
                    v = *(const float4*)&A[(size_t)(bm+row)*lda + k0 + kk];
                As[kk+0][row] = f2tf32(v.x);
                As[kk+1][row] = f2tf32(v.y);
                As[kk+2][row] = f2tf32(v.z);
                As[kk+3][row] = f2tf32(v.w);
            }
        }
        {
            int kk = tid >> 4;
            int nn = (tid & 15) * 4;
            float4 v = make_float4(0.f,0.f,0.f,0.f);
            if (k0 + kk < Kdim)
                v = *(const float4*)&Wm[(size_t)(k0+kk)*N + bn + nn];
            Bs[kk][nn+0] = f2tf32(v.x);
            Bs[kk][nn+1] = f2tf32(v.y);
            Bs[kk][nn+2] = f2tf32(v.z);
            Bs[kk][nn+3] = f2tf32(v.w);
        }
        __syncthreads();
        #pragma unroll
        for (int kh = 0; kh < 2; kh++) {
            int kb = kh*8;
            unsigned a[2][4], bfr[4][2];
            #pragma unroll
            for (int mt = 0; mt < 2; mt++) {
                int m0 = wm + mt*16;
                a[mt][0] = As[kb+tq][m0+g];
                a[mt][1] = As[kb+tq][m0+g+8];
                a[mt][2] = As[kb+tq+4][m0+g];
                a[mt][3] = As[kb+tq+4][m0+g+8];
            }
            #pragma unroll
            for (int nt = 0; nt < 4; nt++) {
                int n0 = wn + nt*8;
                bfr[nt][0] = Bs[kb+tq][n0+g];
                bfr[nt][1] = Bs[kb+tq+4][n0+g];
            }
            #pragma unroll
            for (int mt = 0; mt < 2; mt++)
                #pragma unroll
                for (int nt = 0; nt < 4; nt++) {
                    asm volatile(
                        "mma.sync.aligned.m16n8k8.row.col.f32.tf32.tf32.f32 "
                        "{%0,%1,%2,%3}, {%4,%5,%6,%7}, {%8,%9}, {%0,%1,%2,%3};"
                        : "+f"(acc[mt][nt][0]), "+f"(acc[mt][nt][1]),
                          "+f"(acc[mt][nt][2]), "+f"(acc[mt][nt][3])
                        : "r"(a[mt][0]), "r"(a[mt][1]), "r"(a[mt][2]), "r"(a[mt][3]),
                          "r"(bfr[nt][0]), "r"(bfr[nt][1]));
                }
        }
        __syncthreads();
    }

    #pragma unroll
    for (int mt = 0; mt < 2; mt++) {
        int row0 = bm + wm + mt*16 + g;
        #pragma unroll
        for (int nt = 0; nt < 4; nt++) {
            int col = bn + wn + nt*8 + 2*tq;
            float2 v0 = make_float2(acc[mt][nt][0], acc[mt][nt][1]);
            float2 v1 = make_float2(acc[mt][nt][2], acc[mt][nt][3]);
            if (BIAS_RELU) {
                float b0v = bias[col], b1v = bias[col+1];
                v0.x = fmaxf(v0.x + b0v, 0.f); v0.y = fmaxf(v0.y + b1v, 0.f);
                v1.x = fmaxf(v1.x + b0v, 0.f); v1.y = fmaxf(v1.y + b1v, 0.f);
            }
            *(float2*)&C[(size_t)row0*N + col]     = v0;
            *(float2*)&C[(size_t)(row0+8)*N + col] = v1;
        }
    }
}

// ---------------------------------------------------------------------------
// Seg head + transpose (proven forms)
// ---------------------------------------------------------------------------
__global__ void seg_kernel(const float* __restrict__ g0, const float* __restrict__ Wseg,
                           const float* __restrict__ bseg, float* __restrict__ out) {
    constexpr int TS = 16;
    __shared__ __align__(16) float sg[TS * 128];
    int b = blockIdx.y;
    int s0 = blockIdx.x * TS;
    int tid = threadIdx.x;
    for (int e = tid; e < TS*128; e += 64)
        sg[e] = g0[((size_t)b*N_ + s0)*128 + e];
    __syncthreads();
    int j = tid;
    if (j < 50) {
        float acc[TS];
        #pragma unroll
        for (int t = 0; t < TS; t++) acc[t] = 0.0f;
        for (int c = 0; c < 128; c += 4) {
            float w0 = Wseg[(c+0)*50 + j];
            float w1 = Wseg[(c+1)*50 + j];
            float w2 = Wseg[(c+2)*50 + j];
            float w3 = Wseg[(c+3)*50 + j];
            #pragma unroll
            for (int t = 0; t < TS; t++) {
                float4 v = *(const float4*)&sg[t*128 + c];
                acc[t] += v.x*w0 + v.y*w1 + v.z*w2 + v.w*w3;
            }
        }
        float bb = bseg[j];
        #pragma unroll
        for (int t = 0; t < TS; t++)
            out[((size_t)b*N_ + s0 + t)*50 + j] = acc[t] + bb;
    }
}

__global__ void transpose_kernel(const float* __restrict__ g0, float* __restrict__ out) {
    __shared__ float tile[32][33];
    int b = blockIdx.z;
    int n0 = blockIdx.x * 32, c0 = blockIdx.y * 32;
    int tx = threadIdx.x, ty = threadIdx.y;
    tile[ty][tx] = g0[((size_t)b*N_ + n0 + ty)*128 + c0 + tx];
    __syncthreads();
    out[((size_t)b*128 + c0 + ty)*N_ + n0 + tx] = tile[tx][ty];
}

// ---------------------------------------------------------------------------
extern "C" void kernel_launch(void* const* d_in, const int* in_sizes, int n_in,
                              void* d_out, int out_size) {
    const float* x      = (const float*)d_in[0];
    const float* cls    = (const float*)d_in[1];
    const float* W0 = (const float*)d_in[2];  const float* b0 = (const float*)d_in[3];
    const float* W1 = (const float*)d_in[4];  const float* b1 = (const float*)d_in[5];
    const float* W2 = (const float*)d_in[6];  const float* b2 = (const float*)d_in[7];
    const float* W3 = (const float*)d_in[8];  const float* b3 = (const float*)d_in[9];
    const float* F3 = (const float*)d_in[10]; const float* fb3 = (const float*)d_in[11];
    const float* F2 = (const float*)d_in[12]; const float* fb2 = (const float*)d_in[13];
    const float* F1 = (const float*)d_in[14]; const float* fb1 = (const float*)d_in[15];
    const float* F0 = (const float*)d_in[16]; const float* fb0 = (const float*)d_in[17];
    const float* Wseg = (const float*)d_in[18]; const float* bseg = (const float*)d_in[19];

    float* scratch = nullptr;
    cudaGetSymbolAddress((void**)&scratch, g_scratch);

    float4* xyz4 = (float4*)(scratch + OFF_XYZ4);
    float* nrm   = scratch + OFF_NRM;
    float* skip0 = scratch + OFF_SKIP0;
    float4* x1 = (float4*)(scratch + OFF_X1);
    float4* x2 = (float4*)(scratch + OFF_X2);
    float4* x3 = (float4*)(scratch + OFF_X3);
    float4* x4 = (float4*)(scratch + OFF_X4);
    float* f1 = scratch + OFF_F1;  float* f2 = scratch + OFF_F2;
    float* f3 = scratch + OFF_F3;  float* f4 = scratch + OFF_F4;
    float* g3 = scratch + OFF_G3;  float* g2 = scratch + OFF_G2;
    float* g1 = scratch + OFF_G1;  float* g0 = scratch + OFF_G0;
    int* ni1 = (int*)(scratch + OFF_NI1);
    int* ni2 = (int*)(scratch + OFF_NI2);
    int* ni3 = (int*)(scratch + OFF_NI3);
    int* ni4 = (int*)(scratch + OFF_NI4);
    int* i33 = (int*)(scratch + OFF_I33);
    int* i32 = (int*)(scratch + OFF_I32);
    int* i31 = (int*)(scratch + OFF_I31);
    int* i30 = (int*)(scratch + OFF_I30);
    float* w33 = scratch + OFF_W33;
    float* w32 = scratch + OFF_W32;
    float* w31 = scratch + OFF_W31;
    float* w30 = scratch + OFF_W30;
    float* Abuf = scratch + OFF_ABUF;
    float* Cbuf = scratch + OFF_CBUF;

    float* out1 = (float*)d_out;                    // result [B,N,50]
    float* out2 = out1 + (size_t)B_ * N_ * 50;      // g0^T   [B,128,N]

    const int fps_smem = N_ * (int)sizeof(float4);
    cudaFuncSetAttribute(fps_all_kernel, cudaFuncAttributeMaxDynamicSharedMemorySize, fps_smem);

    prep_kernel<<<dim3(N_/256, B_), 256>>>(x, cls, xyz4, nrm, skip0);
    fps_all_kernel<<<B_, FPS_NT, fps_smem>>>(xyz4, x1, x2, x3, x4);

    knn20_all_kernel<<<dim3(8, B_), 128>>>(xyz4, x1, x2, x3, x4, ni1, ni2, ni3, ni4);
    knn3_all_kernel<<<dim3(39, B_), 128>>>(xyz4, x1, x2, x3, x4,
                                           i30, i31, i32, i33, w30, w31, w32, w33);

    // ---- SA chain ----
    {   // SA1: rows=81920, K=6 (lda 8), N=64
        int total = B_*512*20*8;
        sa_gather_kernel<6,8><<<(total+255)/256, 256>>>(x1, xyz4, nrm, ni1, 512, N_, Abuf);
        gemm_tc_kernel<false><<<dim3(81920/128, 1), 256>>>(Abuf, 8, W0, nullptr, Cbuf, 64, 6);
        int pt = B_*512*64;
        sa_maxpool_kernel<64><<<(pt+255)/256, 256>>>(Cbuf, b0, 512, f1);
    }
    {   // SA2: rows=40960, K=67 (lda 68), N=128
        int total = B_*256*20*68;
        sa_gather_kernel<67,68><<<(total+255)/256, 256>>>(x2, x1, f1, ni2, 256, 512, Abuf);
        gemm_tc_kernel<false><<<dim3(40960/128, 2), 256>>>(Abuf, 68, W1, nullptr, Cbuf, 128, 67);
        int pt = B_*256*128;
        sa_maxpool_kernel<128><<<(pt+255)/256, 256>>>(Cbuf, b1, 256, f2);
    }
    {   // SA3: rows=20480, K=131 (lda 132), N=256
        int total = B_*128*20*132;
        sa_gather_kernel<131,132><<<(total+255)/256, 256>>>(x3, x2, f2, ni3, 128, 256, Abuf);
        gemm_tc_kernel<false><<<dim3(20480/128, 4), 256>>>(Abuf, 132, W2, nullptr, Cbuf, 256, 131);
        int pt = B_*128*256;
        sa_maxpool_kernel<256><<<(pt+255)/256, 256>>>(Cbuf, b2, 128, f3);
    }
    {   // SA4: rows=10240, K=259 (lda 260), N=512
        int total = B_*64*20*260;
        sa_gather_kernel<259,260><<<(total+255)/256, 256>>>(x4, x3, f3, ni4, 64, 128, Abuf);
        gemm_tc_kernel<false><<<dim3(10240/128, 8), 256>>>(Abuf, 260, W3, nullptr, Cbuf, 512, 259);
        int pt = B_*64*512;
        sa_maxpool_kernel<512><<<(pt+255)/256, 256>>>(Cbuf, b3, 64, f4);
    }

    // ---- FP chain ----
    {   // FP3: rows=1024, K=768, N=512
        int total = B_*128*768;
        fp_gather_kernel<512,256,768><<<(total+255)/256, 256>>>(f4, f3, i33, w33, 128, 64, Abuf);
        gemm_tc_kernel<true><<<dim3(1024/128, 8), 256>>>(Abuf, 768, F3, fb3, g3, 512, 768);
    }
    {   // FP2: rows=2048, K=640, N=256
        int total = B_*256*640;
        fp_gather_kernel<512,128,640><<<(total+255)/256, 256>>>(g3, f2, i32, w32, 256, 128, Abuf);
        gemm_tc_kernel<true><<<dim3(2048/128, 4), 256>>>(Abuf, 640, F2, fb2, g2, 256, 640);
    }
    {   // FP1: rows=4096, K=320, N=128
        int total = B_*512*320;
        fp_gather_kernel<256,64,320><<<(total+255)/256, 256>>>(g2, f1, i31, w31, 512, 256, Abuf);
        gemm_tc_kernel<true><<<dim3(4096/128, 2), 256>>>(Abuf, 320, F1, fb1, g1, 128, 320);
    }
    {   // FP0: rows=32768, K=150 (lda 152), N=128
        int total = B_*N_*152;
        fp_gather_kernel<128,22,152><<<(total+255)/256, 256>>>(g1, skip0, i30, w30, N_, 512, Abuf);
        gemm_tc_kernel<true><<<dim3(32768/128, 2), 256>>>(Abuf, 152, F0, fb0, g0, 128, 150);
    }

    // Seg head + transposed feature output
    seg_kernel<<<dim3(N_/16, B_), 64>>>(g0, Wseg, bseg, out1);
    transpose_kernel<<<dim3(N_/32, 128/32, B_), dim3(32,32)>>>(g0, out2);
}

// round 15
// speedup vs baseline: 1.6487x; 1.2082x over previous
#include <cuda_runtime.h>
#include <cuda_bf16.h>
#include <cstdint>

// ---------------------------------------------------------------------------
// PointNet++ part-seg forward. TF32 tensor-core MLPs + single-barrier FPS +
// split-scan kNN (T threads per query, ordered merge):
// prep -> FPS -> knn20(T=4) -> knn3(T=2,+weights)
//   -> [sa_gather -> gemm_tc -> maxpool] x4
//   -> [fp_gather -> gemm_tc(bias+relu)] x4 -> seg + transpose
// ---------------------------------------------------------------------------

#define B_ 8
#define N_ 4096

// ---- scratch layout (floats) ----
#define SZ_XYZ4  (B_*N_*4)
#define SZ_NRM   (B_*N_*3)
#define SZ_SKIP0 (B_*N_*22)
#define SZ_X1    (B_*512*4)
#define SZ_X2    (B_*256*4)
#define SZ_X3    (B_*128*4)
#define SZ_X4    (B_*64*4)
#define SZ_F1    (B_*512*64)
#define SZ_F2    (B_*256*128)
#define SZ_F3    (B_*128*256)
#define SZ_F4    (B_*64*512)
#define SZ_G3    (B_*128*512)
#define SZ_G2    (B_*256*256)
#define SZ_G1    (B_*512*128)
#define SZ_G0    (B_*N_*128)
#define SZ_NI1   (B_*512*20)
#define SZ_NI2   (B_*256*20)
#define SZ_NI3   (B_*128*20)
#define SZ_NI4   (B_*64*20)
#define SZ_I33   (B_*128*3)
#define SZ_I32   (B_*256*3)
#define SZ_I31   (B_*512*3)
#define SZ_I30   (B_*N_*3)
#define SZ_W33   (B_*128*3)
#define SZ_W32   (B_*256*3)
#define SZ_W31   (B_*512*3)
#define SZ_W30   (B_*N_*3)
#define SZ_ABUF  (B_*N_*152)
#define SZ_CBUF  (B_*512*20*64)

#define OFF_XYZ4  0
#define OFF_NRM   (OFF_XYZ4 + SZ_XYZ4)
#define OFF_SKIP0 (OFF_NRM + SZ_NRM)
#define OFF_X1    (OFF_SKIP0 + SZ_SKIP0)
#define OFF_X2    (OFF_X1 + SZ_X1)
#define OFF_X3    (OFF_X2 + SZ_X2)
#define OFF_X4    (OFF_X3 + SZ_X3)
#define OFF_F1    (OFF_X4 + SZ_X4)
#define OFF_F2    (OFF_F1 + SZ_F1)
#define OFF_F3    (OFF_F2 + SZ_F2)
#define OFF_F4    (OFF_F3 + SZ_F3)
#define OFF_G3    (OFF_F4 + SZ_F4)
#define OFF_G2    (OFF_G3 + SZ_G3)
#define OFF_G1    (OFF_G2 + SZ_G2)
#define OFF_G0    (OFF_G1 + SZ_G1)
#define OFF_NI1   (OFF_G0 + SZ_G0)
#define OFF_NI2   (OFF_NI1 + SZ_NI1)
#define OFF_NI3   (OFF_NI2 + SZ_NI2)
#define OFF_NI4   (OFF_NI3 + SZ_NI3)
#define OFF_I33   (OFF_NI4 + SZ_NI4)
#define OFF_I32   (OFF_I33 + SZ_I33)
#define OFF_I31   (OFF_I32 + SZ_I32)
#define OFF_I30   (OFF_I31 + SZ_I31)
#define OFF_W33   (OFF_I30 + SZ_I30)
#define OFF_W32   (OFF_W33 + SZ_W33)
#define OFF_W31   (OFF_W32 + SZ_W32)
#define OFF_W30   (OFF_W31 + SZ_W31)
#define OFF_ABUF  (OFF_W30 + SZ_W30)
#define OFF_CBUF  (OFF_ABUF + SZ_ABUF)
#define SCRATCH_TOTAL (OFF_CBUF + SZ_CBUF)

__device__ __align__(16) float g_scratch[SCRATCH_TOTAL];

// ---------------------------------------------------------------------------
// prep
// ---------------------------------------------------------------------------
__global__ void prep_kernel(const float* __restrict__ x, const float* __restrict__ cls,
                            float4* __restrict__ xyz4, float* __restrict__ nrm,
                            float* __restrict__ skip0) {
    int n = blockIdx.x * blockDim.x + threadIdx.x;
    int b = blockIdx.y;
    if (n >= N_) return;
    const float* xb = x + (size_t)b * 6 * N_;
    float px = xb[0*N_+n], py = xb[1*N_+n], pz = xb[2*N_+n];
    float nx = xb[3*N_+n], ny = xb[4*N_+n], nz = xb[5*N_+n];
    float pp = px*px + py*py + pz*pz;
    xyz4[(size_t)b*N_+n] = make_float4(px, py, pz, pp);
    float* np_ = nrm + ((size_t)b*N_+n)*3;
    np_[0]=nx; np_[1]=ny; np_[2]=nz;
    float* sk = skip0 + ((size_t)b*N_+n)*22;
    #pragma unroll
    for (int c = 0; c < 16; c++) sk[c] = cls[b*16+c];
    sk[16]=px; sk[17]=py; sk[18]=pz;
    sk[19]=nx; sk[20]=ny; sk[21]=nz;
}

// ---------------------------------------------------------------------------
// FPS (R12 single-barrier form)
// ---------------------------------------------------------------------------
#define FPS_NT 512
#define FPS_NW (FPS_NT/32)

struct FpsRed {
    unsigned key[2][FPS_NW];
    int      idx[2][FPS_NW];
};

template<int P>
__device__ void fps_level(const float4* __restrict__ pts, int M, int S,
                          float4* __restrict__ o, float4* spts, FpsRed* r) {
    const int tid = threadIdx.x;
    const int lane = tid & 31;
    const int w = tid >> 5;
    float px[P], py[P], pz[P], dist[P];
    #pragma unroll
    for (int j = 0; j < P; j++) {
        int i = tid + j*FPS_NT;
        if (i < M) {
            float4 p = pts[i];
            spts[i] = p;
            px[j]=p.x; py[j]=p.y; pz[j]=p.z; dist[j]=1e10f;
        } else {
            px[j]=0.f; py[j]=0.f; pz[j]=0.f; dist[j]=-1.0f;
        }
    }
    __syncthreads();

    int win = 0;
    for (int it = 0; it < S; ++it) {
        float4 f = spts[win];
        if (tid == 0) o[it] = f;

        float bv = -1.0f; int bj = 0;
        #pragma unroll
        for (int j = 0; j < P; j++) {
            float dx = px[j]-f.x, dy = py[j]-f.y, dz = pz[j]-f.z;
            float d = dx*dx + dy*dy + dz*dz;
            float nd = fminf(dist[j], d);
            dist[j] = nd;
            if (nd > bv) { bv = nd; bj = j; }
        }
        int myi = tid + bj*FPS_NT;
        unsigned key = (bv > 0.0f) ? __float_as_uint(bv) : 0u;
        unsigned wmax = __reduce_max_sync(0xffffffffu, key);
        int cand = (key == wmax) ? myi : 0x7fffffff;
        int wmin = __reduce_min_sync(0xffffffffu, cand);
        int buf = it & 1;
        if (lane == 0) { r->key[buf][w] = wmax; r->idx[buf][w] = wmin; }
        __syncthreads();
        unsigned k2 = (lane < FPS_NW) ? r->key[buf][lane] : 0u;
        int      i2 = (lane < FPS_NW) ? r->idx[buf][lane] : 0x7fffffff;
        unsigned g  = __reduce_max_sync(0xffffffffu, k2);
        int c2 = (k2 == g) ? i2 : 0x7fffffff;
        win = __reduce_min_sync(0xffffffffu, c2);
    }
    __syncthreads();
}

__global__ void __launch_bounds__(FPS_NT)
fps_all_kernel(const float4* __restrict__ xyz4,
               float4* __restrict__ x1, float4* __restrict__ x2,
               float4* __restrict__ x3, float4* __restrict__ x4) {
    extern __shared__ __align__(16) float4 spts[];
    __shared__ FpsRed r;
    int b = blockIdx.x;
    fps_level<8>(xyz4 + (size_t)b*N_, N_, 512, x1 + (size_t)b*512, spts, &r);
    fps_level<1>(x1 + (size_t)b*512, 512, 256, x2 + (size_t)b*256, spts, &r);
    fps_level<1>(x2 + (size_t)b*256, 256, 128, x3 + (size_t)b*128, spts, &r);
    fps_level<1>(x3 + (size_t)b*128, 128, 64,  x4 + (size_t)b*64,  spts, &r);
}

// ---------------------------------------------------------------------------
// kNN split-scan: each of T threads scans a disjoint ref segment keeping a
// private sorted top-K (same insert arithmetic, global indices), then one
// thread per query merges the T sorted lists by (d, idx) lexicographic order.
// Each per-thread list is (d asc, idx asc), so the merge reproduces the
// sequential top_k result exactly, including smallest-index tie-breaks.
// ---------------------------------------------------------------------------
template<int K>
__device__ __forceinline__ void knn_insert(float d, int m, float* bd, int* bi) {
    if (d < bd[K-1]) {
        #pragma unroll
        for (int t = K-1; t >= 0; --t) {
            bool pred_gt = (t > 0) ? (bd[t-1] > d) : false;
            if (bd[t] > d) {
                if (pred_gt) { bd[t] = bd[t-1]; bi[t] = bi[t-1]; }
                else         { bd[t] = d;       bi[t] = m; }
            }
        }
    }
}

template<int K>
__device__ __forceinline__ void knn_scan_seg(float4 qp, const float4* __restrict__ ref,
                                             int m0, int m1, float* bd, int* bi) {
    float qq = qp.w;
    #pragma unroll
    for (int j = 0; j < K; j++) { bd[j] = 3.0e38f; bi[j] = 0; }
    for (int m = m0; m < m1; m += 4) {
        float4 r0 = ref[m+0];
        float4 r1 = ref[m+1];
        float4 r2 = ref[m+2];
        float4 r3 = ref[m+3];
        float d0 = qq - 2.0f*(qp.x*r0.x + qp.y*r0.y + qp.z*r0.z) + r0.w;
        float d1 = qq - 2.0f*(qp.x*r1.x + qp.y*r1.y + qp.z*r1.z) + r1.w;
        float d2 = qq - 2.0f*(qp.x*r2.x + qp.y*r2.y + qp.z*r2.z) + r2.w;
        float d3 = qq - 2.0f*(qp.x*r3.x + qp.y*r3.y + qp.z*r3.z) + r3.w;
        knn_insert<K>(d0, m+0, bd, bi);
        knn_insert<K>(d1, m+1, bd, bi);
        knn_insert<K>(d2, m+2, bd, bi);
        knn_insert<K>(d3, m+3, bd, bi);
    }
}

// ---------------------------------------------------------------------------
// knn20 fused, T=4 threads/query, 32 queries/block (128 threads).
// grid.x = 30: [0,16) L1; [16,24) L2; [24,28) L3; [28,30) L4.
// ---------------------------------------------------------------------------
__global__ void __launch_bounds__(128)
knn20_all_kernel(const float4* __restrict__ xyz4,
                 const float4* __restrict__ x1, const float4* __restrict__ x2,
                 const float4* __restrict__ x3, const float4* __restrict__ x4,
                 int* __restrict__ ni1, int* __restrict__ ni2,
                 int* __restrict__ ni3, int* __restrict__ ni4) {
    constexpr int K = 20, T = 4, QB = 32;
    __shared__ float sd[QB][T][K];
    __shared__ int   si[QB][T][K];
    int blk = blockIdx.x, b = blockIdx.y;
    int ql = threadIdx.x >> 2;          // query within block
    int t  = threadIdx.x & 3;           // segment id

    const float4* q; const float4* ref; int Sq, M; int* out; int qi;
    if (blk < 16)      { q = x1 + (size_t)b*512; ref = xyz4 + (size_t)b*N_; Sq = 512; M = N_;  out = ni1 + (size_t)b*512*20; qi = blk*QB + ql; }
    else if (blk < 24) { q = x2 + (size_t)b*256; ref = x1 + (size_t)b*512;  Sq = 256; M = 512; out = ni2 + (size_t)b*256*20; qi = (blk-16)*QB + ql; }
    else if (blk < 28) { q = x3 + (size_t)b*128; ref = x2 + (size_t)b*256;  Sq = 128; M = 256; out = ni3 + (size_t)b*128*20; qi = (blk-24)*QB + ql; }
    else               { q = x4 + (size_t)b*64;  ref = x3 + (size_t)b*128;  Sq = 64;  M = 128; out = ni4 + (size_t)b*64*20;  qi = (blk-28)*QB + ql; }

    if (qi < Sq) {
        float bd[K]; int bi[K];
        int seg = M / T;
        knn_scan_seg<K>(q[qi], ref, t*seg, (t+1)*seg, bd, bi);
        #pragma unroll
        for (int j = 0; j < K; j++) { sd[ql][t][j] = bd[j]; si[ql][t][j] = bi[j]; }
    }
    __syncthreads();
    if (t == 0 && qi < Sq) {
        int head[T] = {0,0,0,0};
        int* o = out + (size_t)qi*K;
        #pragma unroll 4
        for (int j = 0; j < K; j++) {
            float best = 3.4e38f; int bidx = 0x7fffffff; int bt = 0;
            #pragma unroll
            for (int tt = 0; tt < T; tt++) {
                float d = sd[ql][tt][head[tt]];
                int   ii = si[ql][tt][head[tt]];
                if (d < best || (d == best && ii < bidx)) { best = d; bidx = ii; bt = tt; }
            }
            o[j] = bidx;
            head[bt]++;
        }
    }
}

// ---------------------------------------------------------------------------
// knn3 fused, T=2 threads/query, 64 queries/block (128 threads), + weights.
// grid.x = 78: [0,64) L0; [64,72) L1; [72,76) L2; [76,78) L3.
// ---------------------------------------------------------------------------
__global__ void __launch_bounds__(128)
knn3_all_kernel(const float4* __restrict__ xyz4,
                const float4* __restrict__ x1, const float4* __restrict__ x2,
                const float4* __restrict__ x3, const float4* __restrict__ x4,
                int* __restrict__ i30, int* __restrict__ i31,
                int* __restrict__ i32, int* __restrict__ i33,
                float* __restrict__ w30, float* __restrict__ w31,
                float* __restrict__ w32, float* __restrict__ w33) {
    constexpr int K = 3, T = 2, QB = 64;
    __shared__ float sd[QB][T][K];
    __shared__ int   si[QB][T][K];
    int blk = blockIdx.x, b = blockIdx.y;
    int ql = threadIdx.x >> 1;
    int t  = threadIdx.x & 1;

    const float4* q; const float4* ref; int Sq, M; int* oi; float* ow; int qi;
    if (blk < 64)      { q = xyz4 + (size_t)b*N_; ref = x1 + (size_t)b*512; Sq = N_;  M = 512; oi = i30 + (size_t)b*N_*3;  ow = w30 + (size_t)b*N_*3;  qi = blk*QB + ql; }
    else if (blk < 72) { q = x1 + (size_t)b*512;  ref = x2 + (size_t)b*256; Sq = 512; M = 256; oi = i31 + (size_t)b*512*3; ow = w31 + (size_t)b*512*3; qi = (blk-64)*QB + ql; }
    else if (blk < 76) { q = x2 + (size_t)b*256;  ref = x3 + (size_t)b*128; Sq = 256; M = 128; oi = i32 + (size_t)b*256*3; ow = w32 + (size_t)b*256*3; qi = (blk-72)*QB + ql; }
    else               { q = x3 + (size_t)b*128;  ref = x4 + (size_t)b*64;  Sq = 128; M = 64;  oi = i33 + (size_t)b*128*3; ow = w33 + (size_t)b*128*3; qi = (blk-76)*QB + ql; }

    if (qi < Sq) {
        float bd[K]; int bi[K];
        int seg = M / T;
        knn_scan_seg<K>(q[qi], ref, t*seg, (t+1)*seg, bd, bi);
        #pragma unroll
        for (int j = 0; j < K; j++) { sd[ql][t][j] = bd[j]; si[ql][t][j] = bi[j]; }
    }
    __syncthreads();
    if (t == 0 && qi < Sq) {
        int head[T] = {0,0};
        int merged[K];
        #pragma unroll
        for (int j = 0; j < K; j++) {
            float best = 3.4e38f; int bidx = 0x7fffffff; int bt = 0;
            #pragma unroll
            for (int tt = 0; tt < T; tt++) {
                float d = sd[ql][tt][head[tt]];
                int   ii = si[ql][tt][head[tt]];
                if (d < best || (d == best && ii < bidx)) { best = d; bidx = ii; bt = tt; }
            }
            merged[j] = bidx;
            head[bt]++;
        }
        // interpolation weights (direct-difference distances, like reference)
        float4 qp = q[qi];
        float wv[K]; float wsum = 0.0f;
        #pragma unroll
        for (int j = 0; j < K; j++) {
            float4 r = ref[merged[j]];
            float dx = r.x-qp.x, dy = r.y-qp.y, dz = r.z-qp.z;
            float dd = dx*dx + dy*dy + dz*dz;
            float w = 1.0f / (dd + 1e-8f);
            wv[j] = w; wsum += w;
        }
        float inv = 1.0f / wsum;
        #pragma unroll
        for (int j = 0; j < K; j++) {
            oi[(size_t)qi*3 + j] = merged[j];
            ow[(size_t)qi*3 + j] = wv[j]*inv;
        }
    }
}

// ---------------------------------------------------------------------------
// SA gather: A[(b*S+s)*20+k, c] = rel-xyz | feat | 0 pad
// ---------------------------------------------------------------------------
template<int CIN, int LDA>
__global__ void sa_gather_kernel(const float4* __restrict__ qxyz, const float4* __restrict__ rxyz,
                                 const float* __restrict__ rfeat, const int* __restrict__ nidx,
                                 int S, int M, float* __restrict__ A) {
    constexpr int CFEAT = CIN - 3;
    int e = blockIdx.x * blockDim.x + threadIdx.x;
    int total = B_ * S * 20 * LDA;
    if (e >= total) return;
    int c = e % LDA;
    int row = e / LDA;
    int bs = row / 20;
    int b = bs / S;
    float v = 0.0f;
    if (c < CIN) {
        int n = nidx[row];
        if (c < 3) {
            v = ((const float*)(rxyz + (size_t)b*M + n))[c]
              - ((const float*)(qxyz + bs))[c];
        } else {
            v = rfeat[((size_t)b*M + n)*CFEAT + (c-3)];
        }
    }
    A[e] = v;
}

// ---------------------------------------------------------------------------
// SA maxpool
// ---------------------------------------------------------------------------
template<int COUT>
__global__ void sa_maxpool_kernel(const float* __restrict__ C, const float* __restrict__ bias,
                                  int S, float* __restrict__ out) {
    int e = blockIdx.x * blockDim.x + threadIdx.x;
    int total = B_ * S * COUT;
    if (e >= total) return;
    int d = e % COUT;
    int bs = e / COUT;
    const float* cp = C + (size_t)bs*20*COUT + d;
    float m = cp[0];
    #pragma unroll 4
    for (int k = 1; k < 20; k++) m = fmaxf(m, cp[(size_t)k*COUT]);
    out[e] = fmaxf(m + bias[d], 0.0f);
}

// ---------------------------------------------------------------------------
// FP gather: A[b*Sq+s, c] = 3-NN interp (c<CI) | skip | 0 pad
// ---------------------------------------------------------------------------
template<int CI, int CS, int LDA>
__global__ void fp_gather_kernel(const float* __restrict__ fr, const float* __restrict__ skip,
                                 const int* __restrict__ idx3, const float* __restrict__ w3,
                                 int Sq, int M, float* __restrict__ A) {
    int e = blockIdx.x * blockDim.x + threadIdx.x;
    int total = B_ * Sq * LDA;
    if (e >= total) return;
    int c = e % LDA;
    int row = e / LDA;
    float v = 0.0f;
    if (c < CI) {
        int b = row / Sq;
        const int*   ip = idx3 + (size_t)row*3;
        const float* wp = w3   + (size_t)row*3;
        size_t base = (size_t)b*M;
        v = wp[0]*fr[(base + ip[0])*CI + c]
          + wp[1]*fr[(base + ip[1])*CI + c]
          + wp[2]*fr[(base + ip[2])*CI + c];
    } else if (c < CI + CS) {
        v = skip[(size_t)row*CS + (c - CI)];
    }
    A[e] = v;
}

// ---------------------------------------------------------------------------
// TF32 tensor-core GEMM (proven R8 form)
// ---------------------------------------------------------------------------
__device__ __forceinline__ unsigned f2tf32(float f) {
    unsigned r; asm("cvt.rna.tf32.f32 %0, %1;" : "=r"(r) : "f"(f)); return r;
}

template<bool BIAS_RELU>
__global__ void __launch_bounds__(256)
gemm_tc_kernel(const float* __restrict__ A, int lda,
               const float* __restrict__ Wm, const float* __restrict__ bias,
               float* __restrict__ C, int N, int Kdim) {
    __shared__ unsigned As[16][132];
    __shared__ unsigned Bs[16][68];
    int bm = blockIdx.x * 128;
    int bn = blockIdx.y * 64;
    int tid = threadIdx.x;
    int warp = tid >> 5, lane = tid & 31;
    int wm = (warp & 3) * 32;
    int wn = (warp >> 2) * 32;
    int g = lane >> 2, tq = lane & 3;

    float acc[2][4][4];
    #pragma unroll
    for (int mt = 0; mt < 2; mt++)
        #pragma unroll
        for (int nt = 0; nt < 4; nt++)
            #pragma unroll
            for (int j = 0; j < 4; j++) acc[mt][nt][j] = 0.0f;

    int ktiles = (Kdim + 15) >> 4;
    for (int t = 0; t < ktiles; t++) {
        int k0 = t * 16;
        {
            int r = tid >> 2;
            int kk = (tid & 3) * 4;
            #pragma unroll
            for (int h = 0; h < 2; h++) {
                int row = r + h*64;
                float4 v = make_float4(0.f,0.f,0.f,0.f);
                if (k0 + kk < lda)
                    v = *(const float4*)&A[(size_t)(bm+row)*lda + k0 + kk];
                As[kk+0][row] = f2tf32(v.x);
                As[kk+1][row] = f2tf32(v.y);
                As[kk+2][row] = f2tf32(v.z);
                As[kk+3][row] = f2tf32(v.w);
            }
        }
        {
            int kk = tid >> 4;
            int nn = (tid & 15) * 4;
            float4 v = make_float4(0.f,0.f,0.f,0.f);
            if (k0 + kk < Kdim)
                v = *(const float4*)&Wm[(size_t)(k0+kk)*N + bn + nn];
            Bs[kk][nn+0] = f2tf32(v.x);
            Bs[kk][nn+1] = f2tf32(v.y);
            Bs[kk][nn+2] = f2tf32(v.z);
            Bs[kk][nn+3] = f2tf32(v.w);
        }
        __syncthreads();
        #pragma unroll
        for (int kh = 0; kh < 2; kh++) {
            int kb = kh*8;
            unsigned a[2][4], bfr[4][2];
            #pragma unroll
            for (int mt = 0; mt < 2; mt++) {
                int m0 = wm + mt*16;
                a[mt][0] = As[kb+tq][m0+g];
                a[mt][1] = As[kb+tq][m0+g+8];
                a[mt][2] = As[kb+tq+4][m0+g];
                a[mt][3] = As[kb+tq+4][m0+g+8];
            }
            #pragma unroll
            for (int nt = 0; nt < 4; nt++) {
                int n0 = wn + nt*8;
                bfr[nt][0] = Bs[kb+tq][n0+g];
                bfr[nt][1] = Bs[kb+tq+4][n0+g];
            }
            #pragma unroll
            for (int mt = 0; mt < 2; mt++)
                #pragma unroll
                for (int nt = 0; nt < 4; nt++) {
                    asm volatile(
                        "mma.sync.aligned.m16n8k8.row.col.f32.tf32.tf32.f32 "
                        "{%0,%1,%2,%3}, {%4,%5,%6,%7}, {%8,%9}, {%0,%1,%2,%3};"
                        : "+f"(acc[mt][nt][0]), "+f"(acc[mt][nt][1]),
                          "+f"(acc[mt][nt][2]), "+f"(acc[mt][nt][3])
                        : "r"(a[mt][0]), "r"(a[mt][1]), "r"(a[mt][2]), "r"(a[mt][3]),
                          "r"(bfr[nt][0]), "r"(bfr[nt][1]));
                }
        }
        __syncthreads();
    }

    #pragma unroll
    for (int mt = 0; mt < 2; mt++) {
        int row0 = bm + wm + mt*16 + g;
        #pragma unroll
        for (int nt = 0; nt < 4; nt++) {
            int col = bn + wn + nt*8 + 2*tq;
            float2 v0 = make_float2(acc[mt][nt][0], acc[mt][nt][1]);
            float2 v1 = make_float2(acc[mt][nt][2], acc[mt][nt][3]);
            if (BIAS_RELU) {
                float b0v = bias[col], b1v = bias[col+1];
                v0.x = fmaxf(v0.x + b0v, 0.f); v0.y = fmaxf(v0.y + b1v, 0.f);
                v1.x = fmaxf(v1.x + b0v, 0.f); v1.y = fmaxf(v1.y + b1v, 0.f);
            }
            *(float2*)&C[(size_t)row0*N + col]     = v0;
            *(float2*)&C[(size_t)(row0+8)*N + col] = v1;
        }
    }
}

// ---------------------------------------------------------------------------
// Seg head + transpose (proven forms)
// ---------------------------------------------------------------------------
__global__ void seg_kernel(const float* __restrict__ g0, const float* __restrict__ Wseg,
                           const float* __restrict__ bseg, float* __restrict__ out) {
    constexpr int TS = 16;
    __shared__ __align__(16) float sg[TS * 128];
    int b = blockIdx.y;
    int s0 = blockIdx.x * TS;
    int tid = threadIdx.x;
    for (int e = tid; e < TS*128; e += 64)
        sg[e] = g0[((size_t)b*N_ + s0)*128 + e];
    __syncthreads();
    int j = tid;
    if (j < 50) {
        float acc[TS];
        #pragma unroll
        for (int t = 0; t < TS; t++) acc[t] = 0.0f;
        for (int c = 0; c < 128; c += 4) {
            float w0 = Wseg[(c+0)*50 + j];
            float w1 = Wseg[(c+1)*50 + j];
            float w2 = Wseg[(c+2)*50 + j];
            float w3 = Wseg[(c+3)*50 + j];
            #pragma unroll
            for (int t = 0; t < TS; t++) {
                float4 v = *(const float4*)&sg[t*128 + c];
                acc[t] += v.x*w0 + v.y*w1 + v.z*w2 + v.w*w3;
            }
        }
        float bb = bseg[j];
        #pragma unroll
        for (int t = 0; t < TS; t++)
            out[((size_t)b*N_ + s0 + t)*50 + j] = acc[t] + bb;
    }
}

__global__ void transpose_kernel(const float* __restrict__ g0, float* __restrict__ out) {
    __shared__ float tile[32][33];
    int b = blockIdx.z;
    int n0 = blockIdx.x * 32, c0 = blockIdx.y * 32;
    int tx = threadIdx.x, ty = threadIdx.y;
    tile[ty][tx] = g0[((size_t)b*N_ + n0 + ty)*128 + c0 + tx];
    __syncthreads();
    out[((size_t)b*128 + c0 + ty)*N_ + n0 + tx] = tile[tx][ty];
}

// ---------------------------------------------------------------------------
extern "C" void kernel_launch(void* const* d_in, const int* in_sizes, int n_in,
                              void* d_out, int out_size) {
    const float* x      = (const float*)d_in[0];
    const float* cls    = (const float*)d_in[1];
    const float* W0 = (const float*)d_in[2];  const float* b0 = (const float*)d_in[3];
    const float* W1 = (const float*)d_in[4];  const float* b1 = (const float*)d_in[5];
    const float* W2 = (const float*)d_in[6];  const float* b2 = (const float*)d_in[7];
    const float* W3 = (const float*)d_in[8];  const float* b3 = (const float*)d_in[9];
    const float* F3 = (const float*)d_in[10]; const float* fb3 = (const float*)d_in[11];
    const float* F2 = (const float*)d_in[12]; const float* fb2 = (const float*)d_in[13];
    const float* F1 = (const float*)d_in[14]; const float* fb1 = (const float*)d_in[15];
    const float* F0 = (const float*)d_in[16]; const float* fb0 = (const float*)d_in[17];
    const float* Wseg = (const float*)d_in[18]; const float* bseg = (const float*)d_in[19];

    float* scratch = nullptr;
    cudaGetSymbolAddress((void**)&scratch, g_scratch);

    float4* xyz4 = (float4*)(scratch + OFF_XYZ4);
    float* nrm   = scratch + OFF_NRM;
    float* skip0 = scratch + OFF_SKIP0;
    float4* x1 = (float4*)(scratch + OFF_X1);
    float4* x2 = (float4*)(scratch + OFF_X2);
    float4* x3 = (float4*)(scratch + OFF_X3);
    float4* x4 = (float4*)(scratch + OFF_X4);
    float* f1 = scratch + OFF_F1;  float* f2 = scratch + OFF_F2;
    float* f3 = scratch + OFF_F3;  float* f4 = scratch + OFF_F4;
    float* g3 = scratch + OFF_G3;  float* g2 = scratch + OFF_G2;
    float* g1 = scratch + OFF_G1;  float* g0 = scratch + OFF_G0;
    int* ni1 = (int*)(scratch + OFF_NI1);
    int* ni2 = (int*)(scratch + OFF_NI2);
    int* ni3 = (int*)(scratch + OFF_NI3);
    int* ni4 = (int*)(scratch + OFF_NI4);
    int* i33 = (int*)(scratch + OFF_I33);
    int* i32 = (int*)(scratch + OFF_I32);
    int* i31 = (int*)(scratch + OFF_I31);
    int* i30 = (int*)(scratch + OFF_I30);
    float* w33 = scratch + OFF_W33;
    float* w32 = scratch + OFF_W32;
    float* w31 = scratch + OFF_W31;
    float* w30 = scratch + OFF_W30;
    float* Abuf = scratch + OFF_ABUF;
    float* Cbuf = scratch + OFF_CBUF;

    float* out1 = (float*)d_out;                    // result [B,N,50]
    float* out2 = out1 + (size_t)B_ * N_ * 50;      // g0^T   [B,128,N]

    const int fps_smem = N_ * (int)sizeof(float4);
    cudaFuncSetAttribute(fps_all_kernel, cudaFuncAttributeMaxDynamicSharedMemorySize, fps_smem);

    prep_kernel<<<dim3(N_/256, B_), 256>>>(x, cls, xyz4, nrm, skip0);
    fps_all_kernel<<<B_, FPS_NT, fps_smem>>>(xyz4, x1, x2, x3, x4);

    knn20_all_kernel<<<dim3(30, B_), 128>>>(xyz4, x1, x2, x3, x4, ni1, ni2, ni3, ni4);
    knn3_all_kernel<<<dim3(78, B_), 128>>>(xyz4, x1, x2, x3, x4,
                                           i30, i31, i32, i33, w30, w31, w32, w33);

    // ---- SA chain ----
    {   // SA1: rows=81920, K=6 (lda 8), N=64
        int total = B_*512*20*8;
        sa_gather_kernel<6,8><<<(total+255)/256, 256>>>(x1, xyz4, nrm, ni1, 512, N_, Abuf);
        gemm_tc_kernel<false><<<dim3(81920/128, 1), 256>>>(Abuf, 8, W0, nullptr, Cbuf, 64, 6);
        int pt = B_*512*64;
        sa_maxpool_kernel<64><<<(pt+255)/256, 256>>>(Cbuf, b0, 512, f1);
    }
    {   // SA2: rows=40960, K=67 (lda 68), N=128
        int total = B_*256*20*68;
        sa_gather_kernel<67,68><<<(total+255)/256, 256>>>(x2, x1, f1, ni2, 256, 512, Abuf);
        gemm_tc_kernel<false><<<dim3(40960/128, 2), 256>>>(Abuf, 68, W1, nullptr, Cbuf, 128, 67);
        int pt = B_*256*128;
        sa_maxpool_kernel<128><<<(pt+255)/256, 256>>>(Cbuf, b1, 256, f2);
    }
    {   // SA3: rows=20480, K=131 (lda 132), N=256
        int total = B_*128*20*132;
        sa_gather_kernel<131,132><<<(total+255)/256, 256>>>(x3, x2, f2, ni3, 128, 256, Abuf);
        gemm_tc_kernel<false><<<dim3(20480/128, 4), 256>>>(Abuf, 132, W2, nullptr, Cbuf, 256, 131);
        int pt = B_*128*256;
        sa_maxpool_kernel<256><<<(pt+255)/256, 256>>>(Cbuf, b2, 128, f3);
    }
    {   // SA4: rows=10240, K=259 (lda 260), N=512
        int total = B_*64*20*260;
        sa_gather_kernel<259,260><<<(total+255)/256, 256>>>(x4, x3, f3, ni4, 64, 128, Abuf);
        gemm_tc_kernel<false><<<dim3(10240/128, 8), 256>>>(Abuf, 260, W3, nullptr, Cbuf, 512, 259);
        int pt = B_*64*512;
        sa_maxpool_kernel<512><<<(pt+255)/256, 256>>>(Cbuf, b3, 64, f4);
    }

    // ---- FP chain ----
    {   // FP3: rows=1024, K=768, N=512
        int total = B_*128*768;
        fp_gather_kernel<512,256,768><<<(total+255)/256, 256>>>(f4, f3, i33, w33, 128, 64, Abuf);
        gemm_tc_kernel<true><<<dim3(1024/128, 8), 256>>>(Abuf, 768, F3, fb3, g3, 512, 768);
    }
    {   // FP2: rows=2048, K=640, N=256
        int total = B_*256*640;
        fp_gather_kernel<512,128,640><<<(total+255)/256, 256>>>(g3, f2, i32, w32, 256, 128, Abuf);
        gemm_tc_kernel<true><<<dim3(2048/128, 4), 256>>>(Abuf, 640, F2, fb2, g2, 256, 640);
    }
    {   // FP1: rows=4096, K=320, N=128
        int total = B_*512*320;
        fp_gather_kernel<256,64,320><<<(total+255)/256, 256>>>(g2, f1, i31, w31, 512, 256, Abuf);
        gemm_tc_kernel<true><<<dim3(4096/128, 2), 256>>>(Abuf, 320, F1, fb1, g1, 128, 320);
    }
    {   // FP0: rows=32768, K=150 (lda 152), N=128
        int total = B_*N_*152;
        fp_gather_kernel<128,22,152><<<(total+255)/256, 256>>>(g1, skip0, i30, w30, N_, 512, Abuf);
        gemm_tc_kernel<true><<<dim3(32768/128, 2), 256>>>(Abuf, 152, F0, fb0, g0, 128, 150);
    }

    // Seg head + transposed feature output
    seg_kernel<<<dim3(N_/16, B_), 64>>>(g0, Wseg, bseg, out1);
    transpose_kernel<<<dim3(N_/32, 128/32, B_), dim3(32,32)>>>(g0, out2);
}

// round 16
// speedup vs baseline: 1.8787x; 1.1395x over previous
#include <cuda_runtime.h>
#include <cuda_bf16.h>
#include <cstdint>

// ---------------------------------------------------------------------------
// PointNet++ part-seg forward. TF32 tensor-core MLPs (pipelined) +
// block-FPS level1 / warp-FPS levels 2-4 + split-scan kNN (knn20 T=8,
// knn3 T=4):
// prep -> FPS -> knn20 -> knn3(+weights)
//   -> [sa_gather -> gemm_tc -> maxpool] x4
//   -> [fp_gather -> gemm_tc(bias+relu)] x4 -> seg + transpose
// ---------------------------------------------------------------------------

#define B_ 8
#define N_ 4096

// ---- scratch layout (floats) ----
#define SZ_XYZ4  (B_*N_*4)
#define SZ_NRM   (B_*N_*3)
#define SZ_SKIP0 (B_*N_*22)
#define SZ_X1    (B_*512*4)
#define SZ_X2    (B_*256*4)
#define SZ_X3    (B_*128*4)
#define SZ_X4    (B_*64*4)
#define SZ_F1    (B_*512*64)
#define SZ_F2    (B_*256*128)
#define SZ_F3    (B_*128*256)
#define SZ_F4    (B_*64*512)
#define SZ_G3    (B_*128*512)
#define SZ_G2    (B_*256*256)
#define SZ_G1    (B_*512*128)
#define SZ_G0    (B_*N_*128)
#define SZ_NI1   (B_*512*20)
#define SZ_NI2   (B_*256*20)
#define SZ_NI3   (B_*128*20)
#define SZ_NI4   (B_*64*20)
#define SZ_I33   (B_*128*3)
#define SZ_I32   (B_*256*3)
#define SZ_I31   (B_*512*3)
#define SZ_I30   (B_*N_*3)
#define SZ_W33   (B_*128*3)
#define SZ_W32   (B_*256*3)
#define SZ_W31   (B_*512*3)
#define SZ_W30   (B_*N_*3)
#define SZ_ABUF  (B_*N_*152)
#define SZ_CBUF  (B_*512*20*64)

#define OFF_XYZ4  0
#define OFF_NRM   (OFF_XYZ4 + SZ_XYZ4)
#define OFF_SKIP0 (OFF_NRM + SZ_NRM)
#define OFF_X1    (OFF_SKIP0 + SZ_SKIP0)
#define OFF_X2    (OFF_X1 + SZ_X1)
#define OFF_X3    (OFF_X2 + SZ_X2)
#define OFF_X4    (OFF_X3 + SZ_X3)
#define OFF_F1    (OFF_X4 + SZ_X4)
#define OFF_F2    (OFF_F1 + SZ_F1)
#define OFF_F3    (OFF_F2 + SZ_F2)
#define OFF_F4    (OFF_F3 + SZ_F3)
#define OFF_G3    (OFF_F4 + SZ_F4)
#define OFF_G2    (OFF_G3 + SZ_G3)
#define OFF_G1    (OFF_G2 + SZ_G2)
#define OFF_G0    (OFF_G1 + SZ_G1)
#define OFF_NI1   (OFF_G0 + SZ_G0)
#define OFF_NI2   (OFF_NI1 + SZ_NI1)
#define OFF_NI3   (OFF_NI2 + SZ_NI2)
#define OFF_NI4   (OFF_NI3 + SZ_NI3)
#define OFF_I33   (OFF_NI4 + SZ_NI4)
#define OFF_I32   (OFF_I33 + SZ_I33)
#define OFF_I31   (OFF_I32 + SZ_I32)
#define OFF_I30   (OFF_I31 + SZ_I31)
#define OFF_W33   (OFF_I30 + SZ_I30)
#define OFF_W32   (OFF_W33 + SZ_W33)
#define OFF_W31   (OFF_W32 + SZ_W32)
#define OFF_W30   (OFF_W31 + SZ_W31)
#define OFF_ABUF  (OFF_W30 + SZ_W30)
#define OFF_CBUF  (OFF_ABUF + SZ_ABUF)
#define SCRATCH_TOTAL (OFF_CBUF + SZ_CBUF)

__device__ __align__(16) float g_scratch[SCRATCH_TOTAL];

// ---------------------------------------------------------------------------
// prep
// ---------------------------------------------------------------------------
__global__ void prep_kernel(const float* __restrict__ x, const float* __restrict__ cls,
                            float4* __restrict__ xyz4, float* __restrict__ nrm,
                            float* __restrict__ skip0) {
    int n = blockIdx.x * blockDim.x + threadIdx.x;
    int b = blockIdx.y;
    if (n >= N_) return;
    const float* xb = x + (size_t)b * 6 * N_;
    float px = xb[0*N_+n], py = xb[1*N_+n], pz = xb[2*N_+n];
    float nx = xb[3*N_+n], ny = xb[4*N_+n], nz = xb[5*N_+n];
    float pp = px*px + py*py + pz*pz;
    xyz4[(size_t)b*N_+n] = make_float4(px, py, pz, pp);
    float* np_ = nrm + ((size_t)b*N_+n)*3;
    np_[0]=nx; np_[1]=ny; np_[2]=nz;
    float* sk = skip0 + ((size_t)b*N_+n)*22;
    #pragma unroll
    for (int c = 0; c < 16; c++) sk[c] = cls[b*16+c];
    sk[16]=px; sk[17]=py; sk[18]=pz;
    sk[19]=nx; sk[20]=ny; sk[21]=nz;
}

// ---------------------------------------------------------------------------
// FPS. Level 1: block-wide single-barrier reduction (R12 proven form), also
// records selections into an smem sel buffer. Levels 2-4: single warp,
// barrier-free (input/output via smem sel buffers; M = 32*P exactly).
// Tie-break: max dist-key, then min index (matches jnp.argmax).
// ---------------------------------------------------------------------------
#define FPS_NT 512
#define FPS_NW (FPS_NT/32)

struct FpsRed {
    unsigned key[2][FPS_NW];
    int      idx[2][FPS_NW];
};

template<int P>
__device__ void fps_level_block(const float4* __restrict__ pts, int M, int S,
                                float4* __restrict__ o, float4* spts,
                                float4* sel_out, FpsRed* r) {
    const int tid = threadIdx.x;
    const int lane = tid & 31;
    const int w = tid >> 5;
    float px[P], py[P], pz[P], dist[P];
    #pragma unroll
    for (int j = 0; j < P; j++) {
        int i = tid + j*FPS_NT;
        if (i < M) {
            float4 p = pts[i];
            spts[i] = p;
            px[j]=p.x; py[j]=p.y; pz[j]=p.z; dist[j]=1e10f;
        } else {
            px[j]=0.f; py[j]=0.f; pz[j]=0.f; dist[j]=-1.0f;
        }
    }
    __syncthreads();

    int win = 0;
    for (int it = 0; it < S; ++it) {
        float4 f = spts[win];
        if (tid == 0) { o[it] = f; sel_out[it] = f; }

        float bv = -1.0f; int bj = 0;
        #pragma unroll
        for (int j = 0; j < P; j++) {
            float dx = px[j]-f.x, dy = py[j]-f.y, dz = pz[j]-f.z;
            float d = dx*dx + dy*dy + dz*dz;
            float nd = fminf(dist[j], d);
            dist[j] = nd;
            if (nd > bv) { bv = nd; bj = j; }
        }
        int myi = tid + bj*FPS_NT;
        unsigned key = (bv > 0.0f) ? __float_as_uint(bv) : 0u;
        unsigned wmax = __reduce_max_sync(0xffffffffu, key);
        int cand = (key == wmax) ? myi : 0x7fffffff;
        int wmin = __reduce_min_sync(0xffffffffu, cand);
        int buf = it & 1;
        if (lane == 0) { r->key[buf][w] = wmax; r->idx[buf][w] = wmin; }
        __syncthreads();
        unsigned k2 = (lane < FPS_NW) ? r->key[buf][lane] : 0u;
        int      i2 = (lane < FPS_NW) ? r->idx[buf][lane] : 0x7fffffff;
        unsigned g  = __reduce_max_sync(0xffffffffu, k2);
        int c2 = (k2 == g) ? i2 : 0x7fffffff;
        win = __reduce_min_sync(0xffffffffu, c2);
    }
    __syncthreads();
}

// Warp-level FPS: M == 32*P, executed by warp 0 only. sel_in/sel_out in smem.
template<int P>
__device__ void fps_level_warp(const float4* sel_in, int M, int S,
                               float4* __restrict__ o, float4* sel_out) {
    const int lane = threadIdx.x & 31;
    __syncwarp();
    float px[P], py[P], pz[P], dist[P];
    #pragma unroll
    for (int j = 0; j < P; j++) {
        int i = lane + j*32;
        float4 p = sel_in[i];
        px[j]=p.x; py[j]=p.y; pz[j]=p.z; dist[j]=1e10f;
    }
    int win = 0;
    for (int it = 0; it < S; ++it) {
        float4 f = sel_in[win];
        if (lane == 0) { o[it] = f; sel_out[it] = f; }
        float bv = -1.0f; int bj = 0;
        #pragma unroll
        for (int j = 0; j < P; j++) {
            float dx = px[j]-f.x, dy = py[j]-f.y, dz = pz[j]-f.z;
            float d = dx*dx + dy*dy + dz*dz;
            float nd = fminf(dist[j], d);
            dist[j] = nd;
            if (nd > bv) { bv = nd; bj = j; }
        }
        int myi = lane + bj*32;
        unsigned key = (bv > 0.0f) ? __float_as_uint(bv) : 0u;
        unsigned wmax = __reduce_max_sync(0xffffffffu, key);
        int cand = (key == wmax) ? myi : 0x7fffffff;
        win = __reduce_min_sync(0xffffffffu, cand);
        __syncwarp();
    }
    __syncwarp();
}

__global__ void __launch_bounds__(FPS_NT)
fps_all_kernel(const float4* __restrict__ xyz4,
               float4* __restrict__ x1, float4* __restrict__ x2,
               float4* __restrict__ x3, float4* __restrict__ x4) {
    extern __shared__ __align__(16) float4 smemf4[];
    float4* cache = smemf4;           // [0, 4096)
    float4* selA  = smemf4 + 4096;    // [4096, 4608)
    float4* selB  = smemf4 + 4608;    // [4608, 5120)
    __shared__ FpsRed r;
    int b = blockIdx.x;
    fps_level_block<8>(xyz4 + (size_t)b*N_, N_, 512, x1 + (size_t)b*512, cache, selA, &r);
    if (threadIdx.x < 32) {
        fps_level_warp<16>(selA, 512, 256, x2 + (size_t)b*256, selB);
        fps_level_warp<8>(selB, 256, 128, x3 + (size_t)b*128, selA);
        fps_level_warp<4>(selA, 128, 64,  x4 + (size_t)b*64,  selB);
    }
}

// ---------------------------------------------------------------------------
// kNN split-scan (proven R15 transform, higher T). Each of T threads scans a
// disjoint ref segment keeping a private sorted top-K; one thread per query
// merges the T sorted lists by (d, idx) lexicographic order -> exact top_k.
// ---------------------------------------------------------------------------
template<int K>
__device__ __forceinline__ void knn_insert(float d, int m, float* bd, int* bi) {
    if (d < bd[K-1]) {
        #pragma unroll
        for (int t = K-1; t >= 0; --t) {
            bool pred_gt = (t > 0) ? (bd[t-1] > d) : false;
            if (bd[t] > d) {
                if (pred_gt) { bd[t] = bd[t-1]; bi[t] = bi[t-1]; }
                else         { bd[t] = d;       bi[t] = m; }
            }
        }
    }
}

template<int K>
__device__ __forceinline__ void knn_scan_seg(float4 qp, const float4* __restrict__ ref,
                                             int m0, int m1, float* bd, int* bi) {
    float qq = qp.w;
    #pragma unroll
    for (int j = 0; j < K; j++) { bd[j] = 3.0e38f; bi[j] = 0; }
    for (int m = m0; m < m1; m += 4) {
        float4 r0 = ref[m+0];
        float4 r1 = ref[m+1];
        float4 r2 = ref[m+2];
        float4 r3 = ref[m+3];
        float d0 = qq - 2.0f*(qp.x*r0.x + qp.y*r0.y + qp.z*r0.z) + r0.w;
        float d1 = qq - 2.0f*(qp.x*r1.x + qp.y*r1.y + qp.z*r1.z) + r1.w;
        float d2 = qq - 2.0f*(qp.x*r2.x + qp.y*r2.y + qp.z*r2.z) + r2.w;
        float d3 = qq - 2.0f*(qp.x*r3.x + qp.y*r3.y + qp.z*r3.z) + r3.w;
        knn_insert<K>(d0, m+0, bd, bi);
        knn_insert<K>(d1, m+1, bd, bi);
        knn_insert<K>(d2, m+2, bd, bi);
        knn_insert<K>(d3, m+3, bd, bi);
    }
}

// ---------------------------------------------------------------------------
// knn20, T=8 threads/query, 16 queries/block (128 threads).
// grid.x = 60: [0,32) L1; [32,48) L2; [48,56) L3; [56,60) L4.
// ---------------------------------------------------------------------------
__global__ void __launch_bounds__(128)
knn20_all_kernel(const float4* __restrict__ xyz4,
                 const float4* __restrict__ x1, const float4* __restrict__ x2,
                 const float4* __restrict__ x3, const float4* __restrict__ x4,
                 int* __restrict__ ni1, int* __restrict__ ni2,
                 int* __restrict__ ni3, int* __restrict__ ni4) {
    constexpr int K = 20, T = 8, QB = 16;
    __shared__ float sd[QB][T][K];
    __shared__ int   si[QB][T][K];
    int blk = blockIdx.x, b = blockIdx.y;
    int ql = threadIdx.x >> 3;
    int t  = threadIdx.x & 7;

    const float4* q; const float4* ref; int Sq, M; int* out; int qi;
    if (blk < 32)      { q = x1 + (size_t)b*512; ref = xyz4 + (size_t)b*N_; Sq = 512; M = N_;  out = ni1 + (size_t)b*512*20; qi = blk*QB + ql; }
    else if (blk < 48) { q = x2 + (size_t)b*256; ref = x1 + (size_t)b*512;  Sq = 256; M = 512; out = ni2 + (size_t)b*256*20; qi = (blk-32)*QB + ql; }
    else if (blk < 56) { q = x3 + (size_t)b*128; ref = x2 + (size_t)b*256;  Sq = 128; M = 256; out = ni3 + (size_t)b*128*20; qi = (blk-48)*QB + ql; }
    else               { q = x4 + (size_t)b*64;  ref = x3 + (size_t)b*128;  Sq = 64;  M = 128; out = ni4 + (size_t)b*64*20;  qi = (blk-56)*QB + ql; }

    if (qi < Sq) {
        float bd[K]; int bi[K];
        int seg = M / T;
        knn_scan_seg<K>(q[qi], ref, t*seg, (t+1)*seg, bd, bi);
        #pragma unroll
        for (int j = 0; j < K; j++) { sd[ql][t][j] = bd[j]; si[ql][t][j] = bi[j]; }
    }
    __syncthreads();
    if (t == 0 && qi < Sq) {
        int head[T] = {0,0,0,0,0,0,0,0};
        int* o = out + (size_t)qi*K;
        #pragma unroll 4
        for (int j = 0; j < K; j++) {
            float best = 3.4e38f; int bidx = 0x7fffffff; int bt = 0;
            #pragma unroll
            for (int tt = 0; tt < T; tt++) {
                float d = sd[ql][tt][head[tt]];
                int   ii = si[ql][tt][head[tt]];
                if (d < best || (d == best && ii < bidx)) { best = d; bidx = ii; bt = tt; }
            }
            o[j] = bidx;
            head[bt]++;
        }
    }
}

// ---------------------------------------------------------------------------
// knn3, T=4 threads/query, 32 queries/block (128 threads), + weights.
// grid.x = 156: [0,128) L0; [128,144) L1; [144,152) L2; [152,156) L3.
// ---------------------------------------------------------------------------
__global__ void __launch_bounds__(128)
knn3_all_kernel(const float4* __restrict__ xyz4,
                const float4* __restrict__ x1, const float4* __restrict__ x2,
                const float4* __restrict__ x3, const float4* __restrict__ x4,
                int* __restrict__ i30, int* __restrict__ i31,
                int* __restrict__ i32, int* __restrict__ i33,
                float* __restrict__ w30, float* __restrict__ w31,
                float* __restrict__ w32, float* __restrict__ w33) {
    constexpr int K = 3, T = 4, QB = 32;
    __shared__ float sd[QB][T][K];
    __shared__ int   si[QB][T][K];
    int blk = blockIdx.x, b = blockIdx.y;
    int ql = threadIdx.x >> 2;
    int t  = threadIdx.x & 3;

    const float4* q; const float4* ref; int Sq, M; int* oi; float* ow; int qi;
    if (blk < 128)      { q = xyz4 + (size_t)b*N_; ref = x1 + (size_t)b*512; Sq = N_;  M = 512; oi = i30 + (size_t)b*N_*3;  ow = w30 + (size_t)b*N_*3;  qi = blk*QB + ql; }
    else if (blk < 144) { q = x1 + (size_t)b*512;  ref = x2 + (size_t)b*256; Sq = 512; M = 256; oi = i31 + (size_t)b*512*3; ow = w31 + (size_t)b*512*3; qi = (blk-128)*QB + ql; }
    else if (blk < 152) { q = x2 + (size_t)b*256;  ref = x3 + (size_t)b*128; Sq = 256; M = 128; oi = i32 + (size_t)b*256*3; ow = w32 + (size_t)b*256*3; qi = (blk-144)*QB + ql; }
    else                { q = x3 + (size_t)b*128;  ref = x4 + (size_t)b*64;  Sq = 128; M = 64;  oi = i33 + (size_t)b*128*3; ow = w33 + (size_t)b*128*3; qi = (blk-152)*QB + ql; }

    if (qi < Sq) {
        float bd[K]; int bi[K];
        int seg = M / T;
        knn_scan_seg<K>(q[qi], ref, t*seg, (t+1)*seg, bd, bi);
        #pragma unroll
        for (int j = 0; j < K; j++) { sd[ql][t][j] = bd[j]; si[ql][t][j] = bi[j]; }
    }
    __syncthreads();
    if (t == 0 && qi < Sq) {
        int head[T] = {0,0,0,0};
        int merged[K];
        #pragma unroll
        for (int j = 0; j < K; j++) {
            float best = 3.4e38f; int bidx = 0x7fffffff; int bt = 0;
            #pragma unroll
            for (int tt = 0; tt < T; tt++) {
                float d = sd[ql][tt][head[tt]];
                int   ii = si[ql][tt][head[tt]];
                if (d < best || (d == best && ii < bidx)) { best = d; bidx = ii; bt = tt; }
            }
            merged[j] = bidx;
            head[bt]++;
        }
        float4 qp = q[qi];
        float wv[K]; float wsum = 0.0f;
        #pragma unroll
        for (int j = 0; j < K; j++) {
            float4 r = ref[merged[j]];
            float dx = r.x-qp.x, dy = r.y-qp.y, dz = r.z-qp.z;
            float dd = dx*dx + dy*dy + dz*dz;
            float w = 1.0f / (dd + 1e-8f);
            wv[j] = w; wsum += w;
        }
        float inv = 1.0f / wsum;
        #pragma unroll
        for (int j = 0; j < K; j++) {
            oi[(size_t)qi*3 + j] = merged[j];
            ow[(size_t)qi*3 + j] = wv[j]*inv;
        }
    }
}

// ---------------------------------------------------------------------------
// SA gather: A[(b*S+s)*20+k, c] = rel-xyz | feat | 0 pad
// ---------------------------------------------------------------------------
template<int CIN, int LDA>
__global__ void sa_gather_kernel(const float4* __restrict__ qxyz, const float4* __restrict__ rxyz,
                                 const float* __restrict__ rfeat, const int* __restrict__ nidx,
                                 int S, int M, float* __restrict__ A) {
    constexpr int CFEAT = CIN - 3;
    int e = blockIdx.x * blockDim.x + threadIdx.x;
    int total = B_ * S * 20 * LDA;
    if (e >= total) return;
    int c = e % LDA;
    int row = e / LDA;
    int bs = row / 20;
    int b = bs / S;
    float v = 0.0f;
    if (c < CIN) {
        int n = nidx[row];
        if (c < 3) {
            v = ((const float*)(rxyz + (size_t)b*M + n))[c]
              - ((const float*)(qxyz + bs))[c];
        } else {
            v = rfeat[((size_t)b*M + n)*CFEAT + (c-3)];
        }
    }
    A[e] = v;
}

// ---------------------------------------------------------------------------
// SA maxpool
// ---------------------------------------------------------------------------
template<int COUT>
__global__ void sa_maxpool_kernel(const float* __restrict__ C, const float* __restrict__ bias,
                                  int S, float* __restrict__ out) {
    int e = blockIdx.x * blockDim.x + threadIdx.x;
    int total = B_ * S * COUT;
    if (e >= total) return;
    int d = e % COUT;
    int bs = e / COUT;
    const float* cp = C + (size_t)bs*20*COUT + d;
    float m = cp[0];
    #pragma unroll 4
    for (int k = 1; k < 20; k++) m = fmaxf(m, cp[(size_t)k*COUT]);
    out[e] = fmaxf(m + bias[d], 0.0f);
}

// ---------------------------------------------------------------------------
// FP gather: A[b*Sq+s, c] = 3-NN interp (c<CI) | skip | 0 pad
// ---------------------------------------------------------------------------
template<int CI, int CS, int LDA>
__global__ void fp_gather_kernel(const float* __restrict__ fr, const float* __restrict__ skip,
                                 const int* __restrict__ idx3, const float* __restrict__ w3,
                                 int Sq, int M, float* __restrict__ A) {
    int e = blockIdx.x * blockDim.x + threadIdx.x;
    int total = B_ * Sq * LDA;
    if (e >= total) return;
    int c = e % LDA;
    int row = e / LDA;
    float v = 0.0f;
    if (c < CI) {
        int b = row / Sq;
        const int*   ip = idx3 + (size_t)row*3;
        const float* wp = w3   + (size_t)row*3;
        size_t base = (size_t)b*M;
        v = wp[0]*fr[(base + ip[0])*CI + c]
          + wp[1]*fr[(base + ip[1])*CI + c]
          + wp[2]*fr[(base + ip[2])*CI + c];
    } else if (c < CI + CS) {
        v = skip[(size_t)row*CS + (c - CI)];
    }
    A[e] = v;
}

// ---------------------------------------------------------------------------
// TF32 tensor-core GEMM, software-pipelined: double-buffered smem, register
// prefetch of tile t+1 before the mma on tile t, ONE sync per k-tile.
// Same tile order and mma sequence as the R8 form -> bit-identical output.
// ---------------------------------------------------------------------------
__device__ __forceinline__ unsigned f2tf32(float f) {
    unsigned r; asm("cvt.rna.tf32.f32 %0, %1;" : "=r"(r) : "f"(f)); return r;
}

template<bool BIAS_RELU>
__global__ void __launch_bounds__(256)
gemm_tc_kernel(const float* __restrict__ A, int lda,
               const float* __restrict__ Wm, const float* __restrict__ bias,
               float* __restrict__ C, int N, int Kdim) {
    __shared__ unsigned As[2][16][132];
    __shared__ unsigned Bs[2][16][68];
    int bm = blockIdx.x * 128;
    int bn = blockIdx.y * 64;
    int tid = threadIdx.x;
    int warp = tid >> 5, lane = tid & 31;
    int wm = (warp & 3) * 32;
    int wn = (warp >> 2) * 32;
    int g = lane >> 2, tq = lane & 3;

    const int ar = tid >> 2;           // A row within 64-row half
    const int ak = (tid & 3) * 4;      // A k offset
    const int bkk = tid >> 4;          // B k row
    const int bnn = (tid & 15) * 4;    // B n offset

    float acc[2][4][4];
    #pragma unroll
    for (int mt = 0; mt < 2; mt++)
        #pragma unroll
        for (int nt = 0; nt < 4; nt++)
            #pragma unroll
            for (int j = 0; j < 4; j++) acc[mt][nt][j] = 0.0f;

    int ktiles = (Kdim + 15) >> 4;

    // load tile 0 into buffer 0
    {
        #pragma unroll
        for (int h = 0; h < 2; h++) {
            int row = ar + h*64;
            float4 v = make_float4(0.f,0.f,0.f,0.f);
            if (ak < lda)
                v = *(const float4*)&A[(size_t)(bm+row)*lda + ak];
            As[0][ak+0][row] = f2tf32(v.x);
            As[0][ak+1][row] = f2tf32(v.y);
            As[0][ak+2][row] = f2tf32(v.z);
            As[0][ak+3][row] = f2tf32(v.w);
        }
        float4 v = make_float4(0.f,0.f,0.f,0.f);
        if (bkk < Kdim)
            v = *(const float4*)&Wm[(size_t)bkk*N + bn + bnn];
        Bs[0][bkk][bnn+0] = f2tf32(v.x);
        Bs[0][bkk][bnn+1] = f2tf32(v.y);
        Bs[0][bkk][bnn+2] = f2tf32(v.z);
        Bs[0][bkk][bnn+3] = f2tf32(v.w);
    }
    __syncthreads();

    for (int t = 0; t < ktiles; t++) {
        int cur = t & 1, nxt = cur ^ 1;
        bool hasNext = (t+1 < ktiles);
        // prefetch tile t+1 into registers
        float4 pa0 = make_float4(0.f,0.f,0.f,0.f);
        float4 pa1 = make_float4(0.f,0.f,0.f,0.f);
        float4 pb  = make_float4(0.f,0.f,0.f,0.f);
        if (hasNext) {
            int k0 = (t+1) * 16;
            if (k0 + ak < lda) {
                pa0 = *(const float4*)&A[(size_t)(bm+ar)*lda + k0 + ak];
                pa1 = *(const float4*)&A[(size_t)(bm+ar+64)*lda + k0 + ak];
            }
            if (k0 + bkk < Kdim)
                pb = *(const float4*)&Wm[(size_t)(k0+bkk)*N + bn + bnn];
        }
        // mma on current buffer
        #pragma unroll
        for (int kh = 0; kh < 2; kh++) {
            int kb = kh*8;
            unsigned a[2][4], bfr[4][2];
            #pragma unroll
            for (int mt = 0; mt < 2; mt++) {
                int m0 = wm + mt*16;
                a[mt][0] = As[cur][kb+tq][m0+g];
                a[mt][1] = As[cur][kb+tq][m0+g+8];
                a[mt][2] = As[cur][kb+tq+4][m0+g];
                a[mt][3] = As[cur][kb+tq+4][m0+g+8];
            }
            #pragma unroll
            for (int nt = 0; nt < 4; nt++) {
                int n0 = wn + nt*8;
                bfr[nt][0] = Bs[cur][kb+tq][n0+g];
                bfr[nt][1] = Bs[cur][kb+tq+4][n0+g];
            }
            #pragma unroll
            for (int mt = 0; mt < 2; mt++)
                #pragma unroll
                for (int nt = 0; nt < 4; nt++) {
                    asm volatile(
                        "mma.sync.aligned.m16n8k8.row.col.f32.tf32.tf32.f32 "
                        "{%0,%1,%2,%3}, {%4,%5,%6,%7}, {%8,%9}, {%0,%1,%2,%3};"
                        : "+f"(acc[mt][nt][0]), "+f"(acc[mt][nt][1]),
                          "+f"(acc[mt][nt][2]), "+f"(acc[mt][nt][3])
                        : "r"(a[mt][0]), "r"(a[mt][1]), "r"(a[mt][2]), "r"(a[mt][3]),
                          "r"(bfr[nt][0]), "r"(bfr[nt][1]));
                }
        }
        // store prefetched tile into the other buffer (no conflict with reads)
        if (hasNext) {
            As[nxt][ak+0][ar] = f2tf32(pa0.x);
            As[nxt][ak+1][ar] = f2tf32(pa0.y);
            As[nxt][ak+2][ar] = f2tf32(pa0.z);
            As[nxt][ak+3][ar] = f2tf32(pa0.w);
            As[nxt][ak+0][ar+64] = f2tf32(pa1.x);
            As[nxt][ak+1][ar+64] = f2tf32(pa1.y);
            As[nxt][ak+2][ar+64] = f2tf32(pa1.z);
            As[nxt][ak+3][ar+64] = f2tf32(pa1.w);
            Bs[nxt][bkk][bnn+0] = f2tf32(pb.x);
            Bs[nxt][bkk][bnn+1] = f2tf32(pb.y);
            Bs[nxt][bkk][bnn+2] = f2tf32(pb.z);
            Bs[nxt][bkk][bnn+3] = f2tf32(pb.w);
            __syncthreads();
        }
    }

    #pragma unroll
    for (int mt = 0; mt < 2; mt++) {
        int row0 = bm + wm + mt*16 + g;
        #pragma unroll
        for (int nt = 0; nt < 4; nt++) {
            int col = bn + wn + nt*8 + 2*tq;
            float2 v0 = make_float2(acc[mt][nt][0], acc[mt][nt][1]);
            float2 v1 = make_float2(acc[mt][nt][2], acc[mt][nt][3]);
            if (BIAS_RELU) {
                float b0v = bias[col], b1v = bias[col+1];
                v0.x = fmaxf(v0.x + b0v, 0.f); v0.y = fmaxf(v0.y + b1v, 0.f);
                v1.x = fmaxf(v1.x + b0v, 0.f); v1.y = fmaxf(v1.y + b1v, 0.f);
            }
            *(float2*)&C[(size_t)row0*N + col]     = v0;
            *(float2*)&C[(size_t)(row0+8)*N + col] = v1;
        }
    }
}

// ---------------------------------------------------------------------------
// Seg head + transpose (proven forms)
// ---------------------------------------------------------------------------
__global__ void seg_kernel(const float* __restrict__ g0, const float* __restrict__ Wseg,
                           const float* __restrict__ bseg, float* __restrict__ out) {
    constexpr int TS = 16;
    __shared__ __align__(16) float sg[TS * 128];
    int b = blockIdx.y;
    int s0 = blockIdx.x * TS;
    int tid = threadIdx.x;
    for (int e = tid; e < TS*128; e += 64)
        sg[e] = g0[((size_t)b*N_ + s0)*128 + e];
    __syncthreads();
    int j = tid;
    if (j < 50) {
        float acc[TS];
        #pragma unroll
        for (int t = 0; t < TS; t++) acc[t] = 0.0f;
        for (int c = 0; c < 128; c += 4) {
            float w0 = Wseg[(c+0)*50 + j];
            float w1 = Wseg[(c+1)*50 + j];
            float w2 = Wseg[(c+2)*50 + j];
            float w3 = Wseg[(c+3)*50 + j];
            #pragma unroll
            for (int t = 0; t < TS; t++) {
                float4 v = *(const float4*)&sg[t*128 + c];
                acc[t] += v.x*w0 + v.y*w1 + v.z*w2 + v.w*w3;
            }
        }
        float bb = bseg[j];
        #pragma unroll
        for (int t = 0; t < TS; t++)
            out[((size_t)b*N_ + s0 + t)*50 + j] = acc[t] + bb;
    }
}

__global__ void transpose_kernel(const float* __restrict__ g0, float* __restrict__ out) {
    __shared__ float tile[32][33];
    int b = blockIdx.z;
    int n0 = blockIdx.x * 32, c0 = blockIdx.y * 32;
    int tx = threadIdx.x, ty = threadIdx.y;
    tile[ty][tx] = g0[((size_t)b*N_ + n0 + ty)*128 + c0 + tx];
    __syncthreads();
    out[((size_t)b*128 + c0 + ty)*N_ + n0 + tx] = tile[tx][ty];
}

// ---------------------------------------------------------------------------
extern "C" void kernel_launch(void* const* d_in, const int* in_sizes, int n_in,
                              void* d_out, int out_size) {
    const float* x      = (const float*)d_in[0];
    const float* cls    = (const float*)d_in[1];
    const float* W0 = (const float*)d_in[2];  const float* b0 = (const float*)d_in[3];
    const float* W1 = (const float*)d_in[4];  const float* b1 = (const float*)d_in[5];
    const float* W2 = (const float*)d_in[6];  const float* b2 = (const float*)d_in[7];
    const float* W3 = (const float*)d_in[8];  const float* b3 = (const float*)d_in[9];
    const float* F3 = (const float*)d_in[10]; const float* fb3 = (const float*)d_in[11];
    const float* F2 = (const float*)d_in[12]; const float* fb2 = (const float*)d_in[13];
    const float* F1 = (const float*)d_in[14]; const float* fb1 = (const float*)d_in[15];
    const float* F0 = (const float*)d_in[16]; const float* fb0 = (const float*)d_in[17];
    const float* Wseg = (const float*)d_in[18]; const float* bseg = (const float*)d_in[19];

    float* scratch = nullptr;
    cudaGetSymbolAddress((void**)&scratch, g_scratch);

    float4* xyz4 = (float4*)(scratch + OFF_XYZ4);
    float* nrm   = scratch + OFF_NRM;
    float* skip0 = scratch + OFF_SKIP0;
    float4* x1 = (float4*)(scratch + OFF_X1);
    float4* x2 = (float4*)(scratch + OFF_X2);
    float4* x3 = (float4*)(scratch + OFF_X3);
    float4* x4 = (float4*)(scratch + OFF_X4);
    float* f1 = scratch + OFF_F1;  float* f2 = scratch + OFF_F2;
    float* f3 = scratch + OFF_F3;  float* f4 = scratch + OFF_F4;
    float* g3 = scratch + OFF_G3;  float* g2 = scratch + OFF_G2;
    float* g1 = scratch + OFF_G1;  float* g0 = scratch + OFF_G0;
    int* ni1 = (int*)(scratch + OFF_NI1);
    int* ni2 = (int*)(scratch + OFF_NI2);
    int* ni3 = (int*)(scratch + OFF_NI3);
    int* ni4 = (int*)(scratch + OFF_NI4);
    int* i33 = (int*)(scratch + OFF_I33);
    int* i32 = (int*)(scratch + OFF_I32);
    int* i31 = (int*)(scratch + OFF_I31);
    int* i30 = (int*)(scratch + OFF_I30);
    float* w33 = scratch + OFF_W33;
    float* w32 = scratch + OFF_W32;
    float* w31 = scratch + OFF_W31;
    float* w30 = scratch + OFF_W30;
    float* Abuf = scratch + OFF_ABUF;
    float* Cbuf = scratch + OFF_CBUF;

    float* out1 = (float*)d_out;                    // result [B,N,50]
    float* out2 = out1 + (size_t)B_ * N_ * 50;      // g0^T   [B,128,N]

    const int fps_smem = 5120 * (int)sizeof(float4);   // 80 KB: cache + 2 sel bufs
    cudaFuncSetAttribute(fps_all_kernel, cudaFuncAttributeMaxDynamicSharedMemorySize, fps_smem);

    prep_kernel<<<dim3(N_/256, B_), 256>>>(x, cls, xyz4, nrm, skip0);
    fps_all_kernel<<<B_, FPS_NT, fps_smem>>>(xyz4, x1, x2, x3, x4);

    knn20_all_kernel<<<dim3(60, B_), 128>>>(xyz4, x1, x2, x3, x4, ni1, ni2, ni3, ni4);
    knn3_all_kernel<<<dim3(156, B_), 128>>>(xyz4, x1, x2, x3, x4,
                                            i30, i31, i32, i33, w30, w31, w32, w33);

    // ---- SA chain ----
    {   // SA1: rows=81920, K=6 (lda 8), N=64
        int total = B_*512*20*8;
        sa_gather_kernel<6,8><<<(total+255)/256, 256>>>(x1, xyz4, nrm, ni1, 512, N_, Abuf);
        gemm_tc_kernel<false><<<dim3(81920/128, 1), 256>>>(Abuf, 8, W0, nullptr, Cbuf, 64, 6);
        int pt = B_*512*64;
        sa_maxpool_kernel<64><<<(pt+255)/256, 256>>>(Cbuf, b0, 512, f1);
    }
    {   // SA2: rows=40960, K=67 (lda 68), N=128
        int total = B_*256*20*68;
        sa_gather_kernel<67,68><<<(total+255)/256, 256>>>(x2, x1, f1, ni2, 256, 512, Abuf);
        gemm_tc_kernel<false><<<dim3(40960/128, 2), 256>>>(Abuf, 68, W1, nullptr, Cbuf, 128, 67);
        int pt = B_*256*128;
        sa_maxpool_kernel<128><<<(pt+255)/256, 256>>>(Cbuf, b1, 256, f2);
    }
    {   // SA3: rows=20480, K=131 (lda 132), N=256
        int total = B_*128*20*132;
        sa_gather_kernel<131,132><<<(total+255)/256, 256>>>(x3, x2, f2, ni3, 128, 256, Abuf);
        gemm_tc_kernel<false><<<dim3(20480/128, 4), 256>>>(Abuf, 132, W2, nullptr, Cbuf, 256, 131);
        int pt = B_*128*256;
        sa_maxpool_kernel<256><<<(pt+255)/256, 256>>>(Cbuf, b2, 128, f3);
    }
    {   // SA4: rows=10240, K=259 (lda 260), N=512
        int total = B_*64*20*260;
        sa_gather_kernel<259,260><<<(total+255)/256, 256>>>(x4, x3, f3, ni4, 64, 128, Abuf);
        gemm_tc_kernel<false><<<dim3(10240/128, 8), 256>>>(Abuf, 260, W3, nullptr, Cbuf, 512, 259);
        int pt = B_*64*512;
        sa_maxpool_kernel<512><<<(pt+255)/256, 256>>>(Cbuf, b3, 64, f4);
    }

    // ---- FP chain ----
    {   // FP3: rows=1024, K=768, N=512
        int total = B_*128*768;
        fp_gather_kernel<512,256,768><<<(total+255)/256, 256>>>(f4, f3, i33, w33, 128, 64, Abuf);
        gemm_tc_kernel<true><<<dim3(1024/128, 8), 256>>>(Abuf, 768, F3, fb3, g3, 512, 768);
    }
    {   // FP2: rows=2048, K=640, N=256
        int total = B_*256*640;
        fp_gather_kernel<512,128,640><<<(total+255)/256, 256>>>(g3, f2, i32, w32, 256, 128, Abuf);
        gemm_tc_kernel<true><<<dim3(2048/128, 4), 256>>>(Abuf, 640, F2, fb2, g2, 256, 640);
    }
    {   // FP1: rows=4096, K=320, N=128
        int total = B_*512*320;
        fp_gather_kernel<256,64,320><<<(total+255)/256, 256>>>(g2, f1, i31, w31, 512, 256, Abuf);
        gemm_tc_kernel<true><<<dim3(4096/128, 2), 256>>>(Abuf, 320, F1, fb1, g1, 128, 320);
    }
    {   // FP0: rows=32768, K=150 (lda 152), N=128
        int total = B_*N_*152;
        fp_gather_kernel<128,22,152><<<(total+255)/256, 256>>>(g1, skip0, i30, w30, N_, 512, Abuf);
        gemm_tc_kernel<true><<<dim3(32768/128, 2), 256>>>(Abuf, 152, F0, fb0, g0, 128, 150);
    }

    // Seg head + transposed feature output
    seg_kernel<<<dim3(N_/16, B_), 64>>>(g0, Wseg, bseg, out1);
    transpose_kernel<<<dim3(N_/32, 128/32, B_), dim3(32,32)>>>(g0, out2);
}

// round 17
// speedup vs baseline: 1.9106x; 1.0169x over previous
#include <cuda_runtime.h>
#include <cuda_bf16.h>
#include <cstdint>

// ---------------------------------------------------------------------------
// PointNet++ part-seg forward. TF32 tensor-core MLPs (pipelined) +
// block-FPS level1 / warp-FPS levels 2-4 + fused split-scan kNN
// (knn20 T=8 + knn3 T=2 in ONE launch):
// prep -> FPS -> knn_all -> [sa_gather -> gemm_tc -> maxpool] x4
//   -> [fp_gather -> gemm_tc(bias+relu)] x4 -> seg + transpose
// ---------------------------------------------------------------------------

#define B_ 8
#define N_ 4096

// ---- scratch layout (floats) ----
#define SZ_XYZ4  (B_*N_*4)
#define SZ_NRM   (B_*N_*3)
#define SZ_SKIP0 (B_*N_*22)
#define SZ_X1    (B_*512*4)
#define SZ_X2    (B_*256*4)
#define SZ_X3    (B_*128*4)
#define SZ_X4    (B_*64*4)
#define SZ_F1    (B_*512*64)
#define SZ_F2    (B_*256*128)
#define SZ_F3    (B_*128*256)
#define SZ_F4    (B_*64*512)
#define SZ_G3    (B_*128*512)
#define SZ_G2    (B_*256*256)
#define SZ_G1    (B_*512*128)
#define SZ_G0    (B_*N_*128)
#define SZ_NI1   (B_*512*20)
#define SZ_NI2   (B_*256*20)
#define SZ_NI3   (B_*128*20)
#define SZ_NI4   (B_*64*20)
#define SZ_I33   (B_*128*3)
#define SZ_I32   (B_*256*3)
#define SZ_I31   (B_*512*3)
#define SZ_I30   (B_*N_*3)
#define SZ_W33   (B_*128*3)
#define SZ_W32   (B_*256*3)
#define SZ_W31   (B_*512*3)
#define SZ_W30   (B_*N_*3)
#define SZ_ABUF  (B_*N_*152)
#define SZ_CBUF  (B_*512*20*64)

#define OFF_XYZ4  0
#define OFF_NRM   (OFF_XYZ4 + SZ_XYZ4)
#define OFF_SKIP0 (OFF_NRM + SZ_NRM)
#define OFF_X1    (OFF_SKIP0 + SZ_SKIP0)
#define OFF_X2    (OFF_X1 + SZ_X1)
#define OFF_X3    (OFF_X2 + SZ_X2)
#define OFF_X4    (OFF_X3 + SZ_X3)
#define OFF_F1    (OFF_X4 + SZ_X4)
#define OFF_F2    (OFF_F1 + SZ_F1)
#define OFF_F3    (OFF_F2 + SZ_F2)
#define OFF_F4    (OFF_F3 + SZ_F3)
#define OFF_G3    (OFF_F4 + SZ_F4)
#define OFF_G2    (OFF_G3 + SZ_G3)
#define OFF_G1    (OFF_G2 + SZ_G2)
#define OFF_G0    (OFF_G1 + SZ_G1)
#define OFF_NI1   (OFF_G0 + SZ_G0)
#define OFF_NI2   (OFF_NI1 + SZ_NI1)
#define OFF_NI3   (OFF_NI2 + SZ_NI2)
#define OFF_NI4   (OFF_NI3 + SZ_NI3)
#define OFF_I33   (OFF_NI4 + SZ_NI4)
#define OFF_I32   (OFF_I33 + SZ_I33)
#define OFF_I31   (OFF_I32 + SZ_I32)
#define OFF_I30   (OFF_I31 + SZ_I31)
#define OFF_W33   (OFF_I30 + SZ_I30)
#define OFF_W32   (OFF_W33 + SZ_W33)
#define OFF_W31   (OFF_W32 + SZ_W32)
#define OFF_W30   (OFF_W31 + SZ_W31)
#define OFF_ABUF  (OFF_W30 + SZ_W30)
#define OFF_CBUF  (OFF_ABUF + SZ_ABUF)
#define SCRATCH_TOTAL (OFF_CBUF + SZ_CBUF)

__device__ __align__(16) float g_scratch[SCRATCH_TOTAL];

// ---------------------------------------------------------------------------
// prep
// ---------------------------------------------------------------------------
__global__ void prep_kernel(const float* __restrict__ x, const float* __restrict__ cls,
                            float4* __restrict__ xyz4, float* __restrict__ nrm,
                            float* __restrict__ skip0) {
    int n = blockIdx.x * blockDim.x + threadIdx.x;
    int b = blockIdx.y;
    if (n >= N_) return;
    const float* xb = x + (size_t)b * 6 * N_;
    float px = xb[0*N_+n], py = xb[1*N_+n], pz = xb[2*N_+n];
    float nx = xb[3*N_+n], ny = xb[4*N_+n], nz = xb[5*N_+n];
    float pp = px*px + py*py + pz*pz;
    xyz4[(size_t)b*N_+n] = make_float4(px, py, pz, pp);
    float* np_ = nrm + ((size_t)b*N_+n)*3;
    np_[0]=nx; np_[1]=ny; np_[2]=nz;
    float* sk = skip0 + ((size_t)b*N_+n)*22;
    #pragma unroll
    for (int c = 0; c < 16; c++) sk[c] = cls[b*16+c];
    sk[16]=px; sk[17]=py; sk[18]=pz;
    sk[19]=nx; sk[20]=ny; sk[21]=nz;
}

// ---------------------------------------------------------------------------
// FPS. Level 1: block-wide single-barrier reduction; levels 2-4: warp 0 only,
// barrier-free via smem sel buffers. Tie-break: max key, min index.
// ---------------------------------------------------------------------------
#define FPS_NT 512
#define FPS_NW (FPS_NT/32)

struct FpsRed {
    unsigned key[2][FPS_NW];
    int      idx[2][FPS_NW];
};

template<int P>
__device__ void fps_level_block(const float4* __restrict__ pts, int M, int S,
                                float4* __restrict__ o, float4* spts,
                                float4* sel_out, FpsRed* r) {
    const int tid = threadIdx.x;
    const int lane = tid & 31;
    const int w = tid >> 5;
    float px[P], py[P], pz[P], dist[P];
    #pragma unroll
    for (int j = 0; j < P; j++) {
        int i = tid + j*FPS_NT;
        if (i < M) {
            float4 p = pts[i];
            spts[i] = p;
            px[j]=p.x; py[j]=p.y; pz[j]=p.z; dist[j]=1e10f;
        } else {
            px[j]=0.f; py[j]=0.f; pz[j]=0.f; dist[j]=-1.0f;
        }
    }
    __syncthreads();

    int win = 0;
    for (int it = 0; it < S; ++it) {
        float4 f = spts[win];
        if (tid == 0) { o[it] = f; sel_out[it] = f; }

        float bv = -1.0f; int bj = 0;
        #pragma unroll
        for (int j = 0; j < P; j++) {
            float dx = px[j]-f.x, dy = py[j]-f.y, dz = pz[j]-f.z;
            float d = dx*dx + dy*dy + dz*dz;
            float nd = fminf(dist[j], d);
            dist[j] = nd;
            if (nd > bv) { bv = nd; bj = j; }
        }
        int myi = tid + bj*FPS_NT;
        unsigned key = (bv > 0.0f) ? __float_as_uint(bv) : 0u;
        unsigned wmax = __reduce_max_sync(0xffffffffu, key);
        int cand = (key == wmax) ? myi : 0x7fffffff;
        int wmin = __reduce_min_sync(0xffffffffu, cand);
        int buf = it & 1;
        if (lane == 0) { r->key[buf][w] = wmax; r->idx[buf][w] = wmin; }
        __syncthreads();
        unsigned k2 = (lane < FPS_NW) ? r->key[buf][lane] : 0u;
        int      i2 = (lane < FPS_NW) ? r->idx[buf][lane] : 0x7fffffff;
        unsigned g  = __reduce_max_sync(0xffffffffu, k2);
        int c2 = (k2 == g) ? i2 : 0x7fffffff;
        win = __reduce_min_sync(0xffffffffu, c2);
    }
    __syncthreads();
}

template<int P>
__device__ void fps_level_warp(const float4* sel_in, int M, int S,
                               float4* __restrict__ o, float4* sel_out) {
    const int lane = threadIdx.x & 31;
    __syncwarp();
    float px[P], py[P], pz[P], dist[P];
    #pragma unroll
    for (int j = 0; j < P; j++) {
        int i = lane + j*32;
        float4 p = sel_in[i];
        px[j]=p.x; py[j]=p.y; pz[j]=p.z; dist[j]=1e10f;
    }
    int win = 0;
    for (int it = 0; it < S; ++it) {
        float4 f = sel_in[win];
        if (lane == 0) { o[it] = f; sel_out[it] = f; }
        float bv = -1.0f; int bj = 0;
        #pragma unroll
        for (int j = 0; j < P; j++) {
            float dx = px[j]-f.x, dy = py[j]-f.y, dz = pz[j]-f.z;
            float d = dx*dx + dy*dy + dz*dz;
            float nd = fminf(dist[j], d);
            dist[j] = nd;
            if (nd > bv) { bv = nd; bj = j; }
        }
        int myi = lane + bj*32;
        unsigned key = (bv > 0.0f) ? __float_as_uint(bv) : 0u;
        unsigned wmax = __reduce_max_sync(0xffffffffu, key);
        int cand = (key == wmax) ? myi : 0x7fffffff;
        win = __reduce_min_sync(0xffffffffu, cand);
        __syncwarp();
    }
    __syncwarp();
}

__global__ void __launch_bounds__(FPS_NT)
fps_all_kernel(const float4* __restrict__ xyz4,
               float4* __restrict__ x1, float4* __restrict__ x2,
               float4* __restrict__ x3, float4* __restrict__ x4) {
    extern __shared__ __align__(16) float4 smemf4[];
    float4* cache = smemf4;           // [0, 4096)
    float4* selA  = smemf4 + 4096;    // [4096, 4608)
    float4* selB  = smemf4 + 4608;    // [4608, 5120)
    __shared__ FpsRed r;
    int b = blockIdx.x;
    fps_level_block<8>(xyz4 + (size_t)b*N_, N_, 512, x1 + (size_t)b*512, cache, selA, &r);
    if (threadIdx.x < 32) {
        fps_level_warp<16>(selA, 512, 256, x2 + (size_t)b*256, selB);
        fps_level_warp<8>(selB, 256, 128, x3 + (size_t)b*128, selA);
        fps_level_warp<4>(selA, 128, 64,  x4 + (size_t)b*64,  selB);
    }
}

// ---------------------------------------------------------------------------
// kNN split-scan primitives (exact top_k semantics incl. tie-breaks)
// ---------------------------------------------------------------------------
template<int K>
__device__ __forceinline__ void knn_insert(float d, int m, float* bd, int* bi) {
    if (d < bd[K-1]) {
        #pragma unroll
        for (int t = K-1; t >= 0; --t) {
            bool pred_gt = (t > 0) ? (bd[t-1] > d) : false;
            if (bd[t] > d) {
                if (pred_gt) { bd[t] = bd[t-1]; bi[t] = bi[t-1]; }
                else         { bd[t] = d;       bi[t] = m; }
            }
        }
    }
}

template<int K>
__device__ __forceinline__ void knn_scan_seg(float4 qp, const float4* __restrict__ ref,
                                             int m0, int m1, float* bd, int* bi) {
    float qq = qp.w;
    #pragma unroll
    for (int j = 0; j < K; j++) { bd[j] = 3.0e38f; bi[j] = 0; }
    for (int m = m0; m < m1; m += 4) {
        float4 r0 = ref[m+0];
        float4 r1 = ref[m+1];
        float4 r2 = ref[m+2];
        float4 r3 = ref[m+3];
        float d0 = qq - 2.0f*(qp.x*r0.x + qp.y*r0.y + qp.z*r0.z) + r0.w;
        float d1 = qq - 2.0f*(qp.x*r1.x + qp.y*r1.y + qp.z*r1.z) + r1.w;
        float d2 = qq - 2.0f*(qp.x*r2.x + qp.y*r2.y + qp.z*r2.z) + r2.w;
        float d3 = qq - 2.0f*(qp.x*r3.x + qp.y*r3.y + qp.z*r3.z) + r3.w;
        knn_insert<K>(d0, m+0, bd, bi);
        knn_insert<K>(d1, m+1, bd, bi);
        knn_insert<K>(d2, m+2, bd, bi);
        knn_insert<K>(d3, m+3, bd, bi);
    }
}

// ---------------------------------------------------------------------------
// Fused kNN: one launch does all knn20 (T=8, QB=16) AND all knn3 (T=2, QB=64)
// jobs via block-range dispatch.
//   blk [0,32)    knn20 L1   [32,48) L2   [48,56) L3   [56,60) L4
//   blk [60,124)  knn3  L0   [124,132) L1 [132,136) L2 [136,138) L3
// ---------------------------------------------------------------------------
__global__ void __launch_bounds__(128)
knn_all_kernel(const float4* __restrict__ xyz4,
               const float4* __restrict__ x1, const float4* __restrict__ x2,
               const float4* __restrict__ x3, const float4* __restrict__ x4,
               int* __restrict__ ni1, int* __restrict__ ni2,
               int* __restrict__ ni3, int* __restrict__ ni4,
               int* __restrict__ i30, int* __restrict__ i31,
               int* __restrict__ i32, int* __restrict__ i33,
               float* __restrict__ w30, float* __restrict__ w31,
               float* __restrict__ w32, float* __restrict__ w33) {
    __shared__ __align__(16) char smem_raw[16*8*20*(4+4)];   // 20 KB (knn20 view)
    int blk = blockIdx.x, b = blockIdx.y;

    if (blk < 60) {
        // ---------------- knn20: T=8, QB=16 ----------------
        constexpr int K = 20, T = 8, QB = 16;
        float (*sd)[T][K] = (float(*)[T][K])smem_raw;
        int   (*si)[T][K] = (int(*)[T][K])(smem_raw + QB*T*K*4);
        int ql = threadIdx.x >> 3;
        int t  = threadIdx.x & 7;

        const float4* q; const float4* ref; int Sq, M; int* out; int qi;
        if (blk < 32)      { q = x1 + (size_t)b*512; ref = xyz4 + (size_t)b*N_; Sq = 512; M = N_;  out = ni1 + (size_t)b*512*20; qi = blk*QB + ql; }
        else if (blk < 48) { q = x2 + (size_t)b*256; ref = x1 + (size_t)b*512;  Sq = 256; M = 512; out = ni2 + (size_t)b*256*20; qi = (blk-32)*QB + ql; }
        else if (blk < 56) { q = x3 + (size_t)b*128; ref = x2 + (size_t)b*256;  Sq = 128; M = 256; out = ni3 + (size_t)b*128*20; qi = (blk-48)*QB + ql; }
        else               { q = x4 + (size_t)b*64;  ref = x3 + (size_t)b*128;  Sq = 64;  M = 128; out = ni4 + (size_t)b*64*20;  qi = (blk-56)*QB + ql; }

        if (qi < Sq) {
            float bd[K]; int bi[K];
            int seg = M / T;
            knn_scan_seg<K>(q[qi], ref, t*seg, (t+1)*seg, bd, bi);
            #pragma unroll
            for (int j = 0; j < K; j++) { sd[ql][t][j] = bd[j]; si[ql][t][j] = bi[j]; }
        }
        __syncthreads();
        if (t == 0 && qi < Sq) {
            int head[T] = {0,0,0,0,0,0,0,0};
            int* o = out + (size_t)qi*K;
            #pragma unroll 4
            for (int j = 0; j < K; j++) {
                float best = 3.4e38f; int bidx = 0x7fffffff; int bt = 0;
                #pragma unroll
                for (int tt = 0; tt < T; tt++) {
                    float d = sd[ql][tt][head[tt]];
                    int   ii = si[ql][tt][head[tt]];
                    if (d < best || (d == best && ii < bidx)) { best = d; bidx = ii; bt = tt; }
                }
                o[j] = bidx;
                head[bt]++;
            }
        }
    } else {
        // ---------------- knn3: T=2, QB=64 ----------------
        constexpr int K = 3, T = 2, QB = 64;
        int kblk = blk - 60;
        float (*sd)[T][K] = (float(*)[T][K])smem_raw;
        int   (*si)[T][K] = (int(*)[T][K])(smem_raw + QB*T*K*4);
        int ql = threadIdx.x >> 1;
        int t  = threadIdx.x & 1;

        const float4* q; const float4* ref; int Sq, M; int* oi; float* ow; int qi;
        if (kblk < 64)      { q = xyz4 + (size_t)b*N_; ref = x1 + (size_t)b*512; Sq = N_;  M = 512; oi = i30 + (size_t)b*N_*3;  ow = w30 + (size_t)b*N_*3;  qi = kblk*QB + ql; }
        else if (kblk < 72) { q = x1 + (size_t)b*512;  ref = x2 + (size_t)b*256; Sq = 512; M = 256; oi = i31 + (size_t)b*512*3; ow = w31 + (size_t)b*512*3; qi = (kblk-64)*QB + ql; }
        else if (kblk < 76) { q = x2 + (size_t)b*256;  ref = x3 + (size_t)b*128; Sq = 256; M = 128; oi = i32 + (size_t)b*256*3; ow = w32 + (size_t)b*256*3; qi = (kblk-72)*QB + ql; }
        else                { q = x3 + (size_t)b*128;  ref = x4 + (size_t)b*64;  Sq = 128; M = 64;  oi = i33 + (size_t)b*128*3; ow = w33 + (size_t)b*128*3; qi = (kblk-76)*QB + ql; }

        if (qi < Sq) {
            float bd[K]; int bi[K];
            int seg = M / T;
            knn_scan_seg<K>(q[qi], ref, t*seg, (t+1)*seg, bd, bi);
            #pragma unroll
            for (int j = 0; j < K; j++) { sd[ql][t][j] = bd[j]; si[ql][t][j] = bi[j]; }
        }
        __syncthreads();
        if (t == 0 && qi < Sq) {
            int head[T] = {0,0};
            int merged[K];
            #pragma unroll
            for (int j = 0; j < K; j++) {
                float best = 3.4e38f; int bidx = 0x7fffffff; int bt = 0;
                #pragma unroll
                for (int tt = 0; tt < T; tt++) {
                    float d = sd[ql][tt][head[tt]];
                    int   ii = si[ql][tt][head[tt]];
                    if (d < best || (d == best && ii < bidx)) { best = d; bidx = ii; bt = tt; }
                }
                merged[j] = bidx;
                head[bt]++;
            }
            float4 qp = q[qi];
            float wv[K]; float wsum = 0.0f;
            #pragma unroll
            for (int j = 0; j < K; j++) {
                float4 r = ref[merged[j]];
                float dx = r.x-qp.x, dy = r.y-qp.y, dz = r.z-qp.z;
                float dd = dx*dx + dy*dy + dz*dz;
                float w = 1.0f / (dd + 1e-8f);
                wv[j] = w; wsum += w;
            }
            float inv = 1.0f / wsum;
            #pragma unroll
            for (int j = 0; j < K; j++) {
                oi[(size_t)qi*3 + j] = merged[j];
                ow[(size_t)qi*3 + j] = wv[j]*inv;
            }
        }
    }
}

// ---------------------------------------------------------------------------
// SA gather: A[(b*S+s)*20+k, c] = rel-xyz | feat | 0 pad
// ---------------------------------------------------------------------------
template<int CIN, int LDA>
__global__ void sa_gather_kernel(const float4* __restrict__ qxyz, const float4* __restrict__ rxyz,
                                 const float* __restrict__ rfeat, const int* __restrict__ nidx,
                                 int S, int M, float* __restrict__ A) {
    constexpr int CFEAT = CIN - 3;
    int e = blockIdx.x * blockDim.x + threadIdx.x;
    int total = B_ * S * 20 * LDA;
    if (e >= total) return;
    int c = e % LDA;
    int row = e / LDA;
    int bs = row / 20;
    int b = bs / S;
    float v = 0.0f;
    if (c < CIN) {
        int n = nidx[row];
        if (c < 3) {
            v = ((const float*)(rxyz + (size_t)b*M + n))[c]
              - ((const float*)(qxyz + bs))[c];
        } else {
            v = rfeat[((size_t)b*M + n)*CFEAT + (c-3)];
        }
    }
    A[e] = v;
}

// ---------------------------------------------------------------------------
// SA maxpool
// ---------------------------------------------------------------------------
template<int COUT>
__global__ void sa_maxpool_kernel(const float* __restrict__ C, const float* __restrict__ bias,
                                  int S, float* __restrict__ out) {
    int e = blockIdx.x * blockDim.x + threadIdx.x;
    int total = B_ * S * COUT;
    if (e >= total) return;
    int d = e % COUT;
    int bs = e / COUT;
    const float* cp = C + (size_t)bs*20*COUT + d;
    float m = cp[0];
    #pragma unroll 4
    for (int k = 1; k < 20; k++) m = fmaxf(m, cp[(size_t)k*COUT]);
    out[e] = fmaxf(m + bias[d], 0.0f);
}

// ---------------------------------------------------------------------------
// FP gather: A[b*Sq+s, c] = 3-NN interp (c<CI) | skip | 0 pad
// ---------------------------------------------------------------------------
template<int CI, int CS, int LDA>
__global__ void fp_gather_kernel(const float* __restrict__ fr, const float* __restrict__ skip,
                                 const int* __restrict__ idx3, const float* __restrict__ w3,
                                 int Sq, int M, float* __restrict__ A) {
    int e = blockIdx.x * blockDim.x + threadIdx.x;
    int total = B_ * Sq * LDA;
    if (e >= total) return;
    int c = e % LDA;
    int row = e / LDA;
    float v = 0.0f;
    if (c < CI) {
        int b = row / Sq;
        const int*   ip = idx3 + (size_t)row*3;
        const float* wp = w3   + (size_t)row*3;
        size_t base = (size_t)b*M;
        v = wp[0]*fr[(base + ip[0])*CI + c]
          + wp[1]*fr[(base + ip[1])*CI + c]
          + wp[2]*fr[(base + ip[2])*CI + c];
    } else if (c < CI + CS) {
        v = skip[(size_t)row*CS + (c - CI)];
    }
    A[e] = v;
}

// ---------------------------------------------------------------------------
// TF32 tensor-core GEMM, software-pipelined (R16 proven form)
// ---------------------------------------------------------------------------
__device__ __forceinline__ unsigned f2tf32(float f) {
    unsigned r; asm("cvt.rna.tf32.f32 %0, %1;" : "=r"(r) : "f"(f)); return r;
}

template<bool BIAS_RELU>
__global__ void __launch_bounds__(256)
gemm_tc_kernel(const float* __restrict__ A, int lda,
               const float* __restrict__ Wm, const float* __restrict__ bias,
               float* __restrict__ C, int N, int Kdim) {
    __shared__ unsigned As[2][16][132];
    __shared__ unsigned Bs[2][16][68];
    int bm = blockIdx.x * 128;
    int bn = blockIdx.y * 64;
    int tid = threadIdx.x;
    int warp = tid >> 5, lane = tid & 31;
    int wm = (warp & 3) * 32;
    int wn = (warp >> 2) * 32;
    int g = lane >> 2, tq = lane & 3;

    const int ar = tid >> 2;
    const int ak = (tid & 3) * 4;
    const int bkk = tid >> 4;
    const int bnn = (tid & 15) * 4;

    float acc[2][4][4];
    #pragma unroll
    for (int mt = 0; mt < 2; mt++)
        #pragma unroll
        for (int nt = 0; nt < 4; nt++)
            #pragma unroll
            for (int j = 0; j < 4; j++) acc[mt][nt][j] = 0.0f;

    int ktiles = (Kdim + 15) >> 4;

    {
        #pragma unroll
        for (int h = 0; h < 2; h++) {
            int row = ar + h*64;
            float4 v = make_float4(0.f,0.f,0.f,0.f);
            if (ak < lda)
                v = *(const float4*)&A[(size_t)(bm+row)*lda + ak];
            As[0][ak+0][row] = f2tf32(v.x);
            As[0][ak+1][row] = f2tf32(v.y);
            As[0][ak+2][row] = f2tf32(v.z);
            As[0][ak+3][row] = f2tf32(v.w);
        }
        float4 v = make_float4(0.f,0.f,0.f,0.f);
        if (bkk < Kdim)
            v = *(const float4*)&Wm[(size_t)bkk*N + bn + bnn];
        Bs[0][bkk][bnn+0] = f2tf32(v.x);
        Bs[0][bkk][bnn+1] = f2tf32(v.y);
        Bs[0][bkk][bnn+2] = f2tf32(v.z);
        Bs[0][bkk][bnn+3] = f2tf32(v.w);
    }
    __syncthreads();

    for (int t = 0; t < ktiles; t++) {
        int cur = t & 1, nxt = cur ^ 1;
        bool hasNext = (t+1 < ktiles);
        float4 pa0 = make_float4(0.f,0.f,0.f,0.f);
        float4 pa1 = make_float4(0.f,0.f,0.f,0.f);
        float4 pb  = make_float4(0.f,0.f,0.f,0.f);
        if (hasNext) {
            int k0 = (t+1) * 16;
            if (k0 + ak < lda) {
                pa0 = *(const float4*)&A[(size_t)(bm+ar)*lda + k0 + ak];
                pa1 = *(const float4*)&A[(size_t)(bm+ar+64)*lda + k0 + ak];
            }
            if (k0 + bkk < Kdim)
                pb = *(const float4*)&Wm[(size_t)(k0+bkk)*N + bn + bnn];
        }
        #pragma unroll
        for (int kh = 0; kh < 2; kh++) {
            int kb = kh*8;
            unsigned a[2][4], bfr[4][2];
            #pragma unroll
            for (int mt = 0; mt < 2; mt++) {
                int m0 = wm + mt*16;
                a[mt][0] = As[cur][kb+tq][m0+g];
                a[mt][1] = As[cur][kb+tq][m0+g+8];
                a[mt][2] = As[cur][kb+tq+4][m0+g];
                a[mt][3] = As[cur][kb+tq+4][m0+g+8];
            }
            #pragma unroll
            for (int nt = 0; nt < 4; nt++) {
                int n0 = wn + nt*8;
                bfr[nt][0] = Bs[cur][kb+tq][n0+g];
                bfr[nt][1] = Bs[cur][kb+tq+4][n0+g];
            }
            #pragma unroll
            for (int mt = 0; mt < 2; mt++)
                #pragma unroll
                for (int nt = 0; nt < 4; nt++) {
                    asm volatile(
                        "mma.sync.aligned.m16n8k8.row.col.f32.tf32.tf32.f32 "
                        "{%0,%1,%2,%3}, {%4,%5,%6,%7}, {%8,%9}, {%0,%1,%2,%3};"
                        : "+f"(acc[mt][nt][0]), "+f"(acc[mt][nt][1]),
                          "+f"(acc[mt][nt][2]), "+f"(acc[mt][nt][3])
                        : "r"(a[mt][0]), "r"(a[mt][1]), "r"(a[mt][2]), "r"(a[mt][3]),
                          "r"(bfr[nt][0]), "r"(bfr[nt][1]));
                }
        }
        if (hasNext) {
            As[nxt][ak+0][ar] = f2tf32(pa0.x);
            As[nxt][ak+1][ar] = f2tf32(pa0.y);
            As[nxt][ak+2][ar] = f2tf32(pa0.z);
            As[nxt][ak+3][ar] = f2tf32(pa0.w);
            As[nxt][ak+0][ar+64] = f2tf32(pa1.x);
            As[nxt][ak+1][ar+64] = f2tf32(pa1.y);
            As[nxt][ak+2][ar+64] = f2tf32(pa1.z);
            As[nxt][ak+3][ar+64] = f2tf32(pa1.w);
            Bs[nxt][bkk][bnn+0] = f2tf32(pb.x);
            Bs[nxt][bkk][bnn+1] = f2tf32(pb.y);
            Bs[nxt][bkk][bnn+2] = f2tf32(pb.z);
            Bs[nxt][bkk][bnn+3] = f2tf32(pb.w);
            __syncthreads();
        }
    }

    #pragma unroll
    for (int mt = 0; mt < 2; mt++) {
        int row0 = bm + wm + mt*16 + g;
        #pragma unroll
        for (int nt = 0; nt < 4; nt++) {
            int col = bn + wn + nt*8 + 2*tq;
            float2 v0 = make_float2(acc[mt][nt][0], acc[mt][nt][1]);
            float2 v1 = make_float2(acc[mt][nt][2], acc[mt][nt][3]);
            if (BIAS_RELU) {
                float b0v = bias[col], b1v = bias[col+1];
                v0.x = fmaxf(v0.x + b0v, 0.f); v0.y = fmaxf(v0.y + b1v, 0.f);
                v1.x = fmaxf(v1.x + b0v, 0.f); v1.y = fmaxf(v1.y + b1v, 0.f);
            }
            *(float2*)&C[(size_t)row0*N + col]     = v0;
            *(float2*)&C[(size_t)(row0+8)*N + col] = v1;
        }
    }
}

// ---------------------------------------------------------------------------
// Seg head + transpose (proven forms)
// ---------------------------------------------------------------------------
__global__ void seg_kernel(const float* __restrict__ g0, const float* __restrict__ Wseg,
                           const float* __restrict__ bseg, float* __restrict__ out) {
    constexpr int TS = 16;
    __shared__ __align__(16) float sg[TS * 128];
    int b = blockIdx.y;
    int s0 = blockIdx.x * TS;
    int tid = threadIdx.x;
    for (int e = tid; e < TS*128; e += 64)
        sg[e] = g0[((size_t)b*N_ + s0)*128 + e];
    __syncthreads();
    int j = tid;
    if (j < 50) {
        float acc[TS];
        #pragma unroll
        for (int t = 0; t < TS; t++) acc[t] = 0.0f;
        for (int c = 0; c < 128; c += 4) {
            float w0 = Wseg[(c+0)*50 + j];
            float w1 = Wseg[(c+1)*50 + j];
            float w2 = Wseg[(c+2)*50 + j];
            float w3 = Wseg[(c+3)*50 + j];
            #pragma unroll
            for (int t = 0; t < TS; t++) {
                float4 v = *(const float4*)&sg[t*128 + c];
                acc[t] += v.x*w0 + v.y*w1 + v.z*w2 + v.w*w3;
            }
        }
        float bb = bseg[j];
        #pragma unroll
        for (int t = 0; t < TS; t++)
            out[((size_t)b*N_ + s0 + t)*50 + j] = acc[t] + bb;
    }
}

__global__ void transpose_kernel(const float* __restrict__ g0, float* __restrict__ out) {
    __shared__ float tile[32][33];
    int b = blockIdx.z;
    int n0 = blockIdx.x * 32, c0 = blockIdx.y * 32;
    int tx = threadIdx.x, ty = threadIdx.y;
    tile[ty][tx] = g0[((size_t)b*N_ + n0 + ty)*128 + c0 + tx];
    __syncthreads();
    out[((size_t)b*128 + c0 + ty)*N_ + n0 + tx] = tile[tx][ty];
}

// ---------------------------------------------------------------------------
extern "C" void kernel_launch(void* const* d_in, const int* in_sizes, int n_in,
                              void* d_out, int out_size) {
    const float* x      = (const float*)d_in[0];
    const float* cls    = (const float*)d_in[1];
    const float* W0 = (const float*)d_in[2];  const float* b0 = (const float*)d_in[3];
    const float* W1 = (const float*)d_in[4];  const float* b1 = (const float*)d_in[5];
    const float* W2 = (const float*)d_in[6];  const float* b2 = (const float*)d_in[7];
    const float* W3 = (const float*)d_in[8];  const float* b3 = (const float*)d_in[9];
    const float* F3 = (const float*)d_in[10]; const float* fb3 = (const float*)d_in[11];
    const float* F2 = (const float*)d_in[12]; const float* fb2 = (const float*)d_in[13];
    const float* F1 = (const float*)d_in[14]; const float* fb1 = (const float*)d_in[15];
    const float* F0 = (const float*)d_in[16]; const float* fb0 = (const float*)d_in[17];
    const float* Wseg = (const float*)d_in[18]; const float* bseg = (const float*)d_in[19];

    float* scratch = nullptr;
    cudaGetSymbolAddress((void**)&scratch, g_scratch);

    float4* xyz4 = (float4*)(scratch + OFF_XYZ4);
    float* nrm   = scratch + OFF_NRM;
    float* skip0 = scratch + OFF_SKIP0;
    float4* x1 = (float4*)(scratch + OFF_X1);
    float4* x2 = (float4*)(scratch + OFF_X2);
    float4* x3 = (float4*)(scratch + OFF_X3);
    float4* x4 = (float4*)(scratch + OFF_X4);
    float* f1 = scratch + OFF_F1;  float* f2 = scratch + OFF_F2;
    float* f3 = scratch + OFF_F3;  float* f4 = scratch + OFF_F4;
    float* g3 = scratch + OFF_G3;  float* g2 = scratch + OFF_G2;
    float* g1 = scratch + OFF_G1;  float* g0 = scratch + OFF_G0;
    int* ni1 = (int*)(scratch + OFF_NI1);
    int* ni2 = (int*)(scratch + OFF_NI2);
    int* ni3 = (int*)(scratch + OFF_NI3);
    int* ni4 = (int*)(scratch + OFF_NI4);
    int* i33 = (int*)(scratch + OFF_I33);
    int* i32 = (int*)(scratch + OFF_I32);
    int* i31 = (int*)(scratch + OFF_I31);
    int* i30 = (int*)(scratch + OFF_I30);
    float* w33 = scratch + OFF_W33;
    float* w32 = scratch + OFF_W32;
    float* w31 = scratch + OFF_W31;
    float* w30 = scratch + OFF_W30;
    float* Abuf = scratch + OFF_ABUF;
    float* Cbuf = scratch + OFF_CBUF;

    float* out1 = (float*)d_out;                    // result [B,N,50]
    float* out2 = out1 + (size_t)B_ * N_ * 50;      // g0^T   [B,128,N]

    const int fps_smem = 5120 * (int)sizeof(float4);   // 80 KB
    cudaFuncSetAttribute(fps_all_kernel, cudaFuncAttributeMaxDynamicSharedMemorySize, fps_smem);

    prep_kernel<<<dim3(N_/256, B_), 256>>>(x, cls, xyz4, nrm, skip0);
    fps_all_kernel<<<B_, FPS_NT, fps_smem>>>(xyz4, x1, x2, x3, x4);

    knn_all_kernel<<<dim3(138, B_), 128>>>(xyz4, x1, x2, x3, x4,
                                           ni1, ni2, ni3, ni4,
                                           i30, i31, i32, i33, w30, w31, w32, w33);

    // ---- SA chain ----
    {   // SA1: rows=81920, K=6 (lda 8), N=64
        int total = B_*512*20*8;
        sa_gather_kernel<6,8><<<(total+255)/256, 256>>>(x1, xyz4, nrm, ni1, 512, N_, Abuf);
        gemm_tc_kernel<false><<<dim3(81920/128, 1), 256>>>(Abuf, 8, W0, nullptr, Cbuf, 64, 6);
        int pt = B_*512*64;
        sa_maxpool_kernel<64><<<(pt+255)/256, 256>>>(Cbuf, b0, 512, f1);
    }
    {   // SA2: rows=40960, K=67 (lda 68), N=128
        int total = B_*256*20*68;
        sa_gather_kernel<67,68><<<(total+255)/256, 256>>>(x2, x1, f1, ni2, 256, 512, Abuf);
        gemm_tc_kernel<false><<<dim3(40960/128, 2), 256>>>(Abuf, 68, W1, nullptr, Cbuf, 128, 67);
        int pt = B_*256*128;
        sa_maxpool_kernel<128><<<(pt+255)/256, 256>>>(Cbuf, b1, 256, f2);
    }
    {   // SA3: rows=20480, K=131 (lda 132), N=256
        int total = B_*128*20*132;
        sa_gather_kernel<131,132><<<(total+255)/256, 256>>>(x3, x2, f2, ni3, 128, 256, Abuf);
        gemm_tc_kernel<false><<<dim3(20480/128, 4), 256>>>(Abuf, 132, W2, nullptr, Cbuf, 256, 131);
        int pt = B_*128*256;
        sa_maxpool_kernel<256><<<(pt+255)/256, 256>>>(Cbuf, b2, 128, f3);
    }
    {   // SA4: rows=10240, K=259 (lda 260), N=512
        int total = B_*64*20*260;
        sa_gather_kernel<259,260><<<(total+255)/256, 256>>>(x4, x3, f3, ni4, 64, 128, Abuf);
        gemm_tc_kernel<false><<<dim3(10240/128, 8), 256>>>(Abuf, 260, W3, nullptr, Cbuf, 512, 259);
        int pt = B_*64*512;
        sa_maxpool_kernel<512><<<(pt+255)/256, 256>>>(Cbuf, b3, 64, f4);
    }

    // ---- FP chain ----
    {   // FP3: rows=1024, K=768, N=512
        int total = B_*128*768;
        fp_gather_kernel<512,256,768><<<(total+255)/256, 256>>>(f4, f3, i33, w33, 128, 64, Abuf);
        gemm_tc_kernel<true><<<dim3(1024/128, 8), 256>>>(Abuf, 768, F3, fb3, g3, 512, 768);
    }
    {   // FP2: rows=2048, K=640, N=256
        int total = B_*256*640;
        fp_gather_kernel<512,128,640><<<(total+255)/256, 256>>>(g3, f2, i32, w32, 256, 128, Abuf);
        gemm_tc_kernel<true><<<dim3(2048/128, 4), 256>>>(Abuf, 640, F2, fb2, g2, 256, 640);
    }
    {   // FP1: rows=4096, K=320, N=128
        int total = B_*512*320;
        fp_gather_kernel<256,64,320><<<(total+255)/256, 256>>>(g2, f1, i31, w31, 512, 256, Abuf);
        gemm_tc_kernel<true><<<dim3(4096/128, 2), 256>>>(Abuf, 320, F1, fb1, g1, 128, 320);
    }
    {   // FP0: rows=32768, K=150 (lda 152), N=128
        int total = B_*N_*152;
        fp_gather_kernel<128,22,152><<<(total+255)/256, 256>>>(g1, skip0, i30, w30, N_, 512, Abuf);
        gemm_tc_kernel<true><<<dim3(32768/128, 2), 256>>>(Abuf, 152, F0, fb0, g0, 128, 150);
    }

    // Seg head + transposed feature output
    seg_kernel<<<dim3(N_/16, B_), 64>>>(g0, Wseg, bseg, out1);
    transpose_kernel<<<dim3(N_/32, 128/32, B_), dim3(32,32)>>>(g0, out2);
}